// round 1
// baseline (speedup 1.0000x reference)
#include <cuda_runtime.h>
#include <cuda_bf16.h>
#include <math.h>

// ---------------------------------------------------------------------------
// Problem constants
// ---------------------------------------------------------------------------
#define BATCH    4
#define SEQ      1024
#define M_ROWS   (BATCH * SEQ)      // 4096
#define D_MODEL  256
#define D_INNER  512
#define D_STATE  16
#define DT_RANK  16
#define D_CONV   4
#define N_LAYERS 2
#define X_DIM    768
#define N_CLS    128

// ---------------------------------------------------------------------------
// Scratch (no cudaMalloc allowed)
// ---------------------------------------------------------------------------
__device__ float g_h   [M_ROWS * D_MODEL];    // residual stream
__device__ float g_hl  [M_ROWS * D_MODEL];    // layernorm output
__device__ float g_xz  [M_ROWS * 2 * D_INNER];
__device__ float g_u   [M_ROWS * D_INNER];
__device__ float g_xdbc[M_ROWS * (DT_RANK + 2 * D_STATE)];
__device__ float g_dlt [M_ROWS * D_INNER];
__device__ float g_y   [M_ROWS * D_INNER];
__device__ float g_h2  [M_ROWS * D_MODEL];
__device__ float g_norm[M_ROWS];

// ---------------------------------------------------------------------------
// Generic tiled GEMM: C[M,N] = A[M,K] @ W[N,K]^T (+bias)(+residual)(+gelu)
// BM=BN=64, BK=16, 256 threads, 4x4 per thread.
// ---------------------------------------------------------------------------
#define BM 64
#define BN 64
#define BK 16

__global__ void gemm_kernel(const float* __restrict__ A, const float* __restrict__ W,
                            const float* __restrict__ bias, const float* __restrict__ res,
                            float* __restrict__ C, int M, int N, int K, int act)
{
    __shared__ float As[BK][BM + 1];
    __shared__ float Ws[BK][BN + 1];
    const int tid = threadIdx.x;
    const int m0 = blockIdx.y * BM;
    const int n0 = blockIdx.x * BN;
    const int tm = tid >> 4;       // 0..15
    const int tn = tid & 15;       // 0..15

    float acc[4][4] = {};

    for (int k0 = 0; k0 < K; k0 += BK) {
        #pragma unroll
        for (int i = 0; i < 4; i++) {
            int idx = tid + i * 256;
            int r = idx >> 4, c = idx & 15;
            int gm = m0 + r;
            As[c][r] = (gm < M) ? A[(size_t)gm * K + k0 + c] : 0.f;
        }
        #pragma unroll
        for (int i = 0; i < 4; i++) {
            int idx = tid + i * 256;
            int r = idx >> 4, c = idx & 15;
            int gn = n0 + r;
            Ws[c][r] = (gn < N) ? W[(size_t)gn * K + k0 + c] : 0.f;
        }
        __syncthreads();
        #pragma unroll
        for (int kk = 0; kk < BK; kk++) {
            float a[4], b[4];
            #pragma unroll
            for (int i = 0; i < 4; i++) a[i] = As[kk][tm * 4 + i];
            #pragma unroll
            for (int j = 0; j < 4; j++) b[j] = Ws[kk][tn * 4 + j];
            #pragma unroll
            for (int i = 0; i < 4; i++)
                #pragma unroll
                for (int j = 0; j < 4; j++)
                    acc[i][j] = fmaf(a[i], b[j], acc[i][j]);
        }
        __syncthreads();
    }

    #pragma unroll
    for (int i = 0; i < 4; i++) {
        int m = m0 + tm * 4 + i;
        if (m >= M) continue;
        #pragma unroll
        for (int j = 0; j < 4; j++) {
            int n = n0 + tn * 4 + j;
            if (n >= N) continue;
            float v = acc[i][j];
            if (bias) v += bias[n];
            if (res)  v += res[(size_t)m * N + n];
            if (act == 1) v = 0.5f * v * (1.f + erff(v * 0.70710678118654752f));
            C[(size_t)m * N + n] = v;
        }
    }
}

// ---------------------------------------------------------------------------
// LayerNorm over D_MODEL=256 (one block per row, 256 threads), optional gelu
// ---------------------------------------------------------------------------
__global__ void ln_kernel(const float* __restrict__ x, const float* __restrict__ g,
                          const float* __restrict__ b, float* __restrict__ out, int do_gelu)
{
    const int row = blockIdx.x;
    const int tid = threadIdx.x;
    float v = x[(size_t)row * D_MODEL + tid];
    float s1 = v, s2 = v * v;
    #pragma unroll
    for (int o = 16; o > 0; o >>= 1) {
        s1 += __shfl_xor_sync(0xffffffffu, s1, o);
        s2 += __shfl_xor_sync(0xffffffffu, s2, o);
    }
    __shared__ float sm1[8], sm2[8];
    __shared__ float mu_s, rstd_s;
    if ((tid & 31) == 0) { sm1[tid >> 5] = s1; sm2[tid >> 5] = s2; }
    __syncthreads();
    if (tid == 0) {
        float t1 = 0.f, t2 = 0.f;
        #pragma unroll
        for (int i = 0; i < 8; i++) { t1 += sm1[i]; t2 += sm2[i]; }
        float mu  = t1 * (1.f / 256.f);
        float var = t2 * (1.f / 256.f) - mu * mu;
        mu_s = mu;
        rstd_s = rsqrtf(var + 1e-5f);
    }
    __syncthreads();
    float y = (v - mu_s) * rstd_s * g[tid] + b[tid];
    if (do_gelu) y = 0.5f * y * (1.f + erff(y * 0.70710678118654752f));
    out[(size_t)row * D_MODEL + tid] = y;
}

// ---------------------------------------------------------------------------
// Depthwise causal conv (kernel 4, left pad 3) over L, then SiLU.
// Input is the first D_INNER columns of xz; output compact (M_ROWS, D_INNER).
// ---------------------------------------------------------------------------
__global__ void conv_silu_kernel(const float* __restrict__ xz, const float* __restrict__ cw,
                                 const float* __restrict__ cb, float* __restrict__ u)
{
    int idx = blockIdx.x * blockDim.x + threadIdx.x;
    if (idx >= M_ROWS * D_INNER) return;
    int d = idx & (D_INNER - 1);
    int l = (idx / D_INNER) & (SEQ - 1);
    int b = idx / (D_INNER * SEQ);
    float acc = cb[d];
    #pragma unroll
    for (int j = 0; j < D_CONV; j++) {
        int ll = l - (D_CONV - 1) + j;
        if (ll >= 0)
            acc = fmaf(cw[d * D_CONV + j],
                       xz[((size_t)(b * SEQ + ll)) * (2 * D_INNER) + d], acc);
    }
    acc = acc / (1.f + expf(-acc));   // silu
    u[idx] = acc;
}

// ---------------------------------------------------------------------------
// delta = softplus(dt @ dtw^T + dtb) ; dt = xdbc[:, :16]
// ---------------------------------------------------------------------------
__global__ void delta_kernel(const float* __restrict__ xdbc, const float* __restrict__ dtw,
                             const float* __restrict__ dtb, float* __restrict__ dlt)
{
    int idx = blockIdx.x * blockDim.x + threadIdx.x;
    if (idx >= M_ROWS * D_INNER) return;
    int d = idx & (D_INNER - 1);
    int row = idx / D_INNER;
    const float* dt = xdbc + (size_t)row * (DT_RANK + 2 * D_STATE);
    float acc = dtb[d];
    #pragma unroll
    for (int r = 0; r < DT_RANK; r++)
        acc = fmaf(dt[r], dtw[d * DT_RANK + r], acc);
    // softplus
    float sp = (acc > 20.f) ? acc : log1pf(expf(acc));
    dlt[idx] = sp;
}

// ---------------------------------------------------------------------------
// Selective scan. One 16-lane group per (b,d); lane n owns state n.
// Fused output gating: y *= silu(z), z = xz[:, D_INNER + d].
// ---------------------------------------------------------------------------
__global__ void scan_kernel(const float* __restrict__ dlt, const float* __restrict__ u,
                            const float* __restrict__ xdbc, const float* __restrict__ xz,
                            const float* __restrict__ A_log, const float* __restrict__ Dp,
                            float* __restrict__ y)
{
    const int tid = threadIdx.x;
    const int gid = blockIdx.x * (blockDim.x >> 4) + (tid >> 4);  // 0..2047
    const int n = tid & 15;
    const int b = gid >> 9;            // / D_INNER
    const int d = gid & (D_INNER - 1);
    const float A  = -__expf(A_log[d * D_STATE + n]);
    const float Dd = Dp[d];
    float s = 0.f;
    const size_t row0 = (size_t)b * SEQ;
    for (int t = 0; t < SEQ; t++) {
        const size_t row = row0 + t;
        const float dt_ = dlt[row * D_INNER + d];
        const float ut  = u  [row * D_INNER + d];
        const float Bn  = xdbc[row * 48 + DT_RANK + n];
        const float Cn  = xdbc[row * 48 + DT_RANK + D_STATE + n];
        s = fmaf(s, __expf(dt_ * A), dt_ * ut * Bn);
        float v = s * Cn;
        #pragma unroll
        for (int o = 8; o > 0; o >>= 1) v += __shfl_xor_sync(0xffffffffu, v, o);
        if (n == 0) {
            const float z = xz[row * (2 * D_INNER) + D_INNER + d];
            y[row * D_INNER + d] = (v + ut * Dd) * (z / (1.f + __expf(-z)));
        }
    }
}

// ---------------------------------------------------------------------------
// Per-row L2 norm of h2 (256 cols) -> g_norm
// ---------------------------------------------------------------------------
__global__ void rownorm_kernel(const float* __restrict__ h, float* __restrict__ nrm)
{
    const int row = blockIdx.x;
    const int tid = threadIdx.x;
    float v = h[(size_t)row * D_MODEL + tid];
    float s = v * v;
    #pragma unroll
    for (int o = 16; o > 0; o >>= 1) s += __shfl_xor_sync(0xffffffffu, s, o);
    __shared__ float sm[8];
    if ((tid & 31) == 0) sm[tid >> 5] = s;
    __syncthreads();
    if (tid == 0) {
        float t = 0.f;
        #pragma unroll
        for (int i = 0; i < 8; i++) t += sm[i];
        nrm[row] = sqrtf(t);
    }
}

// Deterministic reduce of 4096 norms -> scalar loss
__global__ void loss_kernel(const float* __restrict__ nrm, float* __restrict__ out)
{
    const int tid = threadIdx.x; // 1024 threads
    float s = 0.f;
    #pragma unroll
    for (int i = 0; i < 4; i++) s += nrm[tid + i * 1024];
    #pragma unroll
    for (int o = 16; o > 0; o >>= 1) s += __shfl_xor_sync(0xffffffffu, s, o);
    __shared__ float sm[32];
    if ((tid & 31) == 0) sm[tid >> 5] = s;
    __syncthreads();
    if (tid == 0) {
        float t = 0.f;
        #pragma unroll
        for (int i = 0; i < 32; i++) t += sm[i];
        *out = 0.01f * t * (1.f / (float)M_ROWS);
    }
}

// ---------------------------------------------------------------------------
// Launch
// ---------------------------------------------------------------------------
extern "C" void kernel_launch(void* const* d_in, const int* in_sizes, int n_in,
                              void* d_out, int out_size)
{
    const float* x      = (const float*)d_in[0];
    const float* in_w   = (const float*)d_in[1];
    const float* in_b   = (const float*)d_in[2];
    const float* ln_g   = (const float*)d_in[3];
    const float* ln_b   = (const float*)d_in[4];
    const float* blk_ng = (const float*)d_in[5];
    const float* blk_nb = (const float*)d_in[6];
    const float* blk_ipw= (const float*)d_in[7];
    const float* blk_cw = (const float*)d_in[8];
    const float* blk_cb = (const float*)d_in[9];
    const float* blk_xpw= (const float*)d_in[10];
    const float* blk_dtw= (const float*)d_in[11];
    const float* blk_dtb= (const float*)d_in[12];
    const float* blk_Al = (const float*)d_in[13];
    const float* blk_D  = (const float*)d_in[14];
    const float* blk_opw= (const float*)d_in[15];
    const float* op_w   = (const float*)d_in[16];
    const float* op_b   = (const float*)d_in[17];
    const float* cls_w  = (const float*)d_in[18];
    const float* cls_b  = (const float*)d_in[19];
    float* out = (float*)d_out;

    float *h, *hl, *xz, *u, *xdbc, *dlt, *y, *h2, *nrm;
    cudaGetSymbolAddress((void**)&h,    g_h);
    cudaGetSymbolAddress((void**)&hl,   g_hl);
    cudaGetSymbolAddress((void**)&xz,   g_xz);
    cudaGetSymbolAddress((void**)&u,    g_u);
    cudaGetSymbolAddress((void**)&xdbc, g_xdbc);
    cudaGetSymbolAddress((void**)&dlt,  g_dlt);
    cudaGetSymbolAddress((void**)&y,    g_y);
    cudaGetSymbolAddress((void**)&h2,   g_h2);
    cudaGetSymbolAddress((void**)&nrm,  g_norm);

    dim3 blk256(256);

    // 1) h = x @ in_w^T + in_b  (M=4096, K=768, N=256)
    gemm_kernel<<<dim3(D_MODEL / BN, M_ROWS / BM), blk256>>>(
        x, in_w, in_b, nullptr, h, M_ROWS, D_MODEL, X_DIM, 0);
    // 2) h = gelu(layernorm(h))
    ln_kernel<<<M_ROWS, D_MODEL>>>(h, ln_g, ln_b, hl, 1);
    // move hl -> h (use hl as the residual stream holder instead: swap roles)
    // Simpler: copy via kernel-free trick: just treat hl as h from here on.
    float* hs = hl;   // residual stream
    float* lt = h;    // scratch for per-block layernorm output

    for (int l = 0; l < N_LAYERS; l++) {
        const float* ng  = blk_ng  + (size_t)l * D_MODEL;
        const float* nb  = blk_nb  + (size_t)l * D_MODEL;
        const float* ipw = blk_ipw + (size_t)l * 2 * D_INNER * D_MODEL;
        const float* cw  = blk_cw  + (size_t)l * D_INNER * D_CONV;
        const float* cb  = blk_cb  + (size_t)l * D_INNER;
        const float* xpw = blk_xpw + (size_t)l * (DT_RANK + 2 * D_STATE) * D_INNER;
        const float* dtw = blk_dtw + (size_t)l * D_INNER * DT_RANK;
        const float* dtb = blk_dtb + (size_t)l * D_INNER;
        const float* Al  = blk_Al  + (size_t)l * D_INNER * D_STATE;
        const float* Dp  = blk_D   + (size_t)l * D_INNER;
        const float* opw = blk_opw + (size_t)l * D_MODEL * D_INNER;

        // hl' = layernorm(hs)
        ln_kernel<<<M_ROWS, D_MODEL>>>(hs, ng, nb, lt, 0);
        // xz = hl' @ ipw^T  (N=1024, K=256)
        gemm_kernel<<<dim3(2 * D_INNER / BN, M_ROWS / BM), blk256>>>(
            lt, ipw, nullptr, nullptr, xz, M_ROWS, 2 * D_INNER, D_MODEL, 0);
        // u = silu(causal_conv(xz[:, :512]))
        conv_silu_kernel<<<(M_ROWS * D_INNER + 255) / 256, blk256>>>(xz, cw, cb, u);
        // xdbc = u @ xpw^T   (N=48, K=512)
        gemm_kernel<<<dim3(1, M_ROWS / BM), blk256>>>(
            u, xpw, nullptr, nullptr, xdbc, M_ROWS, DT_RANK + 2 * D_STATE, D_INNER, 0);
        // delta = softplus(dt @ dtw^T + dtb)
        delta_kernel<<<(M_ROWS * D_INNER + 255) / 256, blk256>>>(xdbc, dtw, dtb, dlt);
        // selective scan + gate
        scan_kernel<<<(BATCH * D_INNER) / 16, blk256>>>(dlt, u, xdbc, xz, Al, Dp, y);
        // hs = hs + y @ opw^T  (N=256, K=512)
        gemm_kernel<<<dim3(D_MODEL / BN, M_ROWS / BM), blk256>>>(
            y, opw, nullptr, hs, hs, M_ROWS, D_MODEL, D_INNER, 0);
    }

    // head: h2 = gelu(hs @ op_w^T + op_b)
    gemm_kernel<<<dim3(D_MODEL / BN, M_ROWS / BM), blk256>>>(
        hs, op_w, op_b, nullptr, h2, M_ROWS, D_MODEL, D_MODEL, 1);
    // logits = h2 @ cls_w^T + cls_b  -> d_out[0 .. 4096*128)
    gemm_kernel<<<dim3(N_CLS / BN, M_ROWS / BM), blk256>>>(
        h2, cls_w, cls_b, nullptr, out, M_ROWS, N_CLS, D_MODEL, 0);
    // loss = 0.01 * mean(||h2||_2) -> d_out[last]
    rownorm_kernel<<<M_ROWS, D_MODEL>>>(h2, nrm);
    loss_kernel<<<1, 1024>>>(nrm, out + (out_size - 1));
}

// round 2
// speedup vs baseline: 2.3053x; 2.3053x over previous
#include <cuda_runtime.h>
#include <math.h>

#define BATCH    4
#define SEQ      1024
#define M_ROWS   4096
#define D_MODEL  256
#define D_INNER  512
#define D_STATE  16
#define DT_RANK  16
#define D_CONV   4
#define N_LAYERS 2
#define X_DIM    768
#define N_CLS    128

// ---------------------------------------------------------------------------
// Scratch
// ---------------------------------------------------------------------------
__device__ float g_h   [M_ROWS * D_MODEL];
__device__ float g_hl  [M_ROWS * D_MODEL];
__device__ float g_xz  [M_ROWS * 2 * D_INNER];
__device__ float g_u   [M_ROWS * D_INNER];     // [b][t][d]
__device__ float g_ut  [M_ROWS * D_INNER];     // [b][d][t]
__device__ float g_dlt [M_ROWS * D_INNER];     // [b][t][d]
__device__ float g_dltt[M_ROWS * D_INNER];     // [b][d][t]
__device__ float g_yt  [M_ROWS * D_INNER];     // [b][d][t]
__device__ float g_y   [M_ROWS * D_INNER];     // [b][t][d]
__device__ float g_xdbc[M_ROWS * 48];
__device__ float g_h2  [M_ROWS * D_MODEL];
__device__ float g_norm[M_ROWS];

__device__ __forceinline__ float gelu_f(float v) {
    return 0.5f * v * (1.f + erff(v * 0.70710678118654752f));
}

// ---------------------------------------------------------------------------
// GEMM: C[M,N] = A[M,K] @ W[N,K]^T (+bias)(+res)(+gelu)
// 128x64 block tile, BK=16, 256 threads, 8x4 per thread, float4 everywhere.
// Requires M%128==0, K%16==0, N%4==0.
// ---------------------------------------------------------------------------
template<int ACT>
__global__ __launch_bounds__(256) void gemm_k(
    const float* __restrict__ A, const float* __restrict__ W,
    const float* __restrict__ bias, const float* __restrict__ res,
    float* __restrict__ C, int M, int N, int K)
{
    __shared__ float As[16][132];
    __shared__ float Ws[16][68];
    const int tid = threadIdx.x;
    const int m0 = blockIdx.y * 128;
    const int n0 = blockIdx.x * 64;
    const int tm = tid >> 4;        // 0..15 (rows-of-8)
    const int tn = tid & 15;        // 0..15 (cols-of-4)
    const int lr = tid >> 2;        // 0..63
    const int lc = (tid & 3) * 4;   // 0,4,8,12

    float acc[8][4] = {};

    for (int k0 = 0; k0 < K; k0 += 16) {
        #pragma unroll
        for (int i = 0; i < 2; i++) {
            int r = lr + i * 64;
            float4 v = *(const float4*)(A + (size_t)(m0 + r) * K + k0 + lc);
            As[lc + 0][r] = v.x; As[lc + 1][r] = v.y;
            As[lc + 2][r] = v.z; As[lc + 3][r] = v.w;
        }
        {
            float4 v = make_float4(0.f, 0.f, 0.f, 0.f);
            if (n0 + lr < N)
                v = *(const float4*)(W + (size_t)(n0 + lr) * K + k0 + lc);
            Ws[lc + 0][lr] = v.x; Ws[lc + 1][lr] = v.y;
            Ws[lc + 2][lr] = v.z; Ws[lc + 3][lr] = v.w;
        }
        __syncthreads();
        #pragma unroll
        for (int kk = 0; kk < 16; kk++) {
            float4 a0 = *(const float4*)&As[kk][tm * 8];
            float4 a1 = *(const float4*)&As[kk][tm * 8 + 4];
            float4 b4 = *(const float4*)&Ws[kk][tn * 4];
            float a[8] = {a0.x, a0.y, a0.z, a0.w, a1.x, a1.y, a1.z, a1.w};
            float b[4] = {b4.x, b4.y, b4.z, b4.w};
            #pragma unroll
            for (int i = 0; i < 8; i++)
                #pragma unroll
                for (int j = 0; j < 4; j++)
                    acc[i][j] = fmaf(a[i], b[j], acc[i][j]);
        }
        __syncthreads();
    }

    const int n = n0 + tn * 4;
    if (n >= N) return;
    float4 bv = make_float4(0.f, 0.f, 0.f, 0.f);
    if (bias) bv = *(const float4*)(bias + n);
    #pragma unroll
    for (int i = 0; i < 8; i++) {
        int m = m0 + tm * 8 + i;
        float4 v = {acc[i][0] + bv.x, acc[i][1] + bv.y,
                    acc[i][2] + bv.z, acc[i][3] + bv.w};
        if (res) {
            float4 r4 = *(const float4*)(res + (size_t)m * N + n);
            v.x += r4.x; v.y += r4.y; v.z += r4.z; v.w += r4.w;
        }
        if (ACT) {
            v.x = gelu_f(v.x); v.y = gelu_f(v.y);
            v.z = gelu_f(v.z); v.w = gelu_f(v.w);
        }
        *(float4*)(C + (size_t)m * N + n) = v;
    }
}

// ---------------------------------------------------------------------------
// LayerNorm over 256 cols, one block per row, optional gelu
// ---------------------------------------------------------------------------
__global__ void ln_kernel(const float* __restrict__ x, const float* __restrict__ g,
                          const float* __restrict__ b, float* __restrict__ out, int do_gelu)
{
    const int row = blockIdx.x;
    const int tid = threadIdx.x;
    float v = x[(size_t)row * D_MODEL + tid];
    float s1 = v, s2 = v * v;
    #pragma unroll
    for (int o = 16; o > 0; o >>= 1) {
        s1 += __shfl_xor_sync(0xffffffffu, s1, o);
        s2 += __shfl_xor_sync(0xffffffffu, s2, o);
    }
    __shared__ float sm1[8], sm2[8];
    __shared__ float mu_s, rstd_s;
    if ((tid & 31) == 0) { sm1[tid >> 5] = s1; sm2[tid >> 5] = s2; }
    __syncthreads();
    if (tid == 0) {
        float t1 = 0.f, t2 = 0.f;
        #pragma unroll
        for (int i = 0; i < 8; i++) { t1 += sm1[i]; t2 += sm2[i]; }
        float mu  = t1 * (1.f / 256.f);
        float var = t2 * (1.f / 256.f) - mu * mu;
        mu_s = mu;
        rstd_s = rsqrtf(var + 1e-5f);
    }
    __syncthreads();
    float y = (v - mu_s) * rstd_s * g[tid] + b[tid];
    if (do_gelu) y = gelu_f(y);
    out[(size_t)row * D_MODEL + tid] = y;
}

// ---------------------------------------------------------------------------
// Depthwise causal conv (k=4) + SiLU. xz row-major; u row-major.
// ---------------------------------------------------------------------------
__global__ void conv_silu_kernel(const float* __restrict__ xz, const float* __restrict__ cw,
                                 const float* __restrict__ cb, float* __restrict__ u)
{
    int idx = blockIdx.x * blockDim.x + threadIdx.x;
    if (idx >= M_ROWS * D_INNER) return;
    int d = idx & (D_INNER - 1);
    int l = (idx / D_INNER) & (SEQ - 1);
    int b = idx / (D_INNER * SEQ);
    float acc = cb[d];
    #pragma unroll
    for (int j = 0; j < D_CONV; j++) {
        int ll = l - (D_CONV - 1) + j;
        if (ll >= 0)
            acc = fmaf(cw[d * D_CONV + j],
                       xz[((size_t)(b * SEQ + ll)) * (2 * D_INNER) + d], acc);
    }
    u[idx] = acc / (1.f + __expf(-acc));
}

// ---------------------------------------------------------------------------
// delta = softplus(dt @ dtw^T + dtb), row-major out
// ---------------------------------------------------------------------------
__global__ void delta_kernel(const float* __restrict__ xdbc, const float* __restrict__ dtw,
                             const float* __restrict__ dtb, float* __restrict__ dlt)
{
    int idx = blockIdx.x * blockDim.x + threadIdx.x;
    if (idx >= M_ROWS * D_INNER) return;
    int d = idx & (D_INNER - 1);
    int row = idx / D_INNER;
    const float* dt = xdbc + (size_t)row * 48;
    float acc = dtb[d];
    #pragma unroll
    for (int r = 0; r < DT_RANK; r++)
        acc = fmaf(__ldg(dt + r), dtw[d * DT_RANK + r], acc);
    dlt[idx] = (acc > 20.f) ? acc : log1pf(__expf(acc));
}

// ---------------------------------------------------------------------------
// Tiled transpose of u and dlt: [b][t][d] -> [b][d][t]
// grid (SEQ/32, D_INNER/32, BATCH), block (32,8)
// ---------------------------------------------------------------------------
__global__ void transpose2_kernel(const float* __restrict__ u, const float* __restrict__ dlt,
                                  float* __restrict__ ut, float* __restrict__ dltt)
{
    __shared__ float t0[32][33], t1[32][33];
    const int b = blockIdx.z;
    const int tblk = blockIdx.x * 32, dblk = blockIdx.y * 32;
    const int tx = threadIdx.x, ty = threadIdx.y;
    #pragma unroll
    for (int i = 0; i < 4; i++) {
        int t = tblk + ty + i * 8;
        size_t idx = (size_t)(b * SEQ + t) * D_INNER + dblk + tx;
        t0[ty + i * 8][tx] = u[idx];
        t1[ty + i * 8][tx] = dlt[idx];
    }
    __syncthreads();
    #pragma unroll
    for (int i = 0; i < 4; i++) {
        int d = dblk + ty + i * 8;
        size_t idx = (size_t)(b * D_INNER + d) * SEQ + tblk + tx;
        ut[idx]   = t0[tx][ty + i * 8];
        dltt[idx] = t1[tx][ty + i * 8];
    }
}

// ---------------------------------------------------------------------------
// Gate + transpose back: y[b][t][d] = yt[b][d][t] * silu(z[b][t][d])
// ---------------------------------------------------------------------------
__global__ void gate_kernel(const float* __restrict__ yt, const float* __restrict__ xz,
                            float* __restrict__ y)
{
    __shared__ float t0[32][33];
    const int b = blockIdx.z;
    const int tblk = blockIdx.x * 32, dblk = blockIdx.y * 32;
    const int tx = threadIdx.x, ty = threadIdx.y;
    #pragma unroll
    for (int i = 0; i < 4; i++) {
        int d = dblk + ty + i * 8;
        t0[ty + i * 8][tx] = yt[(size_t)(b * D_INNER + d) * SEQ + tblk + tx];
    }
    __syncthreads();
    #pragma unroll
    for (int i = 0; i < 4; i++) {
        int t = tblk + ty + i * 8;
        size_t row = (size_t)(b * SEQ + t);
        float z = xz[row * (2 * D_INNER) + D_INNER + dblk + tx];
        float g = z / (1.f + __expf(-z));
        y[row * D_INNER + dblk + tx] = t0[tx][ty + i * 8] * g;
    }
}

// ---------------------------------------------------------------------------
// Selective scan. 16 lanes per (b,d), lane n owns state n.
// Coalesced chunked loads (16 timesteps / 64B per group), coalesced stores.
// ---------------------------------------------------------------------------
__global__ __launch_bounds__(128) void scan_kernel(
    const float* __restrict__ dltt, const float* __restrict__ ut,
    const float* __restrict__ xdbc, const float* __restrict__ A_log,
    const float* __restrict__ Dp, float* __restrict__ yt)
{
    const int tid = threadIdx.x;
    const int gid = blockIdx.x * (blockDim.x >> 4) + (tid >> 4);  // 0..2047
    const int n = tid & 15;
    const int b = gid >> 9;
    const int d = gid & (D_INNER - 1);
    const float A  = -__expf(A_log[d * D_STATE + n]);
    const float Dd = Dp[d];
    const size_t base = (size_t)gid * SEQ;
    const float* xb = xdbc + (size_t)b * SEQ * 48;
    float s = 0.f;
    for (int tc = 0; tc < SEQ; tc += 16) {
        const float dt16 = dltt[base + tc + n];
        const float u16  = ut  [base + tc + n];
        float rv = 0.f;
        #pragma unroll
        for (int j = 0; j < 16; j++) {
            const float dtj = __shfl_sync(0xffffffffu, dt16, j, 16);
            const float utj = __shfl_sync(0xffffffffu, u16,  j, 16);
            const float* xr = xb + (size_t)(tc + j) * 48;
            const float Bn = __ldg(xr + DT_RANK + n);
            const float Cn = __ldg(xr + DT_RANK + D_STATE + n);
            s = fmaf(s, __expf(dtj * A), dtj * utj * Bn);
            float v = s * Cn;
            #pragma unroll
            for (int o = 8; o > 0; o >>= 1) v += __shfl_xor_sync(0xffffffffu, v, o);
            if (n == j) rv = v + utj * Dd;
        }
        yt[base + tc + n] = rv;
    }
}

// ---------------------------------------------------------------------------
// Row L2 norms + loss
// ---------------------------------------------------------------------------
__global__ void rownorm_kernel(const float* __restrict__ h, float* __restrict__ nrm)
{
    const int row = blockIdx.x;
    const int tid = threadIdx.x;
    float v = h[(size_t)row * D_MODEL + tid];
    float s = v * v;
    #pragma unroll
    for (int o = 16; o > 0; o >>= 1) s += __shfl_xor_sync(0xffffffffu, s, o);
    __shared__ float sm[8];
    if ((tid & 31) == 0) sm[tid >> 5] = s;
    __syncthreads();
    if (tid == 0) {
        float t = 0.f;
        #pragma unroll
        for (int i = 0; i < 8; i++) t += sm[i];
        nrm[row] = sqrtf(t);
    }
}

__global__ void loss_kernel(const float* __restrict__ nrm, float* __restrict__ out)
{
    const int tid = threadIdx.x; // 1024
    float s = 0.f;
    #pragma unroll
    for (int i = 0; i < 4; i++) s += nrm[tid + i * 1024];
    #pragma unroll
    for (int o = 16; o > 0; o >>= 1) s += __shfl_xor_sync(0xffffffffu, s, o);
    __shared__ float sm[32];
    if ((tid & 31) == 0) sm[tid >> 5] = s;
    __syncthreads();
    if (tid == 0) {
        float t = 0.f;
        #pragma unroll
        for (int i = 0; i < 32; i++) t += sm[i];
        *out = 0.01f * t * (1.f / (float)M_ROWS);
    }
}

// ---------------------------------------------------------------------------
// Launch
// ---------------------------------------------------------------------------
extern "C" void kernel_launch(void* const* d_in, const int* in_sizes, int n_in,
                              void* d_out, int out_size)
{
    const float* x      = (const float*)d_in[0];
    const float* in_w   = (const float*)d_in[1];
    const float* in_b   = (const float*)d_in[2];
    const float* ln_g   = (const float*)d_in[3];
    const float* ln_b   = (const float*)d_in[4];
    const float* blk_ng = (const float*)d_in[5];
    const float* blk_nb = (const float*)d_in[6];
    const float* blk_ipw= (const float*)d_in[7];
    const float* blk_cw = (const float*)d_in[8];
    const float* blk_cb = (const float*)d_in[9];
    const float* blk_xpw= (const float*)d_in[10];
    const float* blk_dtw= (const float*)d_in[11];
    const float* blk_dtb= (const float*)d_in[12];
    const float* blk_Al = (const float*)d_in[13];
    const float* blk_D  = (const float*)d_in[14];
    const float* blk_opw= (const float*)d_in[15];
    const float* op_w   = (const float*)d_in[16];
    const float* op_b   = (const float*)d_in[17];
    const float* cls_w  = (const float*)d_in[18];
    const float* cls_b  = (const float*)d_in[19];
    float* out = (float*)d_out;

    float *h, *hl, *xz, *u, *ut, *dlt, *dltt, *yt, *y, *xdbc, *h2, *nrm;
    cudaGetSymbolAddress((void**)&h,    g_h);
    cudaGetSymbolAddress((void**)&hl,   g_hl);
    cudaGetSymbolAddress((void**)&xz,   g_xz);
    cudaGetSymbolAddress((void**)&u,    g_u);
    cudaGetSymbolAddress((void**)&ut,   g_ut);
    cudaGetSymbolAddress((void**)&dlt,  g_dlt);
    cudaGetSymbolAddress((void**)&dltt, g_dltt);
    cudaGetSymbolAddress((void**)&yt,   g_yt);
    cudaGetSymbolAddress((void**)&y,    g_y);
    cudaGetSymbolAddress((void**)&xdbc, g_xdbc);
    cudaGetSymbolAddress((void**)&h2,   g_h2);
    cudaGetSymbolAddress((void**)&nrm,  g_norm);

    dim3 blk256(256);
    dim3 tblk(32, 8);
    dim3 tgrid(SEQ / 32, D_INNER / 32, BATCH);

    // h = x @ in_w^T + in_b
    gemm_k<0><<<dim3(D_MODEL / 64, M_ROWS / 128), blk256>>>(
        x, in_w, in_b, nullptr, h, M_ROWS, D_MODEL, X_DIM);
    // hs = gelu(layernorm(h))
    ln_kernel<<<M_ROWS, D_MODEL>>>(h, ln_g, ln_b, hl, 1);
    float* hs = hl;
    float* lt = h;

    for (int l = 0; l < N_LAYERS; l++) {
        const float* ng  = blk_ng  + (size_t)l * D_MODEL;
        const float* nb  = blk_nb  + (size_t)l * D_MODEL;
        const float* ipw = blk_ipw + (size_t)l * 2 * D_INNER * D_MODEL;
        const float* cw  = blk_cw  + (size_t)l * D_INNER * D_CONV;
        const float* cb  = blk_cb  + (size_t)l * D_INNER;
        const float* xpw = blk_xpw + (size_t)l * 48 * D_INNER;
        const float* dtw = blk_dtw + (size_t)l * D_INNER * DT_RANK;
        const float* dtb = blk_dtb + (size_t)l * D_INNER;
        const float* Al  = blk_Al  + (size_t)l * D_INNER * D_STATE;
        const float* Dp  = blk_D   + (size_t)l * D_INNER;
        const float* opw = blk_opw + (size_t)l * D_MODEL * D_INNER;

        ln_kernel<<<M_ROWS, D_MODEL>>>(hs, ng, nb, lt, 0);
        gemm_k<0><<<dim3(2 * D_INNER / 64, M_ROWS / 128), blk256>>>(
            lt, ipw, nullptr, nullptr, xz, M_ROWS, 2 * D_INNER, D_MODEL);
        conv_silu_kernel<<<(M_ROWS * D_INNER + 255) / 256, blk256>>>(xz, cw, cb, u);
        gemm_k<0><<<dim3(1, M_ROWS / 128), blk256>>>(
            u, xpw, nullptr, nullptr, xdbc, M_ROWS, 48, D_INNER);
        delta_kernel<<<(M_ROWS * D_INNER + 255) / 256, blk256>>>(xdbc, dtw, dtb, dlt);
        transpose2_kernel<<<tgrid, tblk>>>(u, dlt, ut, dltt);
        scan_kernel<<<(BATCH * D_INNER) / 8, 128>>>(dltt, ut, xdbc, Al, Dp, yt);
        gate_kernel<<<tgrid, tblk>>>(yt, xz, y);
        gemm_k<0><<<dim3(D_MODEL / 64, M_ROWS / 128), blk256>>>(
            y, opw, nullptr, hs, hs, M_ROWS, D_MODEL, D_INNER);
    }

    gemm_k<1><<<dim3(D_MODEL / 64, M_ROWS / 128), blk256>>>(
        hs, op_w, op_b, nullptr, h2, M_ROWS, D_MODEL, D_MODEL);
    gemm_k<0><<<dim3(N_CLS / 64, M_ROWS / 128), blk256>>>(
        h2, cls_w, cls_b, nullptr, out, M_ROWS, N_CLS, D_MODEL);
    rownorm_kernel<<<M_ROWS, D_MODEL>>>(h2, nrm);
    loss_kernel<<<1, 1024>>>(nrm, out + (out_size - 1));
}

// round 3
// speedup vs baseline: 2.8295x; 1.2274x over previous
#include <cuda_runtime.h>
#include <math.h>

#define BATCH    4
#define SEQ      1024
#define M_ROWS   4096
#define D_MODEL  256
#define D_INNER  512
#define D_STATE  16
#define DT_RANK  16
#define D_CONV   4
#define N_LAYERS 2
#define X_DIM    768
#define N_CLS    128

// ---------------------------------------------------------------------------
// Scratch
// ---------------------------------------------------------------------------
__device__ float g_h   [M_ROWS * D_MODEL];
__device__ float g_hl  [M_ROWS * D_MODEL];
__device__ float g_xz  [M_ROWS * 2 * D_INNER];
__device__ float g_u   [M_ROWS * D_INNER];     // [b][t][d]
__device__ float g_ut  [M_ROWS * D_INNER];     // [b][d][t]
__device__ float g_dltt[M_ROWS * D_INNER];     // [b][d][t]
__device__ float g_yt  [M_ROWS * D_INNER];     // [b][d][t]
__device__ float g_y   [M_ROWS * D_INNER];     // [b][t][d]
__device__ float g_xdbc[M_ROWS * 48];
__device__ float g_h2  [M_ROWS * D_MODEL];
__device__ float g_norm[M_ROWS];
__device__ float g_part[2 * M_ROWS * D_MODEL]; // split-K partials (max 2x4096x256)

__device__ __forceinline__ float gelu_f(float v) {
    return 0.5f * v * (1.f + erff(v * 0.70710678118654752f));
}
__device__ __forceinline__ float silu_f(float v) {
    return v / (1.f + __expf(-v));
}

// ---------------------------------------------------------------------------
// Double-buffered GEMM: C[M,N] = A[M,K] @ W[N,K]^T
// 128x128 tile, BK=8, 256 threads, 8x8 per thread.
// SPLIT>1: blockIdx.z selects K-chunk, writes raw partial to C + z*M*N.
// SPLIT==1: direct store with optional bias/res/act.
// Requires M%128==0, N%128==0, (K/SPLIT)%8==0.
// ---------------------------------------------------------------------------
template<int SPLIT, int ACT, int BIAS, int RES>
__global__ __launch_bounds__(256) void gemm128(
    const float* __restrict__ A, const float* __restrict__ W,
    const float* __restrict__ bias, const float* __restrict__ res,
    float* __restrict__ C, int M, int N, int K)
{
    __shared__ float As[2][8][132];
    __shared__ float Bs[2][8][132];
    const int tid = threadIdx.x;
    const int m0 = blockIdx.y * 128;
    const int n0 = blockIdx.x * 128;
    const int Kc = K / SPLIT;
    const int kbeg = blockIdx.z * Kc;

    const int lr = tid >> 1;            // 0..127
    const int lc = (tid & 1) * 4;       // 0 or 4
    const float* Aload = A + (size_t)(m0 + lr) * K + kbeg + lc;
    const float* Wload = W + (size_t)(n0 + lr) * K + kbeg + lc;

    const int tm = (tid >> 4) * 4;      // 0..60
    const int tn = (tid & 15) * 4;      // 0..60

    float acc[8][8] = {};

    float4 a_reg = *(const float4*)Aload;
    float4 w_reg = *(const float4*)Wload;
    As[0][lc + 0][lr] = a_reg.x; As[0][lc + 1][lr] = a_reg.y;
    As[0][lc + 2][lr] = a_reg.z; As[0][lc + 3][lr] = a_reg.w;
    Bs[0][lc + 0][lr] = w_reg.x; Bs[0][lc + 1][lr] = w_reg.y;
    Bs[0][lc + 2][lr] = w_reg.z; Bs[0][lc + 3][lr] = w_reg.w;
    __syncthreads();

    const int iters = Kc / 8;
    int buf = 0;
    for (int it = 0; it < iters; it++) {
        if (it + 1 < iters) {
            a_reg = *(const float4*)(Aload + (it + 1) * 8);
            w_reg = *(const float4*)(Wload + (it + 1) * 8);
        }
        #pragma unroll
        for (int kk = 0; kk < 8; kk++) {
            float a[8], b[8];
            *(float4*)&a[0] = *(const float4*)&As[buf][kk][tm];
            *(float4*)&a[4] = *(const float4*)&As[buf][kk][tm + 64];
            *(float4*)&b[0] = *(const float4*)&Bs[buf][kk][tn];
            *(float4*)&b[4] = *(const float4*)&Bs[buf][kk][tn + 64];
            #pragma unroll
            for (int i = 0; i < 8; i++)
                #pragma unroll
                for (int j = 0; j < 8; j++)
                    acc[i][j] = fmaf(a[i], b[j], acc[i][j]);
        }
        if (it + 1 < iters) {
            buf ^= 1;
            As[buf][lc + 0][lr] = a_reg.x; As[buf][lc + 1][lr] = a_reg.y;
            As[buf][lc + 2][lr] = a_reg.z; As[buf][lc + 3][lr] = a_reg.w;
            Bs[buf][lc + 0][lr] = w_reg.x; Bs[buf][lc + 1][lr] = w_reg.y;
            Bs[buf][lc + 2][lr] = w_reg.z; Bs[buf][lc + 3][lr] = w_reg.w;
            __syncthreads();
        }
    }

    float* Cout = (SPLIT > 1) ? (C + (size_t)blockIdx.z * M * N) : C;
    #pragma unroll
    for (int i = 0; i < 8; i++) {
        const int m = m0 + tm + ((i < 4) ? i : (64 + i - 4));
        #pragma unroll
        for (int jh = 0; jh < 2; jh++) {
            const int n = n0 + tn + jh * 64;
            float4 v = {acc[i][jh * 4 + 0], acc[i][jh * 4 + 1],
                        acc[i][jh * 4 + 2], acc[i][jh * 4 + 3]};
            if (SPLIT == 1) {
                if (BIAS) {
                    float4 bv = *(const float4*)(bias + n);
                    v.x += bv.x; v.y += bv.y; v.z += bv.z; v.w += bv.w;
                }
                if (RES) {
                    float4 r4 = *(const float4*)(res + (size_t)m * N + n);
                    v.x += r4.x; v.y += r4.y; v.z += r4.z; v.w += r4.w;
                }
                if (ACT) {
                    v.x = gelu_f(v.x); v.y = gelu_f(v.y);
                    v.z = gelu_f(v.z); v.w = gelu_f(v.w);
                }
            }
            *(float4*)(Cout + (size_t)m * N + n) = v;
        }
    }
}

// ---------------------------------------------------------------------------
// xpw GEMM (N=48): 128x64 tile w/ split-K partials. grid (1, M/128, SPLIT)
// ---------------------------------------------------------------------------
__global__ __launch_bounds__(256) void gemm_xpw(
    const float* __restrict__ A, const float* __restrict__ W,
    float* __restrict__ Cp, int M, int N, int K, int splitK)
{
    __shared__ float As[16][132];
    __shared__ float Ws[16][68];
    const int tid = threadIdx.x;
    const int m0 = blockIdx.y * 128;
    const int Kc = K / splitK;
    const int kbeg = blockIdx.z * Kc;
    const int tm = tid >> 4;
    const int tn = tid & 15;
    const int lr = tid >> 2;
    const int lc = (tid & 3) * 4;

    float acc[8][4] = {};

    for (int k0 = kbeg; k0 < kbeg + Kc; k0 += 16) {
        #pragma unroll
        for (int i = 0; i < 2; i++) {
            int r = lr + i * 64;
            float4 v = *(const float4*)(A + (size_t)(m0 + r) * K + k0 + lc);
            As[lc + 0][r] = v.x; As[lc + 1][r] = v.y;
            As[lc + 2][r] = v.z; As[lc + 3][r] = v.w;
        }
        {
            float4 v = make_float4(0.f, 0.f, 0.f, 0.f);
            if (lr < N)
                v = *(const float4*)(W + (size_t)lr * K + k0 + lc);
            Ws[lc + 0][lr] = v.x; Ws[lc + 1][lr] = v.y;
            Ws[lc + 2][lr] = v.z; Ws[lc + 3][lr] = v.w;
        }
        __syncthreads();
        #pragma unroll
        for (int kk = 0; kk < 16; kk++) {
            float a[8], b[4];
            *(float4*)&a[0] = *(const float4*)&As[kk][tm * 8];
            *(float4*)&a[4] = *(const float4*)&As[kk][tm * 8 + 4];
            *(float4*)&b[0] = *(const float4*)&Ws[kk][tn * 4];
            #pragma unroll
            for (int i = 0; i < 8; i++)
                #pragma unroll
                for (int j = 0; j < 4; j++)
                    acc[i][j] = fmaf(a[i], b[j], acc[i][j]);
        }
        __syncthreads();
    }

    const int n = tn * 4;
    if (n >= N) return;
    float* Cout = Cp + (size_t)blockIdx.z * M * N;
    #pragma unroll
    for (int i = 0; i < 8; i++) {
        int m = m0 + tm * 8 + i;
        float4 v = {acc[i][0], acc[i][1], acc[i][2], acc[i][3]};
        *(float4*)(Cout + (size_t)m * N + n) = v;
    }
}

// ---------------------------------------------------------------------------
// Split-K reduce + fused epilogue
// ---------------------------------------------------------------------------
template<int S, int BIAS, int RES, int ACT>
__global__ void reduce_k(const float* __restrict__ part, const float* __restrict__ bias,
                         const float* __restrict__ res, float* __restrict__ out,
                         int MN, int N)
{
    int i4 = (blockIdx.x * blockDim.x + threadIdx.x) * 4;
    if (i4 >= MN) return;
    float4 v = *(const float4*)(part + i4);
    #pragma unroll
    for (int s = 1; s < S; s++) {
        float4 p = *(const float4*)(part + (size_t)s * MN + i4);
        v.x += p.x; v.y += p.y; v.z += p.z; v.w += p.w;
    }
    if (BIAS) {
        float4 bv = *(const float4*)(bias + (i4 % N));
        v.x += bv.x; v.y += bv.y; v.z += bv.z; v.w += bv.w;
    }
    if (RES) {
        float4 r4 = *(const float4*)(res + i4);
        v.x += r4.x; v.y += r4.y; v.z += r4.z; v.w += r4.w;
    }
    if (ACT) {
        v.x = gelu_f(v.x); v.y = gelu_f(v.y);
        v.z = gelu_f(v.z); v.w = gelu_f(v.w);
    }
    *(float4*)(out + i4) = v;
}

// ---------------------------------------------------------------------------
// LayerNorm over 256 cols, one block per row, optional gelu
// ---------------------------------------------------------------------------
__global__ void ln_kernel(const float* __restrict__ x, const float* __restrict__ g,
                          const float* __restrict__ b, float* __restrict__ out, int do_gelu)
{
    const int row = blockIdx.x;
    const int tid = threadIdx.x;
    float v = x[(size_t)row * D_MODEL + tid];
    float s1 = v, s2 = v * v;
    #pragma unroll
    for (int o = 16; o > 0; o >>= 1) {
        s1 += __shfl_xor_sync(0xffffffffu, s1, o);
        s2 += __shfl_xor_sync(0xffffffffu, s2, o);
    }
    __shared__ float sm1[8], sm2[8];
    __shared__ float mu_s, rstd_s;
    if ((tid & 31) == 0) { sm1[tid >> 5] = s1; sm2[tid >> 5] = s2; }
    __syncthreads();
    if (tid == 0) {
        float t1 = 0.f, t2 = 0.f;
        #pragma unroll
        for (int i = 0; i < 8; i++) { t1 += sm1[i]; t2 += sm2[i]; }
        float mu  = t1 * (1.f / 256.f);
        float var = t2 * (1.f / 256.f) - mu * mu;
        mu_s = mu;
        rstd_s = rsqrtf(var + 1e-5f);
    }
    __syncthreads();
    float y = (v - mu_s) * rstd_s * g[tid] + b[tid];
    if (do_gelu) y = gelu_f(y);
    out[(size_t)row * D_MODEL + tid] = y;
}

// ---------------------------------------------------------------------------
// Depthwise causal conv (k=4) + SiLU -> writes u [b][t][d] AND ut [b][d][t]
// grid (SEQ/32, D_INNER/32, B), block (32,8)
// ---------------------------------------------------------------------------
__global__ void conv2_kernel(const float* __restrict__ xz, const float* __restrict__ cw,
                             const float* __restrict__ cb, float* __restrict__ u,
                             float* __restrict__ ut)
{
    __shared__ float tile[32][33];
    const int b = blockIdx.z;
    const int t0 = blockIdx.x * 32, d0 = blockIdx.y * 32;
    const int tx = threadIdx.x, ty = threadIdx.y;
    const int d = d0 + tx;
    const float w0 = cw[d * 4 + 0], w1 = cw[d * 4 + 1];
    const float w2 = cw[d * 4 + 2], w3 = cw[d * 4 + 3];
    const float bb = cb[d];
    #pragma unroll
    for (int i = 0; i < 4; i++) {
        const int t = t0 + ty + i * 8;
        const size_t rbase = (size_t)(b * SEQ + t) * (2 * D_INNER) + d;
        float acc = bb;
        if (t >= 3) acc = fmaf(w0, xz[rbase - 3 * 2 * D_INNER], acc);
        else if (t >= 3) {}
        if (t >= 3) {
            acc = fmaf(w1, xz[rbase - 2 * 2 * D_INNER], acc);
            acc = fmaf(w2, xz[rbase - 1 * 2 * D_INNER], acc);
        } else {
            if (t >= 2) acc = fmaf(w1, xz[rbase - 2 * 2 * D_INNER], acc);
            if (t >= 1) acc = fmaf(w2, xz[rbase - 1 * 2 * D_INNER], acc);
        }
        acc = fmaf(w3, xz[rbase], acc);
        acc = silu_f(acc);
        u[(size_t)(b * SEQ + t) * D_INNER + d] = acc;
        tile[ty + i * 8][tx] = acc;
    }
    __syncthreads();
    #pragma unroll
    for (int i = 0; i < 4; i++) {
        const int dd = d0 + ty + i * 8;
        ut[(size_t)(b * D_INNER + dd) * SEQ + t0 + tx] = tile[tx][ty + i * 8];
    }
}

// ---------------------------------------------------------------------------
// delta = softplus(dt @ dtw^T + dtb), written transposed -> dltt [b][d][t]
// grid (SEQ/32, D_INNER/32, B), block (32,8)
// ---------------------------------------------------------------------------
__global__ void deltaT_kernel(const float* __restrict__ xdbc, const float* __restrict__ dtw,
                              const float* __restrict__ dtb, float* __restrict__ dltt)
{
    __shared__ float w_s[32][17];
    __shared__ float b_s[32];
    __shared__ float tile[32][33];
    const int b = blockIdx.z;
    const int t0 = blockIdx.x * 32, d0 = blockIdx.y * 32;
    const int tx = threadIdx.x, ty = threadIdx.y;
    const int tid = ty * 32 + tx;
    // stage dtw[d0..d0+31][0..15] and dtb
    {
        int r = tid >> 4, c = tid & 15;          // 16 rows per 256 threads x2
        w_s[r][c] = dtw[(d0 + r) * DT_RANK + c];
        w_s[r + 16][c] = dtw[(d0 + r + 16) * DT_RANK + c];
        if (tid < 32) b_s[tid] = dtb[d0 + tid];
    }
    __syncthreads();
    #pragma unroll
    for (int i = 0; i < 4; i++) {
        const int t = t0 + ty + i * 8;
        const float* xr = xdbc + (size_t)(b * SEQ + t) * 48;
        float acc = b_s[tx];
        #pragma unroll
        for (int r = 0; r < DT_RANK; r++)
            acc = fmaf(__ldg(xr + r), w_s[tx][r], acc);
        tile[ty + i * 8][tx] = (acc > 20.f) ? acc : log1pf(__expf(acc));
    }
    __syncthreads();
    #pragma unroll
    for (int i = 0; i < 4; i++) {
        const int dd = d0 + ty + i * 8;
        dltt[(size_t)(b * D_INNER + dd) * SEQ + t0 + tx] = tile[tx][ty + i * 8];
    }
}

// ---------------------------------------------------------------------------
// Selective scan: 16 lanes per (b,d), lane n owns state n.
// dt/u chunks loaded as uniform float4 vectors (no broadcast shfls).
// ---------------------------------------------------------------------------
__global__ __launch_bounds__(128) void scan_kernel(
    const float* __restrict__ dltt, const float* __restrict__ ut,
    const float* __restrict__ xdbc, const float* __restrict__ A_log,
    const float* __restrict__ Dp, float* __restrict__ yt)
{
    const int tid = threadIdx.x;
    const int gid = blockIdx.x * (blockDim.x >> 4) + (tid >> 4);
    const int n = tid & 15;
    const int b = gid >> 9;
    const int d = gid & (D_INNER - 1);
    const float A  = -__expf(A_log[d * D_STATE + n]);
    const float Dd = Dp[d];
    const size_t base = (size_t)gid * SEQ;
    const float* xb = xdbc + (size_t)b * SEQ * 48 + DT_RANK;
    float s = 0.f;
    for (int tc = 0; tc < SEQ; tc += 16) {
        float dt[16], uu[16];
        #pragma unroll
        for (int q = 0; q < 4; q++) {
            float4 v = ((const float4*)(dltt + base + tc))[q];
            dt[q * 4 + 0] = v.x; dt[q * 4 + 1] = v.y;
            dt[q * 4 + 2] = v.z; dt[q * 4 + 3] = v.w;
            float4 w = ((const float4*)(ut + base + tc))[q];
            uu[q * 4 + 0] = w.x; uu[q * 4 + 1] = w.y;
            uu[q * 4 + 2] = w.z; uu[q * 4 + 3] = w.w;
        }
        float rv = 0.f;
        #pragma unroll
        for (int j = 0; j < 16; j++) {
            const float* xr = xb + (size_t)(tc + j) * 48;
            const float Bn = __ldg(xr + n);
            const float Cn = __ldg(xr + D_STATE + n);
            const float e = __expf(dt[j] * A);
            s = fmaf(s, e, dt[j] * uu[j] * Bn);
            float v = s * Cn;
            #pragma unroll
            for (int o = 8; o > 0; o >>= 1) v += __shfl_xor_sync(0xffffffffu, v, o);
            if (n == j) rv = v + uu[j] * Dd;
        }
        yt[base + tc + n] = rv;
    }
}

// ---------------------------------------------------------------------------
// Gate + transpose back: y[b][t][d] = yt[b][d][t] * silu(z[b][t][d])
// ---------------------------------------------------------------------------
__global__ void gate_kernel(const float* __restrict__ yt, const float* __restrict__ xz,
                            float* __restrict__ y)
{
    __shared__ float t0s[32][33];
    const int b = blockIdx.z;
    const int tblk = blockIdx.x * 32, dblk = blockIdx.y * 32;
    const int tx = threadIdx.x, ty = threadIdx.y;
    #pragma unroll
    for (int i = 0; i < 4; i++) {
        int d = dblk + ty + i * 8;
        t0s[ty + i * 8][tx] = yt[(size_t)(b * D_INNER + d) * SEQ + tblk + tx];
    }
    __syncthreads();
    #pragma unroll
    for (int i = 0; i < 4; i++) {
        int t = tblk + ty + i * 8;
        size_t row = (size_t)(b * SEQ + t);
        float z = xz[row * (2 * D_INNER) + D_INNER + dblk + tx];
        y[row * D_INNER + dblk + tx] = t0s[tx][ty + i * 8] * silu_f(z);
    }
}

// ---------------------------------------------------------------------------
// Row L2 norms + loss
// ---------------------------------------------------------------------------
__global__ void rownorm_kernel(const float* __restrict__ h, float* __restrict__ nrm)
{
    const int row = blockIdx.x;
    const int tid = threadIdx.x;
    float v = h[(size_t)row * D_MODEL + tid];
    float s = v * v;
    #pragma unroll
    for (int o = 16; o > 0; o >>= 1) s += __shfl_xor_sync(0xffffffffu, s, o);
    __shared__ float sm[8];
    if ((tid & 31) == 0) sm[tid >> 5] = s;
    __syncthreads();
    if (tid == 0) {
        float t = 0.f;
        #pragma unroll
        for (int i = 0; i < 8; i++) t += sm[i];
        nrm[row] = sqrtf(t);
    }
}

__global__ void loss_kernel(const float* __restrict__ nrm, float* __restrict__ out)
{
    const int tid = threadIdx.x; // 1024
    float s = 0.f;
    #pragma unroll
    for (int i = 0; i < 4; i++) s += nrm[tid + i * 1024];
    #pragma unroll
    for (int o = 16; o > 0; o >>= 1) s += __shfl_xor_sync(0xffffffffu, s, o);
    __shared__ float sm[32];
    if ((tid & 31) == 0) sm[tid >> 5] = s;
    __syncthreads();
    if (tid == 0) {
        float t = 0.f;
        #pragma unroll
        for (int i = 0; i < 32; i++) t += sm[i];
        *out = 0.01f * t * (1.f / (float)M_ROWS);
    }
}

// ---------------------------------------------------------------------------
// Launch
// ---------------------------------------------------------------------------
extern "C" void kernel_launch(void* const* d_in, const int* in_sizes, int n_in,
                              void* d_out, int out_size)
{
    const float* x      = (const float*)d_in[0];
    const float* in_w   = (const float*)d_in[1];
    const float* in_b   = (const float*)d_in[2];
    const float* ln_g   = (const float*)d_in[3];
    const float* ln_b   = (const float*)d_in[4];
    const float* blk_ng = (const float*)d_in[5];
    const float* blk_nb = (const float*)d_in[6];
    const float* blk_ipw= (const float*)d_in[7];
    const float* blk_cw = (const float*)d_in[8];
    const float* blk_cb = (const float*)d_in[9];
    const float* blk_xpw= (const float*)d_in[10];
    const float* blk_dtw= (const float*)d_in[11];
    const float* blk_dtb= (const float*)d_in[12];
    const float* blk_Al = (const float*)d_in[13];
    const float* blk_D  = (const float*)d_in[14];
    const float* blk_opw= (const float*)d_in[15];
    const float* op_w   = (const float*)d_in[16];
    const float* op_b   = (const float*)d_in[17];
    const float* cls_w  = (const float*)d_in[18];
    const float* cls_b  = (const float*)d_in[19];
    float* out = (float*)d_out;

    float *h, *hl, *xz, *u, *ut, *dltt, *yt, *y, *xdbc, *h2, *nrm, *part;
    cudaGetSymbolAddress((void**)&h,    g_h);
    cudaGetSymbolAddress((void**)&hl,   g_hl);
    cudaGetSymbolAddress((void**)&xz,   g_xz);
    cudaGetSymbolAddress((void**)&u,    g_u);
    cudaGetSymbolAddress((void**)&ut,   g_ut);
    cudaGetSymbolAddress((void**)&dltt, g_dltt);
    cudaGetSymbolAddress((void**)&yt,   g_yt);
    cudaGetSymbolAddress((void**)&y,    g_y);
    cudaGetSymbolAddress((void**)&xdbc, g_xdbc);
    cudaGetSymbolAddress((void**)&h2,   g_h2);
    cudaGetSymbolAddress((void**)&nrm,  g_norm);
    cudaGetSymbolAddress((void**)&part, g_part);

    dim3 blk256(256);
    dim3 tblk(32, 8);
    dim3 tgrid(SEQ / 32, D_INNER / 32, BATCH);

    // in-proj: split-K=2 -> reduce(+bias) -> h
    gemm128<2,0,0,0><<<dim3(D_MODEL / 128, M_ROWS / 128, 2), blk256>>>(
        x, in_w, nullptr, nullptr, part, M_ROWS, D_MODEL, X_DIM);
    reduce_k<2,1,0,0><<<(M_ROWS * D_MODEL / 4 + 255) / 256, blk256>>>(
        part, in_b, nullptr, h, M_ROWS * D_MODEL, D_MODEL);
    // hs = gelu(layernorm(h))
    ln_kernel<<<M_ROWS, D_MODEL>>>(h, ln_g, ln_b, hl, 1);
    float* hs = hl;
    float* lt = h;

    for (int l = 0; l < N_LAYERS; l++) {
        const float* ng  = blk_ng  + (size_t)l * D_MODEL;
        const float* nb  = blk_nb  + (size_t)l * D_MODEL;
        const float* ipw = blk_ipw + (size_t)l * 2 * D_INNER * D_MODEL;
        const float* cw  = blk_cw  + (size_t)l * D_INNER * D_CONV;
        const float* cb  = blk_cb  + (size_t)l * D_INNER;
        const float* xpw = blk_xpw + (size_t)l * 48 * D_INNER;
        const float* dtw = blk_dtw + (size_t)l * D_INNER * DT_RANK;
        const float* dtb = blk_dtb + (size_t)l * D_INNER;
        const float* Al  = blk_Al  + (size_t)l * D_INNER * D_STATE;
        const float* Dp  = blk_D   + (size_t)l * D_INNER;
        const float* opw = blk_opw + (size_t)l * D_MODEL * D_INNER;

        ln_kernel<<<M_ROWS, D_MODEL>>>(hs, ng, nb, lt, 0);
        // ipw GEMM: N=1024, full grid, direct
        gemm128<1,0,0,0><<<dim3(2 * D_INNER / 128, M_ROWS / 128, 1), blk256>>>(
            lt, ipw, nullptr, nullptr, xz, M_ROWS, 2 * D_INNER, D_MODEL);
        conv2_kernel<<<tgrid, tblk>>>(xz, cw, cb, u, ut);
        // xpw: N=48, split-K=4
        gemm_xpw<<<dim3(1, M_ROWS / 128, 4), blk256>>>(
            u, xpw, part, M_ROWS, 48, D_INNER, 4);
        reduce_k<4,0,0,0><<<(M_ROWS * 48 / 4 + 255) / 256, blk256>>>(
            part, nullptr, nullptr, xdbc, M_ROWS * 48, 48);
        deltaT_kernel<<<tgrid, tblk>>>(xdbc, dtw, dtb, dltt);
        scan_kernel<<<(BATCH * D_INNER) / 8, 128>>>(dltt, ut, xdbc, Al, Dp, yt);
        gate_kernel<<<tgrid, tblk>>>(yt, xz, y);
        // opw: N=256, split-K=2 -> reduce(+residual) -> hs
        gemm128<2,0,0,0><<<dim3(D_MODEL / 128, M_ROWS / 128, 2), blk256>>>(
            y, opw, nullptr, nullptr, part, M_ROWS, D_MODEL, D_INNER);
        reduce_k<2,0,1,0><<<(M_ROWS * D_MODEL / 4 + 255) / 256, blk256>>>(
            part, nullptr, hs, hs, M_ROWS * D_MODEL, D_MODEL);
    }

    // head: h2 = gelu(hs @ op_w^T + op_b), split-K=2
    gemm128<2,0,0,0><<<dim3(D_MODEL / 128, M_ROWS / 128, 2), blk256>>>(
        hs, op_w, nullptr, nullptr, part, M_ROWS, D_MODEL, D_MODEL);
    reduce_k<2,1,0,1><<<(M_ROWS * D_MODEL / 4 + 255) / 256, blk256>>>(
        part, op_b, nullptr, h2, M_ROWS * D_MODEL, D_MODEL);
    // logits = h2 @ cls_w^T + cls_b, split-K=2
    gemm128<2,0,0,0><<<dim3(N_CLS / 128, M_ROWS / 128, 2), blk256>>>(
        h2, cls_w, nullptr, nullptr, part, M_ROWS, N_CLS, D_MODEL);
    reduce_k<2,1,0,0><<<(M_ROWS * N_CLS / 4 + 255) / 256, blk256>>>(
        part, cls_b, nullptr, out, M_ROWS * N_CLS, N_CLS);
    rownorm_kernel<<<M_ROWS, D_MODEL>>>(h2, nrm);
    loss_kernel<<<1, 1024>>>(nrm, out + (out_size - 1));
}

// round 4
// speedup vs baseline: 4.1685x; 1.4732x over previous
#include <cuda_runtime.h>
#include <math.h>

#define BATCH    4
#define SEQ      1024
#define M_ROWS   4096
#define D_MODEL  256
#define D_INNER  512
#define D_STATE  16
#define DT_RANK  16
#define D_CONV   4
#define N_LAYERS 2
#define X_DIM    768
#define N_CLS    128

#define NCHUNK   8
#define CHUNK    128          // SEQ / NCHUNK
#define NGROUP   (BATCH * D_INNER)   // 2048

// ---------------------------------------------------------------------------
// Scratch
// ---------------------------------------------------------------------------
__device__ float g_h   [M_ROWS * D_MODEL];
__device__ float g_hl  [M_ROWS * D_MODEL];
__device__ float g_xz  [M_ROWS * 2 * D_INNER];
__device__ float g_u   [M_ROWS * D_INNER];     // [b][t][d]
__device__ float g_ut  [M_ROWS * D_INNER];     // [b][d][t]
__device__ float g_dltt[M_ROWS * D_INNER];     // [b][d][t]
__device__ float g_yt  [M_ROWS * D_INNER];     // [b][d][t]
__device__ float g_y   [M_ROWS * D_INNER];     // [b][t][d]
__device__ float g_xdbc[M_ROWS * 48];
__device__ float g_h2  [M_ROWS * D_MODEL];
__device__ float g_norm[M_ROWS];
__device__ float g_part[4 * M_ROWS * D_MODEL]; // split-K partials
__device__ float g_scanP[NGROUP * NCHUNK * D_STATE];
__device__ float g_scanQ[NGROUP * NCHUNK * D_STATE];
__device__ float g_scanS[NGROUP * NCHUNK * D_STATE];

__device__ __forceinline__ float gelu_f(float v) {
    return 0.5f * v * (1.f + erff(v * 0.70710678118654752f));
}
__device__ __forceinline__ float silu_f(float v) {
    return v / (1.f + __expf(-v));
}

// ---------------------------------------------------------------------------
// Double-buffered GEMM: C[M,N] = A[M,K] @ W[N,K]^T
// 128x128 tile, BK=8, 256 threads, 8x8 per thread.
// SPLIT>1: blockIdx.z selects K-chunk, writes raw partial to C + z*M*N.
// ---------------------------------------------------------------------------
template<int SPLIT, int ACT, int BIAS, int RES>
__global__ __launch_bounds__(256) void gemm128(
    const float* __restrict__ A, const float* __restrict__ W,
    const float* __restrict__ bias, const float* __restrict__ res,
    float* __restrict__ C, int M, int N, int K)
{
    __shared__ float As[2][8][132];
    __shared__ float Bs[2][8][132];
    const int tid = threadIdx.x;
    const int m0 = blockIdx.y * 128;
    const int n0 = blockIdx.x * 128;
    const int Kc = K / SPLIT;
    const int kbeg = blockIdx.z * Kc;

    const int lr = tid >> 1;
    const int lc = (tid & 1) * 4;
    const float* Aload = A + (size_t)(m0 + lr) * K + kbeg + lc;
    const float* Wload = W + (size_t)(n0 + lr) * K + kbeg + lc;

    const int tm = (tid >> 4) * 4;
    const int tn = (tid & 15) * 4;

    float acc[8][8] = {};

    float4 a_reg = *(const float4*)Aload;
    float4 w_reg = *(const float4*)Wload;
    As[0][lc + 0][lr] = a_reg.x; As[0][lc + 1][lr] = a_reg.y;
    As[0][lc + 2][lr] = a_reg.z; As[0][lc + 3][lr] = a_reg.w;
    Bs[0][lc + 0][lr] = w_reg.x; Bs[0][lc + 1][lr] = w_reg.y;
    Bs[0][lc + 2][lr] = w_reg.z; Bs[0][lc + 3][lr] = w_reg.w;
    __syncthreads();

    const int iters = Kc / 8;
    int buf = 0;
    for (int it = 0; it < iters; it++) {
        if (it + 1 < iters) {
            a_reg = *(const float4*)(Aload + (it + 1) * 8);
            w_reg = *(const float4*)(Wload + (it + 1) * 8);
        }
        #pragma unroll
        for (int kk = 0; kk < 8; kk++) {
            float a[8], b[8];
            *(float4*)&a[0] = *(const float4*)&As[buf][kk][tm];
            *(float4*)&a[4] = *(const float4*)&As[buf][kk][tm + 64];
            *(float4*)&b[0] = *(const float4*)&Bs[buf][kk][tn];
            *(float4*)&b[4] = *(const float4*)&Bs[buf][kk][tn + 64];
            #pragma unroll
            for (int i = 0; i < 8; i++)
                #pragma unroll
                for (int j = 0; j < 8; j++)
                    acc[i][j] = fmaf(a[i], b[j], acc[i][j]);
        }
        if (it + 1 < iters) {
            buf ^= 1;
            As[buf][lc + 0][lr] = a_reg.x; As[buf][lc + 1][lr] = a_reg.y;
            As[buf][lc + 2][lr] = a_reg.z; As[buf][lc + 3][lr] = a_reg.w;
            Bs[buf][lc + 0][lr] = w_reg.x; Bs[buf][lc + 1][lr] = w_reg.y;
            Bs[buf][lc + 2][lr] = w_reg.z; Bs[buf][lc + 3][lr] = w_reg.w;
            __syncthreads();
        }
    }

    float* Cout = (SPLIT > 1) ? (C + (size_t)blockIdx.z * M * N) : C;
    #pragma unroll
    for (int i = 0; i < 8; i++) {
        const int m = m0 + tm + ((i < 4) ? i : (64 + i - 4));
        #pragma unroll
        for (int jh = 0; jh < 2; jh++) {
            const int n = n0 + tn + jh * 64;
            float4 v = {acc[i][jh * 4 + 0], acc[i][jh * 4 + 1],
                        acc[i][jh * 4 + 2], acc[i][jh * 4 + 3]};
            if (SPLIT == 1) {
                if (BIAS) {
                    float4 bv = *(const float4*)(bias + n);
                    v.x += bv.x; v.y += bv.y; v.z += bv.z; v.w += bv.w;
                }
                if (RES) {
                    float4 r4 = *(const float4*)(res + (size_t)m * N + n);
                    v.x += r4.x; v.y += r4.y; v.z += r4.z; v.w += r4.w;
                }
                if (ACT) {
                    v.x = gelu_f(v.x); v.y = gelu_f(v.y);
                    v.z = gelu_f(v.z); v.w = gelu_f(v.w);
                }
            }
            *(float4*)(Cout + (size_t)m * N + n) = v;
        }
    }
}

// ---------------------------------------------------------------------------
// xpw GEMM (N=48): 128x64 tile w/ split-K partials. grid (1, M/128, SPLIT)
// ---------------------------------------------------------------------------
__global__ __launch_bounds__(256) void gemm_xpw(
    const float* __restrict__ A, const float* __restrict__ W,
    float* __restrict__ Cp, int M, int N, int K, int splitK)
{
    __shared__ float As[16][132];
    __shared__ float Ws[16][68];
    const int tid = threadIdx.x;
    const int m0 = blockIdx.y * 128;
    const int Kc = K / splitK;
    const int kbeg = blockIdx.z * Kc;
    const int tm = tid >> 4;
    const int tn = tid & 15;
    const int lr = tid >> 2;
    const int lc = (tid & 3) * 4;

    float acc[8][4] = {};

    for (int k0 = kbeg; k0 < kbeg + Kc; k0 += 16) {
        #pragma unroll
        for (int i = 0; i < 2; i++) {
            int r = lr + i * 64;
            float4 v = *(const float4*)(A + (size_t)(m0 + r) * K + k0 + lc);
            As[lc + 0][r] = v.x; As[lc + 1][r] = v.y;
            As[lc + 2][r] = v.z; As[lc + 3][r] = v.w;
        }
        {
            float4 v = make_float4(0.f, 0.f, 0.f, 0.f);
            if (lr < N)
                v = *(const float4*)(W + (size_t)lr * K + k0 + lc);
            Ws[lc + 0][lr] = v.x; Ws[lc + 1][lr] = v.y;
            Ws[lc + 2][lr] = v.z; Ws[lc + 3][lr] = v.w;
        }
        __syncthreads();
        #pragma unroll
        for (int kk = 0; kk < 16; kk++) {
            float a[8], b[4];
            *(float4*)&a[0] = *(const float4*)&As[kk][tm * 8];
            *(float4*)&a[4] = *(const float4*)&As[kk][tm * 8 + 4];
            *(float4*)&b[0] = *(const float4*)&Ws[kk][tn * 4];
            #pragma unroll
            for (int i = 0; i < 8; i++)
                #pragma unroll
                for (int j = 0; j < 4; j++)
                    acc[i][j] = fmaf(a[i], b[j], acc[i][j]);
        }
        __syncthreads();
    }

    const int n = tn * 4;
    if (n >= N) return;
    float* Cout = Cp + (size_t)blockIdx.z * M * N;
    #pragma unroll
    for (int i = 0; i < 8; i++) {
        int m = m0 + tm * 8 + i;
        float4 v = {acc[i][0], acc[i][1], acc[i][2], acc[i][3]};
        *(float4*)(Cout + (size_t)m * N + n) = v;
    }
}

// ---------------------------------------------------------------------------
// Split-K reduce + fused epilogue
// ---------------------------------------------------------------------------
template<int S, int BIAS, int RES, int ACT>
__global__ void reduce_k(const float* __restrict__ part, const float* __restrict__ bias,
                         const float* __restrict__ res, float* __restrict__ out,
                         int MN, int N)
{
    int i4 = (blockIdx.x * blockDim.x + threadIdx.x) * 4;
    if (i4 >= MN) return;
    float4 v = *(const float4*)(part + i4);
    #pragma unroll
    for (int s = 1; s < S; s++) {
        float4 p = *(const float4*)(part + (size_t)s * MN + i4);
        v.x += p.x; v.y += p.y; v.z += p.z; v.w += p.w;
    }
    if (BIAS) {
        float4 bv = *(const float4*)(bias + (i4 % N));
        v.x += bv.x; v.y += bv.y; v.z += bv.z; v.w += bv.w;
    }
    if (RES) {
        float4 r4 = *(const float4*)(res + i4);
        v.x += r4.x; v.y += r4.y; v.z += r4.z; v.w += r4.w;
    }
    if (ACT) {
        v.x = gelu_f(v.x); v.y = gelu_f(v.y);
        v.z = gelu_f(v.z); v.w = gelu_f(v.w);
    }
    *(float4*)(out + i4) = v;
}

// ---------------------------------------------------------------------------
// Warp-per-row LayerNorm (256 cols), float4, no block sync. Optional gelu.
// ---------------------------------------------------------------------------
__global__ void ln_kernel(const float* __restrict__ x, const float* __restrict__ g,
                          const float* __restrict__ b, float* __restrict__ out, int do_gelu)
{
    const int gi = blockIdx.x * blockDim.x + threadIdx.x;
    const int row = gi >> 5;
    const int lane = gi & 31;
    const float4* xr = (const float4*)(x + (size_t)row * D_MODEL) + lane * 2;
    float4 v0 = xr[0], v1 = xr[1];
    float s1 = v0.x + v0.y + v0.z + v0.w + v1.x + v1.y + v1.z + v1.w;
    float s2 = v0.x*v0.x + v0.y*v0.y + v0.z*v0.z + v0.w*v0.w
             + v1.x*v1.x + v1.y*v1.y + v1.z*v1.z + v1.w*v1.w;
    #pragma unroll
    for (int o = 16; o > 0; o >>= 1) {
        s1 += __shfl_xor_sync(0xffffffffu, s1, o);
        s2 += __shfl_xor_sync(0xffffffffu, s2, o);
    }
    const float mu = s1 * (1.f / 256.f);
    const float rstd = rsqrtf(s2 * (1.f / 256.f) - mu * mu + 1e-5f);
    const float4 g0 = ((const float4*)g)[lane * 2], g1 = ((const float4*)g)[lane * 2 + 1];
    const float4 b0 = ((const float4*)b)[lane * 2], b1 = ((const float4*)b)[lane * 2 + 1];
    float4 o0, o1;
    o0.x = (v0.x - mu) * rstd * g0.x + b0.x;
    o0.y = (v0.y - mu) * rstd * g0.y + b0.y;
    o0.z = (v0.z - mu) * rstd * g0.z + b0.z;
    o0.w = (v0.w - mu) * rstd * g0.w + b0.w;
    o1.x = (v1.x - mu) * rstd * g1.x + b1.x;
    o1.y = (v1.y - mu) * rstd * g1.y + b1.y;
    o1.z = (v1.z - mu) * rstd * g1.z + b1.z;
    o1.w = (v1.w - mu) * rstd * g1.w + b1.w;
    if (do_gelu) {
        o0.x = gelu_f(o0.x); o0.y = gelu_f(o0.y); o0.z = gelu_f(o0.z); o0.w = gelu_f(o0.w);
        o1.x = gelu_f(o1.x); o1.y = gelu_f(o1.y); o1.z = gelu_f(o1.z); o1.w = gelu_f(o1.w);
    }
    float4* orow = (float4*)(out + (size_t)row * D_MODEL) + lane * 2;
    orow[0] = o0; orow[1] = o1;
}

// ---------------------------------------------------------------------------
// Depthwise causal conv (k=4) + SiLU -> u [b][t][d] AND ut [b][d][t]
// ---------------------------------------------------------------------------
__global__ void conv2_kernel(const float* __restrict__ xz, const float* __restrict__ cw,
                             const float* __restrict__ cb, float* __restrict__ u,
                             float* __restrict__ ut)
{
    __shared__ float tile[32][33];
    const int b = blockIdx.z;
    const int t0 = blockIdx.x * 32, d0 = blockIdx.y * 32;
    const int tx = threadIdx.x, ty = threadIdx.y;
    const int d = d0 + tx;
    const float w0 = cw[d * 4 + 0], w1 = cw[d * 4 + 1];
    const float w2 = cw[d * 4 + 2], w3 = cw[d * 4 + 3];
    const float bb = cb[d];
    #pragma unroll
    for (int i = 0; i < 4; i++) {
        const int t = t0 + ty + i * 8;
        const size_t rbase = (size_t)(b * SEQ + t) * (2 * D_INNER) + d;
        float acc = bb;
        if (t >= 3) {
            acc = fmaf(w0, xz[rbase - 3 * 2 * D_INNER], acc);
            acc = fmaf(w1, xz[rbase - 2 * 2 * D_INNER], acc);
            acc = fmaf(w2, xz[rbase - 1 * 2 * D_INNER], acc);
        } else {
            if (t >= 2) acc = fmaf(w1, xz[rbase - 2 * 2 * D_INNER], acc);
            if (t >= 1) acc = fmaf(w2, xz[rbase - 1 * 2 * D_INNER], acc);
        }
        acc = fmaf(w3, xz[rbase], acc);
        acc = silu_f(acc);
        u[(size_t)(b * SEQ + t) * D_INNER + d] = acc;
        tile[ty + i * 8][tx] = acc;
    }
    __syncthreads();
    #pragma unroll
    for (int i = 0; i < 4; i++) {
        const int dd = d0 + ty + i * 8;
        ut[(size_t)(b * D_INNER + dd) * SEQ + t0 + tx] = tile[tx][ty + i * 8];
    }
}

// ---------------------------------------------------------------------------
// delta = softplus(dt @ dtw^T + dtb), written transposed -> dltt [b][d][t]
// ---------------------------------------------------------------------------
__global__ void deltaT_kernel(const float* __restrict__ xdbc, const float* __restrict__ dtw,
                              const float* __restrict__ dtb, float* __restrict__ dltt)
{
    __shared__ float w_s[32][17];
    __shared__ float b_s[32];
    __shared__ float tile[32][33];
    const int b = blockIdx.z;
    const int t0 = blockIdx.x * 32, d0 = blockIdx.y * 32;
    const int tx = threadIdx.x, ty = threadIdx.y;
    const int tid = ty * 32 + tx;
    {
        int r = tid >> 4, c = tid & 15;
        w_s[r][c] = dtw[(d0 + r) * DT_RANK + c];
        w_s[r + 16][c] = dtw[(d0 + r + 16) * DT_RANK + c];
        if (tid < 32) b_s[tid] = dtb[d0 + tid];
    }
    __syncthreads();
    #pragma unroll
    for (int i = 0; i < 4; i++) {
        const int t = t0 + ty + i * 8;
        const float* xr = xdbc + (size_t)(b * SEQ + t) * 48;
        float acc = b_s[tx];
        #pragma unroll
        for (int r = 0; r < DT_RANK; r++)
            acc = fmaf(__ldg(xr + r), w_s[tx][r], acc);
        tile[ty + i * 8][tx] = (acc > 20.f) ? acc : log1pf(__expf(acc));
    }
    __syncthreads();
    #pragma unroll
    for (int i = 0; i < 4; i++) {
        const int dd = d0 + ty + i * 8;
        dltt[(size_t)(b * D_INNER + dd) * SEQ + t0 + tx] = tile[tx][ty + i * 8];
    }
}

// ---------------------------------------------------------------------------
// Chunked selective scan
// Pass 1: per (group, chunk<7): local end-state Q and decay product P.
// ---------------------------------------------------------------------------
__global__ __launch_bounds__(256) void scan_pass1(
    const float* __restrict__ dltt, const float* __restrict__ ut,
    const float* __restrict__ xdbc, const float* __restrict__ A_log,
    float* __restrict__ Pc, float* __restrict__ Qc)
{
    const int tid = threadIdx.x;
    const int gidx = blockIdx.x * 16 + (tid >> 4);   // 0 .. 2048*7-1
    if (gidx >= NGROUP * (NCHUNK - 1)) return;
    const int n = tid & 15;
    const int g = gidx / (NCHUNK - 1);
    const int c = gidx - g * (NCHUNK - 1);
    const int b = g >> 9;
    const int d = g & (D_INNER - 1);
    const float A = -__expf(A_log[d * D_STATE + n]);
    const size_t base = (size_t)g * SEQ + c * CHUNK;
    const float* xb = xdbc + ((size_t)b * SEQ + c * CHUNK) * 48 + DT_RANK;
    float s = 0.f, sumd = 0.f;
    for (int tc = 0; tc < CHUNK; tc += 16) {
        float dt[16], uu[16];
        #pragma unroll
        for (int q = 0; q < 4; q++) {
            float4 v = ((const float4*)(dltt + base + tc))[q];
            dt[q*4+0] = v.x; dt[q*4+1] = v.y; dt[q*4+2] = v.z; dt[q*4+3] = v.w;
            float4 w = ((const float4*)(ut + base + tc))[q];
            uu[q*4+0] = w.x; uu[q*4+1] = w.y; uu[q*4+2] = w.z; uu[q*4+3] = w.w;
        }
        #pragma unroll
        for (int j = 0; j < 16; j++) {
            const float Bn = __ldg(xb + (size_t)(tc + j) * 48 + n);
            s = fmaf(s, __expf(dt[j] * A), dt[j] * uu[j] * Bn);
            sumd += dt[j];
        }
    }
    const int idx = (g * NCHUNK + c) * D_STATE + n;
    Qc[idx] = s;
    Pc[idx] = __expf(A * sumd);
}

// Pass 2: sequential combine over chunks -> start state per chunk
__global__ void scan_pass2(const float* __restrict__ Pc, const float* __restrict__ Qc,
                           float* __restrict__ Sc)
{
    const int gi = blockIdx.x * blockDim.x + threadIdx.x;  // 0..32767
    const int g = gi >> 4;
    const int n = gi & 15;
    float s = 0.f;
    #pragma unroll
    for (int c = 0; c < NCHUNK; c++) {
        const int idx = (g * NCHUNK + c) * D_STATE + n;
        Sc[idx] = s;
        if (c < NCHUNK - 1) s = fmaf(Pc[idx], s, Qc[idx]);
    }
}

// Pass 3: full scan per chunk with known start state, writes yt
__global__ __launch_bounds__(256) void scan_pass3(
    const float* __restrict__ dltt, const float* __restrict__ ut,
    const float* __restrict__ xdbc, const float* __restrict__ A_log,
    const float* __restrict__ Dp, const float* __restrict__ Sc,
    float* __restrict__ yt)
{
    const int tid = threadIdx.x;
    const int gidx = blockIdx.x * 16 + (tid >> 4);   // 0 .. 2048*8-1
    const int n = tid & 15;
    const int g = gidx >> 3;
    const int c = gidx & 7;
    const int b = g >> 9;
    const int d = g & (D_INNER - 1);
    const float A = -__expf(A_log[d * D_STATE + n]);
    const float Dd = Dp[d];
    const size_t base = (size_t)g * SEQ + c * CHUNK;
    const float* xb = xdbc + ((size_t)b * SEQ + c * CHUNK) * 48 + DT_RANK;
    float s = Sc[(g * NCHUNK + c) * D_STATE + n];
    for (int tc = 0; tc < CHUNK; tc += 16) {
        float dt[16], uu[16];
        #pragma unroll
        for (int q = 0; q < 4; q++) {
            float4 v = ((const float4*)(dltt + base + tc))[q];
            dt[q*4+0] = v.x; dt[q*4+1] = v.y; dt[q*4+2] = v.z; dt[q*4+3] = v.w;
            float4 w = ((const float4*)(ut + base + tc))[q];
            uu[q*4+0] = w.x; uu[q*4+1] = w.y; uu[q*4+2] = w.z; uu[q*4+3] = w.w;
        }
        float rv = 0.f;
        #pragma unroll
        for (int j = 0; j < 16; j++) {
            const float* xr = xb + (size_t)(tc + j) * 48;
            const float Bn = __ldg(xr + n);
            const float Cn = __ldg(xr + D_STATE + n);
            s = fmaf(s, __expf(dt[j] * A), dt[j] * uu[j] * Bn);
            float v = s * Cn;
            #pragma unroll
            for (int o = 8; o > 0; o >>= 1) v += __shfl_xor_sync(0xffffffffu, v, o);
            if (n == j) rv = v + uu[j] * Dd;
        }
        yt[base + tc + n] = rv;
    }
}

// ---------------------------------------------------------------------------
// Gate + transpose back: y[b][t][d] = yt[b][d][t] * silu(z[b][t][d])
// ---------------------------------------------------------------------------
__global__ void gate_kernel(const float* __restrict__ yt, const float* __restrict__ xz,
                            float* __restrict__ y)
{
    __shared__ float t0s[32][33];
    const int b = blockIdx.z;
    const int tblk = blockIdx.x * 32, dblk = blockIdx.y * 32;
    const int tx = threadIdx.x, ty = threadIdx.y;
    #pragma unroll
    for (int i = 0; i < 4; i++) {
        int d = dblk + ty + i * 8;
        t0s[ty + i * 8][tx] = yt[(size_t)(b * D_INNER + d) * SEQ + tblk + tx];
    }
    __syncthreads();
    #pragma unroll
    for (int i = 0; i < 4; i++) {
        int t = tblk + ty + i * 8;
        size_t row = (size_t)(b * SEQ + t);
        float z = xz[row * (2 * D_INNER) + D_INNER + dblk + tx];
        y[row * D_INNER + dblk + tx] = t0s[tx][ty + i * 8] * silu_f(z);
    }
}

// ---------------------------------------------------------------------------
// Row L2 norms + loss
// ---------------------------------------------------------------------------
__global__ void rownorm_kernel(const float* __restrict__ h, float* __restrict__ nrm)
{
    const int gi = blockIdx.x * blockDim.x + threadIdx.x;
    const int row = gi >> 5;
    const int lane = gi & 31;
    const float4* xr = (const float4*)(h + (size_t)row * D_MODEL) + lane * 2;
    float4 v0 = xr[0], v1 = xr[1];
    float s = v0.x*v0.x + v0.y*v0.y + v0.z*v0.z + v0.w*v0.w
            + v1.x*v1.x + v1.y*v1.y + v1.z*v1.z + v1.w*v1.w;
    #pragma unroll
    for (int o = 16; o > 0; o >>= 1) s += __shfl_xor_sync(0xffffffffu, s, o);
    if (lane == 0) nrm[row] = sqrtf(s);
}

__global__ void loss_kernel(const float* __restrict__ nrm, float* __restrict__ out)
{
    const int tid = threadIdx.x; // 1024
    float s = 0.f;
    #pragma unroll
    for (int i = 0; i < 4; i++) s += nrm[tid + i * 1024];
    #pragma unroll
    for (int o = 16; o > 0; o >>= 1) s += __shfl_xor_sync(0xffffffffu, s, o);
    __shared__ float sm[32];
    if ((tid & 31) == 0) sm[tid >> 5] = s;
    __syncthreads();
    if (tid == 0) {
        float t = 0.f;
        #pragma unroll
        for (int i = 0; i < 32; i++) t += sm[i];
        *out = 0.01f * t * (1.f / (float)M_ROWS);
    }
}

// ---------------------------------------------------------------------------
// Launch
// ---------------------------------------------------------------------------
extern "C" void kernel_launch(void* const* d_in, const int* in_sizes, int n_in,
                              void* d_out, int out_size)
{
    const float* x      = (const float*)d_in[0];
    const float* in_w   = (const float*)d_in[1];
    const float* in_b   = (const float*)d_in[2];
    const float* ln_g   = (const float*)d_in[3];
    const float* ln_b   = (const float*)d_in[4];
    const float* blk_ng = (const float*)d_in[5];
    const float* blk_nb = (const float*)d_in[6];
    const float* blk_ipw= (const float*)d_in[7];
    const float* blk_cw = (const float*)d_in[8];
    const float* blk_cb = (const float*)d_in[9];
    const float* blk_xpw= (const float*)d_in[10];
    const float* blk_dtw= (const float*)d_in[11];
    const float* blk_dtb= (const float*)d_in[12];
    const float* blk_Al = (const float*)d_in[13];
    const float* blk_D  = (const float*)d_in[14];
    const float* blk_opw= (const float*)d_in[15];
    const float* op_w   = (const float*)d_in[16];
    const float* op_b   = (const float*)d_in[17];
    const float* cls_w  = (const float*)d_in[18];
    const float* cls_b  = (const float*)d_in[19];
    float* out = (float*)d_out;

    float *h, *hl, *xz, *u, *ut, *dltt, *yt, *y, *xdbc, *h2, *nrm, *part;
    float *scP, *scQ, *scS;
    cudaGetSymbolAddress((void**)&h,    g_h);
    cudaGetSymbolAddress((void**)&hl,   g_hl);
    cudaGetSymbolAddress((void**)&xz,   g_xz);
    cudaGetSymbolAddress((void**)&u,    g_u);
    cudaGetSymbolAddress((void**)&ut,   g_ut);
    cudaGetSymbolAddress((void**)&dltt, g_dltt);
    cudaGetSymbolAddress((void**)&yt,   g_yt);
    cudaGetSymbolAddress((void**)&y,    g_y);
    cudaGetSymbolAddress((void**)&xdbc, g_xdbc);
    cudaGetSymbolAddress((void**)&h2,   g_h2);
    cudaGetSymbolAddress((void**)&nrm,  g_norm);
    cudaGetSymbolAddress((void**)&part, g_part);
    cudaGetSymbolAddress((void**)&scP,  g_scanP);
    cudaGetSymbolAddress((void**)&scQ,  g_scanQ);
    cudaGetSymbolAddress((void**)&scS,  g_scanS);

    dim3 blk256(256);
    dim3 tblk(32, 8);
    dim3 tgrid(SEQ / 32, D_INNER / 32, BATCH);
    const int LN_BLOCKS = M_ROWS * 32 / 256;   // warp per row

    // in-proj: split-K=4 -> reduce(+bias) -> h
    gemm128<4,0,0,0><<<dim3(D_MODEL / 128, M_ROWS / 128, 4), blk256>>>(
        x, in_w, nullptr, nullptr, part, M_ROWS, D_MODEL, X_DIM);
    reduce_k<4,1,0,0><<<(M_ROWS * D_MODEL / 4 + 255) / 256, blk256>>>(
        part, in_b, nullptr, h, M_ROWS * D_MODEL, D_MODEL);
    ln_kernel<<<LN_BLOCKS, blk256>>>(h, ln_g, ln_b, hl, 1);
    float* hs = hl;
    float* lt = h;

    for (int l = 0; l < N_LAYERS; l++) {
        const float* ng  = blk_ng  + (size_t)l * D_MODEL;
        const float* nb  = blk_nb  + (size_t)l * D_MODEL;
        const float* ipw = blk_ipw + (size_t)l * 2 * D_INNER * D_MODEL;
        const float* cw  = blk_cw  + (size_t)l * D_INNER * D_CONV;
        const float* cb  = blk_cb  + (size_t)l * D_INNER;
        const float* xpw = blk_xpw + (size_t)l * 48 * D_INNER;
        const float* dtw = blk_dtw + (size_t)l * D_INNER * DT_RANK;
        const float* dtb = blk_dtb + (size_t)l * D_INNER;
        const float* Al  = blk_Al  + (size_t)l * D_INNER * D_STATE;
        const float* Dp  = blk_D   + (size_t)l * D_INNER;
        const float* opw = blk_opw + (size_t)l * D_MODEL * D_INNER;

        ln_kernel<<<LN_BLOCKS, blk256>>>(hs, ng, nb, lt, 0);
        gemm128<1,0,0,0><<<dim3(2 * D_INNER / 128, M_ROWS / 128, 1), blk256>>>(
            lt, ipw, nullptr, nullptr, xz, M_ROWS, 2 * D_INNER, D_MODEL);
        conv2_kernel<<<tgrid, tblk>>>(xz, cw, cb, u, ut);
        gemm_xpw<<<dim3(1, M_ROWS / 128, 4), blk256>>>(
            u, xpw, part, M_ROWS, 48, D_INNER, 4);
        reduce_k<4,0,0,0><<<(M_ROWS * 48 / 4 + 255) / 256, blk256>>>(
            part, nullptr, nullptr, xdbc, M_ROWS * 48, 48);
        deltaT_kernel<<<tgrid, tblk>>>(xdbc, dtw, dtb, dltt);
        // chunked scan
        scan_pass1<<<(NGROUP * (NCHUNK - 1) + 15) / 16, blk256>>>(
            dltt, ut, xdbc, Al, scP, scQ);
        scan_pass2<<<(NGROUP * D_STATE) / 256, blk256>>>(scP, scQ, scS);
        scan_pass3<<<(NGROUP * NCHUNK) / 16, blk256>>>(
            dltt, ut, xdbc, Al, Dp, scS, yt);
        gate_kernel<<<tgrid, tblk>>>(yt, xz, y);
        gemm128<4,0,0,0><<<dim3(D_MODEL / 128, M_ROWS / 128, 4), blk256>>>(
            y, opw, nullptr, nullptr, part, M_ROWS, D_MODEL, D_INNER);
        reduce_k<4,0,1,0><<<(M_ROWS * D_MODEL / 4 + 255) / 256, blk256>>>(
            part, nullptr, hs, hs, M_ROWS * D_MODEL, D_MODEL);
    }

    gemm128<4,0,0,0><<<dim3(D_MODEL / 128, M_ROWS / 128, 4), blk256>>>(
        hs, op_w, nullptr, nullptr, part, M_ROWS, D_MODEL, D_MODEL);
    reduce_k<4,1,0,1><<<(M_ROWS * D_MODEL / 4 + 255) / 256, blk256>>>(
        part, op_b, nullptr, h2, M_ROWS * D_MODEL, D_MODEL);
    gemm128<4,0,0,0><<<dim3(N_CLS / 128, M_ROWS / 128, 4), blk256>>>(
        h2, cls_w, nullptr, nullptr, part, M_ROWS, N_CLS, D_MODEL);
    reduce_k<4,1,0,0><<<(M_ROWS * N_CLS / 4 + 255) / 256, blk256>>>(
        part, cls_b, nullptr, out, M_ROWS * N_CLS, N_CLS);
    rownorm_kernel<<<M_ROWS * 32 / 256, blk256>>>(h2, nrm);
    loss_kernel<<<1, 1024>>>(nrm, out + (out_size - 1));
}

// round 5
// speedup vs baseline: 4.1741x; 1.0013x over previous
#include <cuda_runtime.h>
#include <math.h>

#define BATCH    4
#define SEQ      1024
#define M_ROWS   4096
#define D_MODEL  256
#define D_INNER  512
#define D_STATE  16
#define DT_RANK  16
#define D_CONV   4
#define N_LAYERS 2
#define X_DIM    768
#define N_CLS    128

#define NCHUNK   16
#define CHUNK    64           // SEQ / NCHUNK
#define NGROUP   (BATCH * D_INNER)   // 2048

// ---------------------------------------------------------------------------
// Scratch
// ---------------------------------------------------------------------------
__device__ float g_hl  [M_ROWS * D_MODEL];     // residual stream hs
__device__ float g_lt  [M_ROWS * D_MODEL];     // per-layer LN output
__device__ float g_xz  [M_ROWS * 2 * D_INNER];
__device__ float g_u   [M_ROWS * D_INNER];     // [b][t][d]
__device__ float g_ut  [M_ROWS * D_INNER];     // [b][d][t]
__device__ float g_dltt[M_ROWS * D_INNER];     // [b][d][t]
__device__ float g_yt  [M_ROWS * D_INNER];     // [b][d][t]
__device__ float g_y   [M_ROWS * D_INNER];     // [b][t][d]
__device__ float g_xdbc[M_ROWS * 48];
__device__ float g_h2  [M_ROWS * D_MODEL];
__device__ float g_norm[M_ROWS];
__device__ float g_part[4 * M_ROWS * D_MODEL]; // split-K partials

__device__ __forceinline__ float gelu_f(float v) {
    return 0.5f * v * (1.f + erff(v * 0.70710678118654752f));
}
__device__ __forceinline__ float silu_f(float v) {
    return v / (1.f + __expf(-v));
}

// ---------------------------------------------------------------------------
// Double-buffered GEMM, BK=16: C[M,N] = A[M,K] @ W[N,K]^T
// 128x128 tile, 256 threads, 8x8 per thread.
// SPLIT>1: blockIdx.z selects K-chunk, writes raw partial to C + z*M*N.
// Requires M%128==0, N%128==0, (K/SPLIT)%16==0.
// ---------------------------------------------------------------------------
template<int SPLIT>
__global__ __launch_bounds__(256) void gemm16(
    const float* __restrict__ A, const float* __restrict__ W,
    float* __restrict__ C, int M, int N, int K)
{
    __shared__ float As[2][16][132];
    __shared__ float Bs[2][16][132];
    const int tid = threadIdx.x;
    const int m0 = blockIdx.y * 128;
    const int n0 = blockIdx.x * 128;
    const int Kc = K / SPLIT;
    const int kbeg = blockIdx.z * Kc;

    const int lr = tid >> 1;            // 0..127
    const int lc8 = (tid & 1) * 8;      // 0 or 8
    const float* Aload = A + (size_t)(m0 + lr) * K + kbeg + lc8;
    const float* Wload = W + (size_t)(n0 + lr) * K + kbeg + lc8;

    const int tm = (tid >> 4) * 4;
    const int tn = (tid & 15) * 4;

    float acc[8][8] = {};

    float4 a0 = *(const float4*)Aload;
    float4 a1 = *(const float4*)(Aload + 4);
    float4 w0 = *(const float4*)Wload;
    float4 w1 = *(const float4*)(Wload + 4);
    As[0][lc8 + 0][lr] = a0.x; As[0][lc8 + 1][lr] = a0.y;
    As[0][lc8 + 2][lr] = a0.z; As[0][lc8 + 3][lr] = a0.w;
    As[0][lc8 + 4][lr] = a1.x; As[0][lc8 + 5][lr] = a1.y;
    As[0][lc8 + 6][lr] = a1.z; As[0][lc8 + 7][lr] = a1.w;
    Bs[0][lc8 + 0][lr] = w0.x; Bs[0][lc8 + 1][lr] = w0.y;
    Bs[0][lc8 + 2][lr] = w0.z; Bs[0][lc8 + 3][lr] = w0.w;
    Bs[0][lc8 + 4][lr] = w1.x; Bs[0][lc8 + 5][lr] = w1.y;
    Bs[0][lc8 + 6][lr] = w1.z; Bs[0][lc8 + 7][lr] = w1.w;
    __syncthreads();

    const int iters = Kc / 16;
    int buf = 0;
    for (int it = 0; it < iters; it++) {
        if (it + 1 < iters) {
            a0 = *(const float4*)(Aload + (it + 1) * 16);
            a1 = *(const float4*)(Aload + (it + 1) * 16 + 4);
            w0 = *(const float4*)(Wload + (it + 1) * 16);
            w1 = *(const float4*)(Wload + (it + 1) * 16 + 4);
        }
        #pragma unroll
        for (int kk = 0; kk < 16; kk++) {
            float a[8], b[8];
            *(float4*)&a[0] = *(const float4*)&As[buf][kk][tm];
            *(float4*)&a[4] = *(const float4*)&As[buf][kk][tm + 64];
            *(float4*)&b[0] = *(const float4*)&Bs[buf][kk][tn];
            *(float4*)&b[4] = *(const float4*)&Bs[buf][kk][tn + 64];
            #pragma unroll
            for (int i = 0; i < 8; i++)
                #pragma unroll
                for (int j = 0; j < 8; j++)
                    acc[i][j] = fmaf(a[i], b[j], acc[i][j]);
        }
        if (it + 1 < iters) {
            buf ^= 1;
            As[buf][lc8 + 0][lr] = a0.x; As[buf][lc8 + 1][lr] = a0.y;
            As[buf][lc8 + 2][lr] = a0.z; As[buf][lc8 + 3][lr] = a0.w;
            As[buf][lc8 + 4][lr] = a1.x; As[buf][lc8 + 5][lr] = a1.y;
            As[buf][lc8 + 6][lr] = a1.z; As[buf][lc8 + 7][lr] = a1.w;
            Bs[buf][lc8 + 0][lr] = w0.x; Bs[buf][lc8 + 1][lr] = w0.y;
            Bs[buf][lc8 + 2][lr] = w0.z; Bs[buf][lc8 + 3][lr] = w0.w;
            Bs[buf][lc8 + 4][lr] = w1.x; Bs[buf][lc8 + 5][lr] = w1.y;
            Bs[buf][lc8 + 6][lr] = w1.z; Bs[buf][lc8 + 7][lr] = w1.w;
            __syncthreads();
        }
    }

    float* Cout = (SPLIT > 1) ? (C + (size_t)blockIdx.z * M * N) : C;
    #pragma unroll
    for (int i = 0; i < 8; i++) {
        const int m = m0 + tm + ((i < 4) ? i : (64 + i - 4));
        #pragma unroll
        for (int jh = 0; jh < 2; jh++) {
            const int n = n0 + tn + jh * 64;
            float4 v = {acc[i][jh * 4 + 0], acc[i][jh * 4 + 1],
                        acc[i][jh * 4 + 2], acc[i][jh * 4 + 3]};
            *(float4*)(Cout + (size_t)m * N + n) = v;
        }
    }
}

// ---------------------------------------------------------------------------
// xpw GEMM (N=48): 128x64 tile w/ split-K partials. grid (1, M/128, SPLIT)
// ---------------------------------------------------------------------------
__global__ __launch_bounds__(256) void gemm_xpw(
    const float* __restrict__ A, const float* __restrict__ W,
    float* __restrict__ Cp, int M, int N, int K, int splitK)
{
    __shared__ float As[16][132];
    __shared__ float Ws[16][68];
    const int tid = threadIdx.x;
    const int m0 = blockIdx.y * 128;
    const int Kc = K / splitK;
    const int kbeg = blockIdx.z * Kc;
    const int tm = tid >> 4;
    const int tn = tid & 15;
    const int lr = tid >> 2;
    const int lc = (tid & 3) * 4;

    float acc[8][4] = {};

    for (int k0 = kbeg; k0 < kbeg + Kc; k0 += 16) {
        #pragma unroll
        for (int i = 0; i < 2; i++) {
            int r = lr + i * 64;
            float4 v = *(const float4*)(A + (size_t)(m0 + r) * K + k0 + lc);
            As[lc + 0][r] = v.x; As[lc + 1][r] = v.y;
            As[lc + 2][r] = v.z; As[lc + 3][r] = v.w;
        }
        {
            float4 v = make_float4(0.f, 0.f, 0.f, 0.f);
            if (lr < N)
                v = *(const float4*)(W + (size_t)lr * K + k0 + lc);
            Ws[lc + 0][lr] = v.x; Ws[lc + 1][lr] = v.y;
            Ws[lc + 2][lr] = v.z; Ws[lc + 3][lr] = v.w;
        }
        __syncthreads();
        #pragma unroll
        for (int kk = 0; kk < 16; kk++) {
            float a[8], b[4];
            *(float4*)&a[0] = *(const float4*)&As[kk][tm * 8];
            *(float4*)&a[4] = *(const float4*)&As[kk][tm * 8 + 4];
            *(float4*)&b[0] = *(const float4*)&Ws[kk][tn * 4];
            #pragma unroll
            for (int i = 0; i < 8; i++)
                #pragma unroll
                for (int j = 0; j < 4; j++)
                    acc[i][j] = fmaf(a[i], b[j], acc[i][j]);
        }
        __syncthreads();
    }

    const int n = tn * 4;
    if (n >= N) return;
    float* Cout = Cp + (size_t)blockIdx.z * M * N;
    #pragma unroll
    for (int i = 0; i < 8; i++) {
        int m = m0 + tm * 8 + i;
        float4 v = {acc[i][0], acc[i][1], acc[i][2], acc[i][3]};
        *(float4*)(Cout + (size_t)m * N + n) = v;
    }
}

// ---------------------------------------------------------------------------
// Generic split-K reduce (xdbc, cls)
// ---------------------------------------------------------------------------
template<int S, int BIAS>
__global__ void reduce_k(const float* __restrict__ part, const float* __restrict__ bias,
                         float* __restrict__ out, int MN, int N)
{
    int i4 = (blockIdx.x * blockDim.x + threadIdx.x) * 4;
    if (i4 >= MN) return;
    float4 v = *(const float4*)(part + i4);
    #pragma unroll
    for (int s = 1; s < S; s++) {
        float4 p = *(const float4*)(part + (size_t)s * MN + i4);
        v.x += p.x; v.y += p.y; v.z += p.z; v.w += p.w;
    }
    if (BIAS) {
        float4 bv = *(const float4*)(bias + (i4 % N));
        v.x += bv.x; v.y += bv.y; v.z += bv.z; v.w += bv.w;
    }
    *(float4*)(out + i4) = v;
}

// ---------------------------------------------------------------------------
// Warp-per-row helpers: each lane holds 8 cols of a 256-col row:
// cols [lane*4 .. lane*4+3] and [128+lane*4 .. 128+lane*4+3].
// ---------------------------------------------------------------------------
__device__ __forceinline__ void warp_stats(const float4& v0, const float4& v1,
                                           float& mu, float& rstd)
{
    float s1 = v0.x + v0.y + v0.z + v0.w + v1.x + v1.y + v1.z + v1.w;
    float s2 = v0.x*v0.x + v0.y*v0.y + v0.z*v0.z + v0.w*v0.w
             + v1.x*v1.x + v1.y*v1.y + v1.z*v1.z + v1.w*v1.w;
    #pragma unroll
    for (int o = 16; o > 0; o >>= 1) {
        s1 += __shfl_xor_sync(0xffffffffu, s1, o);
        s2 += __shfl_xor_sync(0xffffffffu, s2, o);
    }
    mu = s1 * (1.f / 256.f);
    rstd = rsqrtf(s2 * (1.f / 256.f) - mu * mu + 1e-5f);
}

__device__ __forceinline__ float4 ln_apply4(const float4& v, float mu, float rstd,
                                            const float4& g, const float4& b)
{
    float4 o;
    o.x = (v.x - mu) * rstd * g.x + b.x;
    o.y = (v.y - mu) * rstd * g.y + b.y;
    o.z = (v.z - mu) * rstd * g.z + b.z;
    o.w = (v.w - mu) * rstd * g.w + b.w;
    return o;
}
__device__ __forceinline__ float4 gelu4(float4 v) {
    v.x = gelu_f(v.x); v.y = gelu_f(v.y); v.z = gelu_f(v.z); v.w = gelu_f(v.w);
    return v;
}

// ---------------------------------------------------------------------------
// in-proj epilogue: reduce 4 partials + bias -> LN(ln_g)+gelu -> hs
//                   -> LN(blk_ng[0]) -> lt
// ---------------------------------------------------------------------------
__global__ void ep_inproj(const float* __restrict__ part, const float* __restrict__ bias,
                          const float* __restrict__ lng, const float* __restrict__ lnb,
                          const float* __restrict__ ng0, const float* __restrict__ nb0,
                          float* __restrict__ hs, float* __restrict__ lt)
{
    const int gi = blockIdx.x * blockDim.x + threadIdx.x;
    const int row = gi >> 5;
    const int lane = gi & 31;
    const int MN = M_ROWS * D_MODEL;
    const int c0 = lane * 4, c1 = 128 + lane * 4;
    const size_t i0 = (size_t)row * D_MODEL + c0;
    const size_t i1 = (size_t)row * D_MODEL + c1;
    float4 v0 = make_float4(0,0,0,0), v1 = make_float4(0,0,0,0);
    #pragma unroll
    for (int s = 0; s < 4; s++) {
        float4 p0 = *(const float4*)(part + (size_t)s * MN + i0);
        float4 p1 = *(const float4*)(part + (size_t)s * MN + i1);
        v0.x += p0.x; v0.y += p0.y; v0.z += p0.z; v0.w += p0.w;
        v1.x += p1.x; v1.y += p1.y; v1.z += p1.z; v1.w += p1.w;
    }
    float4 b0 = *(const float4*)(bias + c0), b1 = *(const float4*)(bias + c1);
    v0.x += b0.x; v0.y += b0.y; v0.z += b0.z; v0.w += b0.w;
    v1.x += b1.x; v1.y += b1.y; v1.z += b1.z; v1.w += b1.w;
    float mu, rstd;
    warp_stats(v0, v1, mu, rstd);
    float4 g0 = *(const float4*)(lng + c0), g1 = *(const float4*)(lng + c1);
    float4 bb0 = *(const float4*)(lnb + c0), bb1 = *(const float4*)(lnb + c1);
    float4 w0 = gelu4(ln_apply4(v0, mu, rstd, g0, bb0));
    float4 w1 = gelu4(ln_apply4(v1, mu, rstd, g1, bb1));
    *(float4*)(hs + i0) = w0;
    *(float4*)(hs + i1) = w1;
    // second LN (layer 0 input)
    warp_stats(w0, w1, mu, rstd);
    g0 = *(const float4*)(ng0 + c0); g1 = *(const float4*)(ng0 + c1);
    bb0 = *(const float4*)(nb0 + c0); bb1 = *(const float4*)(nb0 + c1);
    *(float4*)(lt + i0) = ln_apply4(w0, mu, rstd, g0, bb0);
    *(float4*)(lt + i1) = ln_apply4(w1, mu, rstd, g1, bb1);
}

// ---------------------------------------------------------------------------
// opw epilogue: hs += reduce4(part); optional LN(ng,nb) -> lt
// ---------------------------------------------------------------------------
template<int LN>
__global__ void ep_opw(const float* __restrict__ part, const float* __restrict__ ng,
                       const float* __restrict__ nb, float* __restrict__ hs,
                       float* __restrict__ lt)
{
    const int gi = blockIdx.x * blockDim.x + threadIdx.x;
    const int row = gi >> 5;
    const int lane = gi & 31;
    const int MN = M_ROWS * D_MODEL;
    const int c0 = lane * 4, c1 = 128 + lane * 4;
    const size_t i0 = (size_t)row * D_MODEL + c0;
    const size_t i1 = (size_t)row * D_MODEL + c1;
    float4 v0 = *(const float4*)(hs + i0);
    float4 v1 = *(const float4*)(hs + i1);
    #pragma unroll
    for (int s = 0; s < 4; s++) {
        float4 p0 = *(const float4*)(part + (size_t)s * MN + i0);
        float4 p1 = *(const float4*)(part + (size_t)s * MN + i1);
        v0.x += p0.x; v0.y += p0.y; v0.z += p0.z; v0.w += p0.w;
        v1.x += p1.x; v1.y += p1.y; v1.z += p1.z; v1.w += p1.w;
    }
    *(float4*)(hs + i0) = v0;
    *(float4*)(hs + i1) = v1;
    if (LN) {
        float mu, rstd;
        warp_stats(v0, v1, mu, rstd);
        float4 g0 = *(const float4*)(ng + c0), g1 = *(const float4*)(ng + c1);
        float4 b0 = *(const float4*)(nb + c0), b1 = *(const float4*)(nb + c1);
        *(float4*)(lt + i0) = ln_apply4(v0, mu, rstd, g0, b0);
        *(float4*)(lt + i1) = ln_apply4(v1, mu, rstd, g1, b1);
    }
}

// ---------------------------------------------------------------------------
// head epilogue: h2 = gelu(reduce4 + bias); nrm[row] = ||h2 row||
// ---------------------------------------------------------------------------
__global__ void ep_head(const float* __restrict__ part, const float* __restrict__ bias,
                        float* __restrict__ h2, float* __restrict__ nrm)
{
    const int gi = blockIdx.x * blockDim.x + threadIdx.x;
    const int row = gi >> 5;
    const int lane = gi & 31;
    const int MN = M_ROWS * D_MODEL;
    const int c0 = lane * 4, c1 = 128 + lane * 4;
    const size_t i0 = (size_t)row * D_MODEL + c0;
    const size_t i1 = (size_t)row * D_MODEL + c1;
    float4 v0 = make_float4(0,0,0,0), v1 = make_float4(0,0,0,0);
    #pragma unroll
    for (int s = 0; s < 4; s++) {
        float4 p0 = *(const float4*)(part + (size_t)s * MN + i0);
        float4 p1 = *(const float4*)(part + (size_t)s * MN + i1);
        v0.x += p0.x; v0.y += p0.y; v0.z += p0.z; v0.w += p0.w;
        v1.x += p1.x; v1.y += p1.y; v1.z += p1.z; v1.w += p1.w;
    }
    float4 b0 = *(const float4*)(bias + c0), b1 = *(const float4*)(bias + c1);
    v0.x += b0.x; v0.y += b0.y; v0.z += b0.z; v0.w += b0.w;
    v1.x += b1.x; v1.y += b1.y; v1.z += b1.z; v1.w += b1.w;
    v0 = gelu4(v0); v1 = gelu4(v1);
    *(float4*)(h2 + i0) = v0;
    *(float4*)(h2 + i1) = v1;
    float s = v0.x*v0.x + v0.y*v0.y + v0.z*v0.z + v0.w*v0.w
            + v1.x*v1.x + v1.y*v1.y + v1.z*v1.z + v1.w*v1.w;
    #pragma unroll
    for (int o = 16; o > 0; o >>= 1) s += __shfl_xor_sync(0xffffffffu, s, o);
    if (lane == 0) nrm[row] = sqrtf(s);
}

// ---------------------------------------------------------------------------
// Depthwise causal conv (k=4) + SiLU -> u [b][t][d] AND ut [b][d][t]
// ---------------------------------------------------------------------------
__global__ void conv2_kernel(const float* __restrict__ xz, const float* __restrict__ cw,
                             const float* __restrict__ cb, float* __restrict__ u,
                             float* __restrict__ ut)
{
    __shared__ float tile[32][33];
    const int b = blockIdx.z;
    const int t0 = blockIdx.x * 32, d0 = blockIdx.y * 32;
    const int tx = threadIdx.x, ty = threadIdx.y;
    const int d = d0 + tx;
    const float w0 = cw[d * 4 + 0], w1 = cw[d * 4 + 1];
    const float w2 = cw[d * 4 + 2], w3 = cw[d * 4 + 3];
    const float bb = cb[d];
    #pragma unroll
    for (int i = 0; i < 4; i++) {
        const int t = t0 + ty + i * 8;
        const size_t rbase = (size_t)(b * SEQ + t) * (2 * D_INNER) + d;
        float acc = bb;
        if (t >= 3) {
            acc = fmaf(w0, xz[rbase - 3 * 2 * D_INNER], acc);
            acc = fmaf(w1, xz[rbase - 2 * 2 * D_INNER], acc);
            acc = fmaf(w2, xz[rbase - 1 * 2 * D_INNER], acc);
        } else {
            if (t >= 2) acc = fmaf(w1, xz[rbase - 2 * 2 * D_INNER], acc);
            if (t >= 1) acc = fmaf(w2, xz[rbase - 1 * 2 * D_INNER], acc);
        }
        acc = fmaf(w3, xz[rbase], acc);
        acc = silu_f(acc);
        u[(size_t)(b * SEQ + t) * D_INNER + d] = acc;
        tile[ty + i * 8][tx] = acc;
    }
    __syncthreads();
    #pragma unroll
    for (int i = 0; i < 4; i++) {
        const int dd = d0 + ty + i * 8;
        ut[(size_t)(b * D_INNER + dd) * SEQ + t0 + tx] = tile[tx][ty + i * 8];
    }
}

// ---------------------------------------------------------------------------
// delta = softplus(dt @ dtw^T + dtb), written transposed -> dltt [b][d][t]
// ---------------------------------------------------------------------------
__global__ void deltaT_kernel(const float* __restrict__ xdbc, const float* __restrict__ dtw,
                              const float* __restrict__ dtb, float* __restrict__ dltt)
{
    __shared__ float w_s[32][17];
    __shared__ float b_s[32];
    __shared__ float tile[32][33];
    const int b = blockIdx.z;
    const int t0 = blockIdx.x * 32, d0 = blockIdx.y * 32;
    const int tx = threadIdx.x, ty = threadIdx.y;
    const int tid = ty * 32 + tx;
    {
        int r = tid >> 4, c = tid & 15;
        w_s[r][c] = dtw[(d0 + r) * DT_RANK + c];
        w_s[r + 16][c] = dtw[(d0 + r + 16) * DT_RANK + c];
        if (tid < 32) b_s[tid] = dtb[d0 + tid];
    }
    __syncthreads();
    #pragma unroll
    for (int i = 0; i < 4; i++) {
        const int t = t0 + ty + i * 8;
        const float* xr = xdbc + (size_t)(b * SEQ + t) * 48;
        float acc = b_s[tx];
        #pragma unroll
        for (int r = 0; r < DT_RANK; r++)
            acc = fmaf(__ldg(xr + r), w_s[tx][r], acc);
        tile[ty + i * 8][tx] = (acc > 20.f) ? acc : log1pf(__expf(acc));
    }
    __syncthreads();
    #pragma unroll
    for (int i = 0; i < 4; i++) {
        const int dd = d0 + ty + i * 8;
        dltt[(size_t)(b * D_INNER + dd) * SEQ + t0 + tx] = tile[tx][ty + i * 8];
    }
}

// ---------------------------------------------------------------------------
// Fused chunked selective scan. One block per (b,d): 256 thr = 16 chunks x 16.
// Phase1: per-chunk local scan (P,Q). Phase2: serial combine (16 thr).
// Phase3: rescan with true start states, write yt.
// ---------------------------------------------------------------------------
__global__ __launch_bounds__(256) void scan_fused(
    const float* __restrict__ dltt, const float* __restrict__ ut,
    const float* __restrict__ xdbc, const float* __restrict__ A_log,
    const float* __restrict__ Dp, float* __restrict__ yt)
{
    __shared__ float Ps[NCHUNK][D_STATE];
    __shared__ float Qs[NCHUNK][D_STATE];
    __shared__ float Ts[NCHUNK][D_STATE];
    const int tid = threadIdx.x;
    const int g = blockIdx.x;                  // 0..2047
    const int c = tid >> 4;                    // chunk 0..15
    const int n = tid & 15;
    const int b = g >> 9;
    const int d = g & (D_INNER - 1);
    const float A  = -__expf(A_log[d * D_STATE + n]);
    const float Dd = Dp[d];
    const size_t base = (size_t)g * SEQ + c * CHUNK;
    const float* xb = xdbc + ((size_t)b * SEQ + c * CHUNK) * 48 + DT_RANK;

    // Phase 1: local scan, accumulate decay exponent
    float dt[16], uu[16];
    {
        float s = 0.f, sumd = 0.f;
        for (int tc = 0; tc < CHUNK; tc += 16) {
            #pragma unroll
            for (int q = 0; q < 4; q++) {
                float4 v = ((const float4*)(dltt + base + tc))[q];
                dt[q*4+0] = v.x; dt[q*4+1] = v.y; dt[q*4+2] = v.z; dt[q*4+3] = v.w;
                float4 w = ((const float4*)(ut + base + tc))[q];
                uu[q*4+0] = w.x; uu[q*4+1] = w.y; uu[q*4+2] = w.z; uu[q*4+3] = w.w;
            }
            #pragma unroll
            for (int j = 0; j < 16; j++) {
                const float Bn = __ldg(xb + (size_t)(tc + j) * 48 + n);
                s = fmaf(s, __expf(dt[j] * A), dt[j] * uu[j] * Bn);
                sumd += dt[j];
            }
        }
        Qs[c][n] = s;
        Ps[c][n] = __expf(A * sumd);
    }
    __syncthreads();

    // Phase 2: serial combine -> chunk start states
    if (tid < D_STATE) {
        float t = 0.f;
        Ts[0][tid] = 0.f;
        #pragma unroll
        for (int cc = 1; cc < NCHUNK; cc++) {
            t = fmaf(Ps[cc - 1][tid], t, Qs[cc - 1][tid]);
            Ts[cc][tid] = t;
        }
    }
    __syncthreads();

    // Phase 3: rescan with true start state, write outputs
    {
        float s = Ts[c][n];
        for (int tc = 0; tc < CHUNK; tc += 16) {
            #pragma unroll
            for (int q = 0; q < 4; q++) {
                float4 v = ((const float4*)(dltt + base + tc))[q];
                dt[q*4+0] = v.x; dt[q*4+1] = v.y; dt[q*4+2] = v.z; dt[q*4+3] = v.w;
                float4 w = ((const float4*)(ut + base + tc))[q];
                uu[q*4+0] = w.x; uu[q*4+1] = w.y; uu[q*4+2] = w.z; uu[q*4+3] = w.w;
            }
            float rv = 0.f;
            #pragma unroll
            for (int j = 0; j < 16; j++) {
                const float* xr = xb + (size_t)(tc + j) * 48;
                const float Bn = __ldg(xr + n);
                const float Cn = __ldg(xr + D_STATE + n);
                s = fmaf(s, __expf(dt[j] * A), dt[j] * uu[j] * Bn);
                float v = s * Cn;
                #pragma unroll
                for (int o = 8; o > 0; o >>= 1) v += __shfl_xor_sync(0xffffffffu, v, o);
                if (n == j) rv = v + uu[j] * Dd;
            }
            yt[base + tc + n] = rv;
        }
    }
}

// ---------------------------------------------------------------------------
// Gate + transpose back: y[b][t][d] = yt[b][d][t] * silu(z[b][t][d])
// ---------------------------------------------------------------------------
__global__ void gate_kernel(const float* __restrict__ yt, const float* __restrict__ xz,
                            float* __restrict__ y)
{
    __shared__ float t0s[32][33];
    const int b = blockIdx.z;
    const int tblk = blockIdx.x * 32, dblk = blockIdx.y * 32;
    const int tx = threadIdx.x, ty = threadIdx.y;
    #pragma unroll
    for (int i = 0; i < 4; i++) {
        int d = dblk + ty + i * 8;
        t0s[ty + i * 8][tx] = yt[(size_t)(b * D_INNER + d) * SEQ + tblk + tx];
    }
    __syncthreads();
    #pragma unroll
    for (int i = 0; i < 4; i++) {
        int t = tblk + ty + i * 8;
        size_t row = (size_t)(b * SEQ + t);
        float z = xz[row * (2 * D_INNER) + D_INNER + dblk + tx];
        y[row * D_INNER + dblk + tx] = t0s[tx][ty + i * 8] * silu_f(z);
    }
}

__global__ void loss_kernel(const float* __restrict__ nrm, float* __restrict__ out)
{
    const int tid = threadIdx.x; // 1024
    float s = 0.f;
    #pragma unroll
    for (int i = 0; i < 4; i++) s += nrm[tid + i * 1024];
    #pragma unroll
    for (int o = 16; o > 0; o >>= 1) s += __shfl_xor_sync(0xffffffffu, s, o);
    __shared__ float sm[32];
    if ((tid & 31) == 0) sm[tid >> 5] = s;
    __syncthreads();
    if (tid == 0) {
        float t = 0.f;
        #pragma unroll
        for (int i = 0; i < 32; i++) t += sm[i];
        *out = 0.01f * t * (1.f / (float)M_ROWS);
    }
}

// ---------------------------------------------------------------------------
// Launch
// ---------------------------------------------------------------------------
extern "C" void kernel_launch(void* const* d_in, const int* in_sizes, int n_in,
                              void* d_out, int out_size)
{
    const float* x      = (const float*)d_in[0];
    const float* in_w   = (const float*)d_in[1];
    const float* in_b   = (const float*)d_in[2];
    const float* ln_g   = (const float*)d_in[3];
    const float* ln_b   = (const float*)d_in[4];
    const float* blk_ng = (const float*)d_in[5];
    const float* blk_nb = (const float*)d_in[6];
    const float* blk_ipw= (const float*)d_in[7];
    const float* blk_cw = (const float*)d_in[8];
    const float* blk_cb = (const float*)d_in[9];
    const float* blk_xpw= (const float*)d_in[10];
    const float* blk_dtw= (const float*)d_in[11];
    const float* blk_dtb= (const float*)d_in[12];
    const float* blk_Al = (const float*)d_in[13];
    const float* blk_D  = (const float*)d_in[14];
    const float* blk_opw= (const float*)d_in[15];
    const float* op_w   = (const float*)d_in[16];
    const float* op_b   = (const float*)d_in[17];
    const float* cls_w  = (const float*)d_in[18];
    const float* cls_b  = (const float*)d_in[19];
    float* out = (float*)d_out;

    float *hs, *lt, *xz, *u, *ut, *dltt, *yt, *y, *xdbc, *h2, *nrm, *part;
    cudaGetSymbolAddress((void**)&hs,   g_hl);
    cudaGetSymbolAddress((void**)&lt,   g_lt);
    cudaGetSymbolAddress((void**)&xz,   g_xz);
    cudaGetSymbolAddress((void**)&u,    g_u);
    cudaGetSymbolAddress((void**)&ut,   g_ut);
    cudaGetSymbolAddress((void**)&dltt, g_dltt);
    cudaGetSymbolAddress((void**)&yt,   g_yt);
    cudaGetSymbolAddress((void**)&y,    g_y);
    cudaGetSymbolAddress((void**)&xdbc, g_xdbc);
    cudaGetSymbolAddress((void**)&h2,   g_h2);
    cudaGetSymbolAddress((void**)&nrm,  g_norm);
    cudaGetSymbolAddress((void**)&part, g_part);

    dim3 blk256(256);
    dim3 tblk(32, 8);
    dim3 tgrid(SEQ / 32, D_INNER / 32, BATCH);
    const int EP_BLOCKS = M_ROWS * 32 / 256;   // warp per row

    // in-proj (split-K=4) + fused epilogue (reduce+bias+LN+gelu+LN0)
    gemm16<4><<<dim3(D_MODEL / 128, M_ROWS / 128, 4), blk256>>>(
        x, in_w, part, M_ROWS, D_MODEL, X_DIM);
    ep_inproj<<<EP_BLOCKS, blk256>>>(part, in_b, ln_g, ln_b,
                                     blk_ng, blk_nb, hs, lt);

    for (int l = 0; l < N_LAYERS; l++) {
        const float* ipw = blk_ipw + (size_t)l * 2 * D_INNER * D_MODEL;
        const float* cw  = blk_cw  + (size_t)l * D_INNER * D_CONV;
        const float* cb  = blk_cb  + (size_t)l * D_INNER;
        const float* xpw = blk_xpw + (size_t)l * 48 * D_INNER;
        const float* dtw = blk_dtw + (size_t)l * D_INNER * DT_RANK;
        const float* dtb = blk_dtb + (size_t)l * D_INNER;
        const float* Al  = blk_Al  + (size_t)l * D_INNER * D_STATE;
        const float* Dp  = blk_D   + (size_t)l * D_INNER;
        const float* opw = blk_opw + (size_t)l * D_MODEL * D_INNER;

        gemm16<1><<<dim3(2 * D_INNER / 128, M_ROWS / 128, 1), blk256>>>(
            lt, ipw, xz, M_ROWS, 2 * D_INNER, D_MODEL);
        conv2_kernel<<<tgrid, tblk>>>(xz, cw, cb, u, ut);
        gemm_xpw<<<dim3(1, M_ROWS / 128, 4), blk256>>>(
            u, xpw, part, M_ROWS, 48, D_INNER, 4);
        reduce_k<4,0><<<(M_ROWS * 48 / 4 + 255) / 256, blk256>>>(
            part, nullptr, xdbc, M_ROWS * 48, 48);
        deltaT_kernel<<<tgrid, tblk>>>(xdbc, dtw, dtb, dltt);
        scan_fused<<<NGROUP, blk256>>>(dltt, ut, xdbc, Al, Dp, yt);
        gate_kernel<<<tgrid, tblk>>>(yt, xz, y);
        gemm16<4><<<dim3(D_MODEL / 128, M_ROWS / 128, 4), blk256>>>(
            y, opw, part, M_ROWS, D_MODEL, D_INNER);
        if (l + 1 < N_LAYERS) {
            ep_opw<1><<<EP_BLOCKS, blk256>>>(part,
                blk_ng + (size_t)(l + 1) * D_MODEL,
                blk_nb + (size_t)(l + 1) * D_MODEL, hs, lt);
        } else {
            ep_opw<0><<<EP_BLOCKS, blk256>>>(part, nullptr, nullptr, hs, lt);
        }
    }

    // head
    gemm16<4><<<dim3(D_MODEL / 128, M_ROWS / 128, 4), blk256>>>(
        hs, op_w, part, M_ROWS, D_MODEL, D_MODEL);
    ep_head<<<EP_BLOCKS, blk256>>>(part, op_b, h2, nrm);
    gemm16<4><<<dim3(N_CLS / 128, M_ROWS / 128, 4), blk256>>>(
        h2, cls_w, part, M_ROWS, N_CLS, D_MODEL);
    reduce_k<4,1><<<(M_ROWS * N_CLS / 4 + 255) / 256, blk256>>>(
        part, cls_b, out, M_ROWS * N_CLS, N_CLS);
    loss_kernel<<<1, 1024>>>(nrm, out + (out_size - 1));
}

// round 6
// speedup vs baseline: 4.5175x; 1.0823x over previous
#include <cuda_runtime.h>
#include <math.h>

#define BATCH    4
#define SEQ      1024
#define M_ROWS   4096
#define D_MODEL  256
#define D_INNER  512
#define D_STATE  16
#define DT_RANK  16
#define D_CONV   4
#define N_LAYERS 2
#define X_DIM    768
#define N_CLS    128

#define NCHUNK   16
#define CHUNK    64           // SEQ / NCHUNK
#define NGROUP   (BATCH * D_INNER)   // 2048

// ---------------------------------------------------------------------------
// Scratch
// ---------------------------------------------------------------------------
__device__ float g_hl  [M_ROWS * D_MODEL];     // residual stream hs
__device__ float g_lt  [M_ROWS * D_MODEL];     // per-layer LN output
__device__ float g_xz  [M_ROWS * 2 * D_INNER];
__device__ float g_u   [M_ROWS * D_INNER];     // [b][t][d]
__device__ float g_ut  [M_ROWS * D_INNER];     // [b][d][t]
__device__ float g_dltt[M_ROWS * D_INNER];     // [b][d][t]
__device__ float g_yt  [M_ROWS * D_INNER];     // [b][d][t]
__device__ float g_y   [M_ROWS * D_INNER];     // [b][t][d]
__device__ float g_xdbc[M_ROWS * 48];
__device__ float g_h2  [M_ROWS * D_MODEL];
__device__ float g_norm[M_ROWS];
__device__ float g_part[4 * M_ROWS * D_MODEL]; // split-K partials

__device__ __forceinline__ float gelu_f(float v) {
    return 0.5f * v * (1.f + erff(v * 0.70710678118654752f));
}
__device__ __forceinline__ float silu_f(float v) {
    return v / (1.f + __expf(-v));
}

// ---------------------------------------------------------------------------
// Packed f32x2 helpers (sm_100+): FFMA2 = 2 FMAs per issue slot
// ---------------------------------------------------------------------------
__device__ __forceinline__ void fma_f32x2(unsigned long long& d,
                                          unsigned long long a,
                                          unsigned long long b) {
    asm("fma.rn.f32x2 %0, %1, %2, %0;" : "+l"(d) : "l"(a), "l"(b));
}
__device__ __forceinline__ unsigned long long pack_dup(float a) {
    unsigned long long r;
    asm("mov.b64 %0, {%1, %1};" : "=l"(r) : "f"(a));
    return r;
}
__device__ __forceinline__ float2 unpack_f32x2(unsigned long long v) {
    float2 r;
    asm("mov.b64 {%0, %1}, %2;" : "=f"(r.x), "=f"(r.y) : "l"(v));
    return r;
}

// ---------------------------------------------------------------------------
// Double-buffered GEMM, BK=16, FFMA2 inner loop.
// C[M,N] = A[M,K] @ W[N,K]^T. 128x128 tile, 256 threads, 8x8 per thread
// (acc packed as 8x4 f32x2 pairs along n).
// SPLIT>1: blockIdx.z selects K-chunk, writes raw partial to C + z*M*N.
// Requires M%128==0, N%128==0, (K/SPLIT)%16==0.
// ---------------------------------------------------------------------------
template<int SPLIT>
__global__ __launch_bounds__(256) void gemm16(
    const float* __restrict__ A, const float* __restrict__ W,
    float* __restrict__ C, int M, int N, int K)
{
    __shared__ float As[2][16][132];
    __shared__ float Bs[2][16][132];
    const int tid = threadIdx.x;
    const int m0 = blockIdx.y * 128;
    const int n0 = blockIdx.x * 128;
    const int Kc = K / SPLIT;
    const int kbeg = blockIdx.z * Kc;

    const int lr = tid >> 1;            // 0..127
    const int lc8 = (tid & 1) * 8;      // 0 or 8
    const float* Aload = A + (size_t)(m0 + lr) * K + kbeg + lc8;
    const float* Wload = W + (size_t)(n0 + lr) * K + kbeg + lc8;

    const int tm = (tid >> 4) * 4;
    const int tn = (tid & 15) * 4;

    unsigned long long acc2[8][4];
    #pragma unroll
    for (int i = 0; i < 8; i++)
        #pragma unroll
        for (int j = 0; j < 4; j++) acc2[i][j] = 0ull;

    float4 a0 = *(const float4*)Aload;
    float4 a1 = *(const float4*)(Aload + 4);
    float4 w0 = *(const float4*)Wload;
    float4 w1 = *(const float4*)(Wload + 4);
    As[0][lc8 + 0][lr] = a0.x; As[0][lc8 + 1][lr] = a0.y;
    As[0][lc8 + 2][lr] = a0.z; As[0][lc8 + 3][lr] = a0.w;
    As[0][lc8 + 4][lr] = a1.x; As[0][lc8 + 5][lr] = a1.y;
    As[0][lc8 + 6][lr] = a1.z; As[0][lc8 + 7][lr] = a1.w;
    Bs[0][lc8 + 0][lr] = w0.x; Bs[0][lc8 + 1][lr] = w0.y;
    Bs[0][lc8 + 2][lr] = w0.z; Bs[0][lc8 + 3][lr] = w0.w;
    Bs[0][lc8 + 4][lr] = w1.x; Bs[0][lc8 + 5][lr] = w1.y;
    Bs[0][lc8 + 6][lr] = w1.z; Bs[0][lc8 + 7][lr] = w1.w;
    __syncthreads();

    const int iters = Kc / 16;
    int buf = 0;
    for (int it = 0; it < iters; it++) {
        if (it + 1 < iters) {
            a0 = *(const float4*)(Aload + (it + 1) * 16);
            a1 = *(const float4*)(Aload + (it + 1) * 16 + 4);
            w0 = *(const float4*)(Wload + (it + 1) * 16);
            w1 = *(const float4*)(Wload + (it + 1) * 16 + 4);
        }
        #pragma unroll
        for (int kk = 0; kk < 16; kk++) {
            float a[8];
            unsigned long long b2[4];
            *(float4*)&a[0] = *(const float4*)&As[buf][kk][tm];
            *(float4*)&a[4] = *(const float4*)&As[buf][kk][tm + 64];
            {
                ulonglong2 bb0 = *(const ulonglong2*)&Bs[buf][kk][tn];
                ulonglong2 bb1 = *(const ulonglong2*)&Bs[buf][kk][tn + 64];
                b2[0] = bb0.x; b2[1] = bb0.y; b2[2] = bb1.x; b2[3] = bb1.y;
            }
            #pragma unroll
            for (int i = 0; i < 8; i++) {
                const unsigned long long a2 = pack_dup(a[i]);
                fma_f32x2(acc2[i][0], a2, b2[0]);
                fma_f32x2(acc2[i][1], a2, b2[1]);
                fma_f32x2(acc2[i][2], a2, b2[2]);
                fma_f32x2(acc2[i][3], a2, b2[3]);
            }
        }
        if (it + 1 < iters) {
            buf ^= 1;
            As[buf][lc8 + 0][lr] = a0.x; As[buf][lc8 + 1][lr] = a0.y;
            As[buf][lc8 + 2][lr] = a0.z; As[buf][lc8 + 3][lr] = a0.w;
            As[buf][lc8 + 4][lr] = a1.x; As[buf][lc8 + 5][lr] = a1.y;
            As[buf][lc8 + 6][lr] = a1.z; As[buf][lc8 + 7][lr] = a1.w;
            Bs[buf][lc8 + 0][lr] = w0.x; Bs[buf][lc8 + 1][lr] = w0.y;
            Bs[buf][lc8 + 2][lr] = w0.z; Bs[buf][lc8 + 3][lr] = w0.w;
            Bs[buf][lc8 + 4][lr] = w1.x; Bs[buf][lc8 + 5][lr] = w1.y;
            Bs[buf][lc8 + 6][lr] = w1.z; Bs[buf][lc8 + 7][lr] = w1.w;
            __syncthreads();
        }
    }

    float* Cout = (SPLIT > 1) ? (C + (size_t)blockIdx.z * M * N) : C;
    #pragma unroll
    for (int i = 0; i < 8; i++) {
        const int m = m0 + tm + ((i < 4) ? i : (64 + i - 4));
        #pragma unroll
        for (int jh = 0; jh < 2; jh++) {
            const int n = n0 + tn + jh * 64;
            float2 p0 = unpack_f32x2(acc2[i][jh * 2 + 0]);
            float2 p1 = unpack_f32x2(acc2[i][jh * 2 + 1]);
            float4 v = {p0.x, p0.y, p1.x, p1.y};
            *(float4*)(Cout + (size_t)m * N + n) = v;
        }
    }
}

// ---------------------------------------------------------------------------
// xpw GEMM (N=48): 128x64 tile w/ split-K partials. grid (1, M/128, SPLIT)
// ---------------------------------------------------------------------------
__global__ __launch_bounds__(256) void gemm_xpw(
    const float* __restrict__ A, const float* __restrict__ W,
    float* __restrict__ Cp, int M, int N, int K, int splitK)
{
    __shared__ float As[16][132];
    __shared__ float Ws[16][68];
    const int tid = threadIdx.x;
    const int m0 = blockIdx.y * 128;
    const int Kc = K / splitK;
    const int kbeg = blockIdx.z * Kc;
    const int tm = tid >> 4;
    const int tn = tid & 15;
    const int lr = tid >> 2;
    const int lc = (tid & 3) * 4;

    float acc[8][4] = {};

    for (int k0 = kbeg; k0 < kbeg + Kc; k0 += 16) {
        #pragma unroll
        for (int i = 0; i < 2; i++) {
            int r = lr + i * 64;
            float4 v = *(const float4*)(A + (size_t)(m0 + r) * K + k0 + lc);
            As[lc + 0][r] = v.x; As[lc + 1][r] = v.y;
            As[lc + 2][r] = v.z; As[lc + 3][r] = v.w;
        }
        {
            float4 v = make_float4(0.f, 0.f, 0.f, 0.f);
            if (lr < N)
                v = *(const float4*)(W + (size_t)lr * K + k0 + lc);
            Ws[lc + 0][lr] = v.x; Ws[lc + 1][lr] = v.y;
            Ws[lc + 2][lr] = v.z; Ws[lc + 3][lr] = v.w;
        }
        __syncthreads();
        #pragma unroll
        for (int kk = 0; kk < 16; kk++) {
            float a[8], b[4];
            *(float4*)&a[0] = *(const float4*)&As[kk][tm * 8];
            *(float4*)&a[4] = *(const float4*)&As[kk][tm * 8 + 4];
            *(float4*)&b[0] = *(const float4*)&Ws[kk][tn * 4];
            #pragma unroll
            for (int i = 0; i < 8; i++)
                #pragma unroll
                for (int j = 0; j < 4; j++)
                    acc[i][j] = fmaf(a[i], b[j], acc[i][j]);
        }
        __syncthreads();
    }

    const int n = tn * 4;
    if (n >= N) return;
    float* Cout = Cp + (size_t)blockIdx.z * M * N;
    #pragma unroll
    for (int i = 0; i < 8; i++) {
        int m = m0 + tm * 8 + i;
        float4 v = {acc[i][0], acc[i][1], acc[i][2], acc[i][3]};
        *(float4*)(Cout + (size_t)m * N + n) = v;
    }
}

// ---------------------------------------------------------------------------
// Generic split-K reduce (xdbc, cls)
// ---------------------------------------------------------------------------
template<int S, int BIAS>
__global__ void reduce_k(const float* __restrict__ part, const float* __restrict__ bias,
                         float* __restrict__ out, int MN, int N)
{
    int i4 = (blockIdx.x * blockDim.x + threadIdx.x) * 4;
    if (i4 >= MN) return;
    float4 v = *(const float4*)(part + i4);
    #pragma unroll
    for (int s = 1; s < S; s++) {
        float4 p = *(const float4*)(part + (size_t)s * MN + i4);
        v.x += p.x; v.y += p.y; v.z += p.z; v.w += p.w;
    }
    if (BIAS) {
        float4 bv = *(const float4*)(bias + (i4 % N));
        v.x += bv.x; v.y += bv.y; v.z += bv.z; v.w += bv.w;
    }
    *(float4*)(out + i4) = v;
}

// ---------------------------------------------------------------------------
// Warp-per-row helpers: each lane holds 8 cols of a 256-col row.
// ---------------------------------------------------------------------------
__device__ __forceinline__ void warp_stats(const float4& v0, const float4& v1,
                                           float& mu, float& rstd)
{
    float s1 = v0.x + v0.y + v0.z + v0.w + v1.x + v1.y + v1.z + v1.w;
    float s2 = v0.x*v0.x + v0.y*v0.y + v0.z*v0.z + v0.w*v0.w
             + v1.x*v1.x + v1.y*v1.y + v1.z*v1.z + v1.w*v1.w;
    #pragma unroll
    for (int o = 16; o > 0; o >>= 1) {
        s1 += __shfl_xor_sync(0xffffffffu, s1, o);
        s2 += __shfl_xor_sync(0xffffffffu, s2, o);
    }
    mu = s1 * (1.f / 256.f);
    rstd = rsqrtf(s2 * (1.f / 256.f) - mu * mu + 1e-5f);
}

__device__ __forceinline__ float4 ln_apply4(const float4& v, float mu, float rstd,
                                            const float4& g, const float4& b)
{
    float4 o;
    o.x = (v.x - mu) * rstd * g.x + b.x;
    o.y = (v.y - mu) * rstd * g.y + b.y;
    o.z = (v.z - mu) * rstd * g.z + b.z;
    o.w = (v.w - mu) * rstd * g.w + b.w;
    return o;
}
__device__ __forceinline__ float4 gelu4(float4 v) {
    v.x = gelu_f(v.x); v.y = gelu_f(v.y); v.z = gelu_f(v.z); v.w = gelu_f(v.w);
    return v;
}

// ---------------------------------------------------------------------------
// in-proj epilogue: reduce 4 partials + bias -> LN(ln_g)+gelu -> hs
//                   -> LN(blk_ng[0]) -> lt
// ---------------------------------------------------------------------------
__global__ void ep_inproj(const float* __restrict__ part, const float* __restrict__ bias,
                          const float* __restrict__ lng, const float* __restrict__ lnb,
                          const float* __restrict__ ng0, const float* __restrict__ nb0,
                          float* __restrict__ hs, float* __restrict__ lt)
{
    const int gi = blockIdx.x * blockDim.x + threadIdx.x;
    const int row = gi >> 5;
    const int lane = gi & 31;
    const int MN = M_ROWS * D_MODEL;
    const int c0 = lane * 4, c1 = 128 + lane * 4;
    const size_t i0 = (size_t)row * D_MODEL + c0;
    const size_t i1 = (size_t)row * D_MODEL + c1;
    float4 v0 = make_float4(0,0,0,0), v1 = make_float4(0,0,0,0);
    #pragma unroll
    for (int s = 0; s < 4; s++) {
        float4 p0 = *(const float4*)(part + (size_t)s * MN + i0);
        float4 p1 = *(const float4*)(part + (size_t)s * MN + i1);
        v0.x += p0.x; v0.y += p0.y; v0.z += p0.z; v0.w += p0.w;
        v1.x += p1.x; v1.y += p1.y; v1.z += p1.z; v1.w += p1.w;
    }
    float4 b0 = *(const float4*)(bias + c0), b1 = *(const float4*)(bias + c1);
    v0.x += b0.x; v0.y += b0.y; v0.z += b0.z; v0.w += b0.w;
    v1.x += b1.x; v1.y += b1.y; v1.z += b1.z; v1.w += b1.w;
    float mu, rstd;
    warp_stats(v0, v1, mu, rstd);
    float4 g0 = *(const float4*)(lng + c0), g1 = *(const float4*)(lng + c1);
    float4 bb0 = *(const float4*)(lnb + c0), bb1 = *(const float4*)(lnb + c1);
    float4 w0 = gelu4(ln_apply4(v0, mu, rstd, g0, bb0));
    float4 w1 = gelu4(ln_apply4(v1, mu, rstd, g1, bb1));
    *(float4*)(hs + i0) = w0;
    *(float4*)(hs + i1) = w1;
    warp_stats(w0, w1, mu, rstd);
    g0 = *(const float4*)(ng0 + c0); g1 = *(const float4*)(ng0 + c1);
    bb0 = *(const float4*)(nb0 + c0); bb1 = *(const float4*)(nb0 + c1);
    *(float4*)(lt + i0) = ln_apply4(w0, mu, rstd, g0, bb0);
    *(float4*)(lt + i1) = ln_apply4(w1, mu, rstd, g1, bb1);
}

// ---------------------------------------------------------------------------
// opw epilogue: hs += reduce4(part); optional LN(ng,nb) -> lt
// ---------------------------------------------------------------------------
template<int LN>
__global__ void ep_opw(const float* __restrict__ part, const float* __restrict__ ng,
                       const float* __restrict__ nb, float* __restrict__ hs,
                       float* __restrict__ lt)
{
    const int gi = blockIdx.x * blockDim.x + threadIdx.x;
    const int row = gi >> 5;
    const int lane = gi & 31;
    const int MN = M_ROWS * D_MODEL;
    const int c0 = lane * 4, c1 = 128 + lane * 4;
    const size_t i0 = (size_t)row * D_MODEL + c0;
    const size_t i1 = (size_t)row * D_MODEL + c1;
    float4 v0 = *(const float4*)(hs + i0);
    float4 v1 = *(const float4*)(hs + i1);
    #pragma unroll
    for (int s = 0; s < 4; s++) {
        float4 p0 = *(const float4*)(part + (size_t)s * MN + i0);
        float4 p1 = *(const float4*)(part + (size_t)s * MN + i1);
        v0.x += p0.x; v0.y += p0.y; v0.z += p0.z; v0.w += p0.w;
        v1.x += p1.x; v1.y += p1.y; v1.z += p1.z; v1.w += p1.w;
    }
    *(float4*)(hs + i0) = v0;
    *(float4*)(hs + i1) = v1;
    if (LN) {
        float mu, rstd;
        warp_stats(v0, v1, mu, rstd);
        float4 g0 = *(const float4*)(ng + c0), g1 = *(const float4*)(ng + c1);
        float4 b0 = *(const float4*)(nb + c0), b1 = *(const float4*)(nb + c1);
        *(float4*)(lt + i0) = ln_apply4(v0, mu, rstd, g0, b0);
        *(float4*)(lt + i1) = ln_apply4(v1, mu, rstd, g1, b1);
    }
}

// ---------------------------------------------------------------------------
// head epilogue: h2 = gelu(reduce4 + bias); nrm[row] = ||h2 row||
// ---------------------------------------------------------------------------
__global__ void ep_head(const float* __restrict__ part, const float* __restrict__ bias,
                        float* __restrict__ h2, float* __restrict__ nrm)
{
    const int gi = blockIdx.x * blockDim.x + threadIdx.x;
    const int row = gi >> 5;
    const int lane = gi & 31;
    const int MN = M_ROWS * D_MODEL;
    const int c0 = lane * 4, c1 = 128 + lane * 4;
    const size_t i0 = (size_t)row * D_MODEL + c0;
    const size_t i1 = (size_t)row * D_MODEL + c1;
    float4 v0 = make_float4(0,0,0,0), v1 = make_float4(0,0,0,0);
    #pragma unroll
    for (int s = 0; s < 4; s++) {
        float4 p0 = *(const float4*)(part + (size_t)s * MN + i0);
        float4 p1 = *(const float4*)(part + (size_t)s * MN + i1);
        v0.x += p0.x; v0.y += p0.y; v0.z += p0.z; v0.w += p0.w;
        v1.x += p1.x; v1.y += p1.y; v1.z += p1.z; v1.w += p1.w;
    }
    float4 b0 = *(const float4*)(bias + c0), b1 = *(const float4*)(bias + c1);
    v0.x += b0.x; v0.y += b0.y; v0.z += b0.z; v0.w += b0.w;
    v1.x += b1.x; v1.y += b1.y; v1.z += b1.z; v1.w += b1.w;
    v0 = gelu4(v0); v1 = gelu4(v1);
    *(float4*)(h2 + i0) = v0;
    *(float4*)(h2 + i1) = v1;
    float s = v0.x*v0.x + v0.y*v0.y + v0.z*v0.z + v0.w*v0.w
            + v1.x*v1.x + v1.y*v1.y + v1.z*v1.z + v1.w*v1.w;
    #pragma unroll
    for (int o = 16; o > 0; o >>= 1) s += __shfl_xor_sync(0xffffffffu, s, o);
    if (lane == 0) nrm[row] = sqrtf(s);
}

// ---------------------------------------------------------------------------
// Depthwise causal conv (k=4) + SiLU -> u [b][t][d] AND ut [b][d][t]
// ---------------------------------------------------------------------------
__global__ void conv2_kernel(const float* __restrict__ xz, const float* __restrict__ cw,
                             const float* __restrict__ cb, float* __restrict__ u,
                             float* __restrict__ ut)
{
    __shared__ float tile[32][33];
    const int b = blockIdx.z;
    const int t0 = blockIdx.x * 32, d0 = blockIdx.y * 32;
    const int tx = threadIdx.x, ty = threadIdx.y;
    const int d = d0 + tx;
    const float w0 = cw[d * 4 + 0], w1 = cw[d * 4 + 1];
    const float w2 = cw[d * 4 + 2], w3 = cw[d * 4 + 3];
    const float bb = cb[d];
    #pragma unroll
    for (int i = 0; i < 4; i++) {
        const int t = t0 + ty + i * 8;
        const size_t rbase = (size_t)(b * SEQ + t) * (2 * D_INNER) + d;
        float acc = bb;
        if (t >= 3) {
            acc = fmaf(w0, xz[rbase - 3 * 2 * D_INNER], acc);
            acc = fmaf(w1, xz[rbase - 2 * 2 * D_INNER], acc);
            acc = fmaf(w2, xz[rbase - 1 * 2 * D_INNER], acc);
        } else {
            if (t >= 2) acc = fmaf(w1, xz[rbase - 2 * 2 * D_INNER], acc);
            if (t >= 1) acc = fmaf(w2, xz[rbase - 1 * 2 * D_INNER], acc);
        }
        acc = fmaf(w3, xz[rbase], acc);
        acc = silu_f(acc);
        u[(size_t)(b * SEQ + t) * D_INNER + d] = acc;
        tile[ty + i * 8][tx] = acc;
    }
    __syncthreads();
    #pragma unroll
    for (int i = 0; i < 4; i++) {
        const int dd = d0 + ty + i * 8;
        ut[(size_t)(b * D_INNER + dd) * SEQ + t0 + tx] = tile[tx][ty + i * 8];
    }
}

// ---------------------------------------------------------------------------
// delta = softplus(dt @ dtw^T + dtb), written transposed -> dltt [b][d][t]
// ---------------------------------------------------------------------------
__global__ void deltaT_kernel(const float* __restrict__ xdbc, const float* __restrict__ dtw,
                              const float* __restrict__ dtb, float* __restrict__ dltt)
{
    __shared__ float w_s[32][17];
    __shared__ float b_s[32];
    __shared__ float tile[32][33];
    const int b = blockIdx.z;
    const int t0 = blockIdx.x * 32, d0 = blockIdx.y * 32;
    const int tx = threadIdx.x, ty = threadIdx.y;
    const int tid = ty * 32 + tx;
    {
        int r = tid >> 4, c = tid & 15;
        w_s[r][c] = dtw[(d0 + r) * DT_RANK + c];
        w_s[r + 16][c] = dtw[(d0 + r + 16) * DT_RANK + c];
        if (tid < 32) b_s[tid] = dtb[d0 + tid];
    }
    __syncthreads();
    #pragma unroll
    for (int i = 0; i < 4; i++) {
        const int t = t0 + ty + i * 8;
        const float* xr = xdbc + (size_t)(b * SEQ + t) * 48;
        float acc = b_s[tx];
        #pragma unroll
        for (int r = 0; r < DT_RANK; r++)
            acc = fmaf(__ldg(xr + r), w_s[tx][r], acc);
        tile[ty + i * 8][tx] = (acc > 20.f) ? acc : log1pf(__expf(acc));
    }
    __syncthreads();
    #pragma unroll
    for (int i = 0; i < 4; i++) {
        const int dd = d0 + ty + i * 8;
        dltt[(size_t)(b * D_INNER + dd) * SEQ + t0 + tx] = tile[tx][ty + i * 8];
    }
}

// ---------------------------------------------------------------------------
// Fused chunked selective scan. One block per (b,d): 256 thr = 16 chunks x 16.
// ---------------------------------------------------------------------------
__global__ __launch_bounds__(256) void scan_fused(
    const float* __restrict__ dltt, const float* __restrict__ ut,
    const float* __restrict__ xdbc, const float* __restrict__ A_log,
    const float* __restrict__ Dp, float* __restrict__ yt)
{
    __shared__ float Ps[NCHUNK][D_STATE];
    __shared__ float Qs[NCHUNK][D_STATE];
    __shared__ float Ts[NCHUNK][D_STATE];
    const int tid = threadIdx.x;
    const int g = blockIdx.x;                  // 0..2047
    const int c = tid >> 4;                    // chunk 0..15
    const int n = tid & 15;
    const int b = g >> 9;
    const int d = g & (D_INNER - 1);
    const float A  = -__expf(A_log[d * D_STATE + n]);
    const float Dd = Dp[d];
    const size_t base = (size_t)g * SEQ + c * CHUNK;
    const float* xb = xdbc + ((size_t)b * SEQ + c * CHUNK) * 48 + DT_RANK;

    float dt[16], uu[16];
    {
        float s = 0.f, sumd = 0.f;
        for (int tc = 0; tc < CHUNK; tc += 16) {
            #pragma unroll
            for (int q = 0; q < 4; q++) {
                float4 v = ((const float4*)(dltt + base + tc))[q];
                dt[q*4+0] = v.x; dt[q*4+1] = v.y; dt[q*4+2] = v.z; dt[q*4+3] = v.w;
                float4 w = ((const float4*)(ut + base + tc))[q];
                uu[q*4+0] = w.x; uu[q*4+1] = w.y; uu[q*4+2] = w.z; uu[q*4+3] = w.w;
            }
            #pragma unroll
            for (int j = 0; j < 16; j++) {
                const float Bn = __ldg(xb + (size_t)(tc + j) * 48 + n);
                s = fmaf(s, __expf(dt[j] * A), dt[j] * uu[j] * Bn);
                sumd += dt[j];
            }
        }
        Qs[c][n] = s;
        Ps[c][n] = __expf(A * sumd);
    }
    __syncthreads();

    if (tid < D_STATE) {
        float t = 0.f;
        Ts[0][tid] = 0.f;
        #pragma unroll
        for (int cc = 1; cc < NCHUNK; cc++) {
            t = fmaf(Ps[cc - 1][tid], t, Qs[cc - 1][tid]);
            Ts[cc][tid] = t;
        }
    }
    __syncthreads();

    {
        float s = Ts[c][n];
        for (int tc = 0; tc < CHUNK; tc += 16) {
            #pragma unroll
            for (int q = 0; q < 4; q++) {
                float4 v = ((const float4*)(dltt + base + tc))[q];
                dt[q*4+0] = v.x; dt[q*4+1] = v.y; dt[q*4+2] = v.z; dt[q*4+3] = v.w;
                float4 w = ((const float4*)(ut + base + tc))[q];
                uu[q*4+0] = w.x; uu[q*4+1] = w.y; uu[q*4+2] = w.z; uu[q*4+3] = w.w;
            }
            float rv = 0.f;
            #pragma unroll
            for (int j = 0; j < 16; j++) {
                const float* xr = xb + (size_t)(tc + j) * 48;
                const float Bn = __ldg(xr + n);
                const float Cn = __ldg(xr + D_STATE + n);
                s = fmaf(s, __expf(dt[j] * A), dt[j] * uu[j] * Bn);
                float v = s * Cn;
                #pragma unroll
                for (int o = 8; o > 0; o >>= 1) v += __shfl_xor_sync(0xffffffffu, v, o);
                if (n == j) rv = v + uu[j] * Dd;
            }
            yt[base + tc + n] = rv;
        }
    }
}

// ---------------------------------------------------------------------------
// Gate + transpose back: y[b][t][d] = yt[b][d][t] * silu(z[b][t][d])
// ---------------------------------------------------------------------------
__global__ void gate_kernel(const float* __restrict__ yt, const float* __restrict__ xz,
                            float* __restrict__ y)
{
    __shared__ float t0s[32][33];
    const int b = blockIdx.z;
    const int tblk = blockIdx.x * 32, dblk = blockIdx.y * 32;
    const int tx = threadIdx.x, ty = threadIdx.y;
    #pragma unroll
    for (int i = 0; i < 4; i++) {
        int d = dblk + ty + i * 8;
        t0s[ty + i * 8][tx] = yt[(size_t)(b * D_INNER + d) * SEQ + tblk + tx];
    }
    __syncthreads();
    #pragma unroll
    for (int i = 0; i < 4; i++) {
        int t = tblk + ty + i * 8;
        size_t row = (size_t)(b * SEQ + t);
        float z = xz[row * (2 * D_INNER) + D_INNER + dblk + tx];
        y[row * D_INNER + dblk + tx] = t0s[tx][ty + i * 8] * silu_f(z);
    }
}

__global__ void loss_kernel(const float* __restrict__ nrm, float* __restrict__ out)
{
    const int tid = threadIdx.x; // 1024
    float s = 0.f;
    #pragma unroll
    for (int i = 0; i < 4; i++) s += nrm[tid + i * 1024];
    #pragma unroll
    for (int o = 16; o > 0; o >>= 1) s += __shfl_xor_sync(0xffffffffu, s, o);
    __shared__ float sm[32];
    if ((tid & 31) == 0) sm[tid >> 5] = s;
    __syncthreads();
    if (tid == 0) {
        float t = 0.f;
        #pragma unroll
        for (int i = 0; i < 32; i++) t += sm[i];
        *out = 0.01f * t * (1.f / (float)M_ROWS);
    }
}

// ---------------------------------------------------------------------------
// Launch
// ---------------------------------------------------------------------------
extern "C" void kernel_launch(void* const* d_in, const int* in_sizes, int n_in,
                              void* d_out, int out_size)
{
    const float* x      = (const float*)d_in[0];
    const float* in_w   = (const float*)d_in[1];
    const float* in_b   = (const float*)d_in[2];
    const float* ln_g   = (const float*)d_in[3];
    const float* ln_b   = (const float*)d_in[4];
    const float* blk_ng = (const float*)d_in[5];
    const float* blk_nb = (const float*)d_in[6];
    const float* blk_ipw= (const float*)d_in[7];
    const float* blk_cw = (const float*)d_in[8];
    const float* blk_cb = (const float*)d_in[9];
    const float* blk_xpw= (const float*)d_in[10];
    const float* blk_dtw= (const float*)d_in[11];
    const float* blk_dtb= (const float*)d_in[12];
    const float* blk_Al = (const float*)d_in[13];
    const float* blk_D  = (const float*)d_in[14];
    const float* blk_opw= (const float*)d_in[15];
    const float* op_w   = (const float*)d_in[16];
    const float* op_b   = (const float*)d_in[17];
    const float* cls_w  = (const float*)d_in[18];
    const float* cls_b  = (const float*)d_in[19];
    float* out = (float*)d_out;

    float *hs, *lt, *xz, *u, *ut, *dltt, *yt, *y, *xdbc, *h2, *nrm, *part;
    cudaGetSymbolAddress((void**)&hs,   g_hl);
    cudaGetSymbolAddress((void**)&lt,   g_lt);
    cudaGetSymbolAddress((void**)&xz,   g_xz);
    cudaGetSymbolAddress((void**)&u,    g_u);
    cudaGetSymbolAddress((void**)&ut,   g_ut);
    cudaGetSymbolAddress((void**)&dltt, g_dltt);
    cudaGetSymbolAddress((void**)&yt,   g_yt);
    cudaGetSymbolAddress((void**)&y,    g_y);
    cudaGetSymbolAddress((void**)&xdbc, g_xdbc);
    cudaGetSymbolAddress((void**)&h2,   g_h2);
    cudaGetSymbolAddress((void**)&nrm,  g_norm);
    cudaGetSymbolAddress((void**)&part, g_part);

    dim3 blk256(256);
    dim3 tblk(32, 8);
    dim3 tgrid(SEQ / 32, D_INNER / 32, BATCH);
    const int EP_BLOCKS = M_ROWS * 32 / 256;   // warp per row

    // in-proj (split-K=4) + fused epilogue
    gemm16<4><<<dim3(D_MODEL / 128, M_ROWS / 128, 4), blk256>>>(
        x, in_w, part, M_ROWS, D_MODEL, X_DIM);
    ep_inproj<<<EP_BLOCKS, blk256>>>(part, in_b, ln_g, ln_b,
                                     blk_ng, blk_nb, hs, lt);

    for (int l = 0; l < N_LAYERS; l++) {
        const float* ipw = blk_ipw + (size_t)l * 2 * D_INNER * D_MODEL;
        const float* cw  = blk_cw  + (size_t)l * D_INNER * D_CONV;
        const float* cb  = blk_cb  + (size_t)l * D_INNER;
        const float* xpw = blk_xpw + (size_t)l * 48 * D_INNER;
        const float* dtw = blk_dtw + (size_t)l * D_INNER * DT_RANK;
        const float* dtb = blk_dtb + (size_t)l * D_INNER;
        const float* Al  = blk_Al  + (size_t)l * D_INNER * D_STATE;
        const float* Dp  = blk_D   + (size_t)l * D_INNER;
        const float* opw = blk_opw + (size_t)l * D_MODEL * D_INNER;

        gemm16<1><<<dim3(2 * D_INNER / 128, M_ROWS / 128, 1), blk256>>>(
            lt, ipw, xz, M_ROWS, 2 * D_INNER, D_MODEL);
        conv2_kernel<<<tgrid, tblk>>>(xz, cw, cb, u, ut);
        gemm_xpw<<<dim3(1, M_ROWS / 128, 4), blk256>>>(
            u, xpw, part, M_ROWS, 48, D_INNER, 4);
        reduce_k<4,0><<<(M_ROWS * 48 / 4 + 255) / 256, blk256>>>(
            part, nullptr, xdbc, M_ROWS * 48, 48);
        deltaT_kernel<<<tgrid, tblk>>>(xdbc, dtw, dtb, dltt);
        scan_fused<<<NGROUP, blk256>>>(dltt, ut, xdbc, Al, Dp, yt);
        gate_kernel<<<tgrid, tblk>>>(yt, xz, y);
        gemm16<4><<<dim3(D_MODEL / 128, M_ROWS / 128, 4), blk256>>>(
            y, opw, part, M_ROWS, D_MODEL, D_INNER);
        if (l + 1 < N_LAYERS) {
            ep_opw<1><<<EP_BLOCKS, blk256>>>(part,
                blk_ng + (size_t)(l + 1) * D_MODEL,
                blk_nb + (size_t)(l + 1) * D_MODEL, hs, lt);
        } else {
            ep_opw<0><<<EP_BLOCKS, blk256>>>(part, nullptr, nullptr, hs, lt);
        }
    }

    // head
    gemm16<4><<<dim3(D_MODEL / 128, M_ROWS / 128, 4), blk256>>>(
        hs, op_w, part, M_ROWS, D_MODEL, D_MODEL);
    ep_head<<<EP_BLOCKS, blk256>>>(part, op_b, h2, nrm);
    gemm16<4><<<dim3(N_CLS / 128, M_ROWS / 128, 4), blk256>>>(
        h2, cls_w, part, M_ROWS, N_CLS, D_MODEL);
    reduce_k<4,1><<<(M_ROWS * N_CLS / 4 + 255) / 256, blk256>>>(
        part, cls_b, out, M_ROWS * N_CLS, N_CLS);
    loss_kernel<<<1, 1024>>>(nrm, out + (out_size - 1));
}

// round 8
// speedup vs baseline: 4.7234x; 1.0456x over previous
#include <cuda_runtime.h>
#include <cuda_bf16.h>
#include <math.h>

#define BATCH    4
#define SEQ      1024
#define M_ROWS   4096
#define D_MODEL  256
#define D_INNER  512
#define D_STATE  16
#define DT_RANK  16
#define D_CONV   4
#define N_LAYERS 2
#define X_DIM    768
#define N_CLS    128

#define NCHUNK   16
#define CHUNK    64
#define NGROUP   (BATCH * D_INNER)

typedef unsigned int u32;
typedef unsigned short u16;

// ---------------------------------------------------------------------------
// Scratch (fp32)
// ---------------------------------------------------------------------------
__device__ float g_hl  [M_ROWS * D_MODEL];     // residual stream hs
__device__ float g_xz  [M_ROWS * 2 * D_INNER];
__device__ float g_u   [M_ROWS * D_INNER];
__device__ float g_ut  [M_ROWS * D_INNER];
__device__ float g_dltt[M_ROWS * D_INNER];
__device__ float g_yt  [M_ROWS * D_INNER];
__device__ float g_xdbc[M_ROWS * 48];
__device__ float g_norm[M_ROWS];
__device__ float g_part[4 * M_ROWS * D_MODEL];

// bf16 hi/lo operand buffers
__device__ __nv_bfloat16 g_xhi [M_ROWS * X_DIM],   g_xlo [M_ROWS * X_DIM];
__device__ __nv_bfloat16 g_lthi[M_ROWS * D_MODEL], g_ltlo[M_ROWS * D_MODEL];
__device__ __nv_bfloat16 g_yhi [M_ROWS * D_INNER], g_ylo [M_ROWS * D_INNER];
__device__ __nv_bfloat16 g_hshi[M_ROWS * D_MODEL], g_hslo[M_ROWS * D_MODEL];
__device__ __nv_bfloat16 g_h2hi[M_ROWS * D_MODEL], g_h2lo[M_ROWS * D_MODEL];
__device__ __nv_bfloat16 g_wihi[D_MODEL * X_DIM],  g_wilo[D_MODEL * X_DIM];
__device__ __nv_bfloat16 g_wphi[N_LAYERS * 2 * D_INNER * D_MODEL], g_wplo[N_LAYERS * 2 * D_INNER * D_MODEL];
__device__ __nv_bfloat16 g_wohi[N_LAYERS * D_MODEL * D_INNER],     g_wolo[N_LAYERS * D_MODEL * D_INNER];
__device__ __nv_bfloat16 g_wqhi[D_MODEL * D_MODEL], g_wqlo[D_MODEL * D_MODEL];
__device__ __nv_bfloat16 g_wchi[N_CLS * D_MODEL],   g_wclo[N_CLS * D_MODEL];

__device__ __forceinline__ float gelu_f(float v) {
    return 0.5f * v * (1.f + erff(v * 0.70710678118654752f));
}
__device__ __forceinline__ float silu_f(float v) {
    return v / (1.f + __expf(-v));
}
__device__ __forceinline__ u32 s2u(const void* p) {
    u32 a;
    asm("{ .reg .u64 t; cvta.to.shared.u64 t, %1; cvt.u32.u64 %0, t; }" : "=r"(a) : "l"(p));
    return a;
}

// ---------------------------------------------------------------------------
// Warp-MMA primitives (non-'a' ISA: sm_80+, works on sm_103 base target)
// ---------------------------------------------------------------------------
#define LDSM4(r, addr) \
    asm volatile("ldmatrix.sync.aligned.m8n8.x4.shared.b16 {%0,%1,%2,%3}, [%4];" \
        : "=r"((r)[0]), "=r"((r)[1]), "=r"((r)[2]), "=r"((r)[3]) : "r"(addr))

#define MMA16816(c, a, b0, b1) \
    asm volatile("mma.sync.aligned.m16n8k16.row.col.f32.bf16.bf16.f32 " \
        "{%0,%1,%2,%3}, {%4,%5,%6,%7}, {%8,%9}, {%0,%1,%2,%3};" \
        : "+f"((c)[0]), "+f"((c)[1]), "+f"((c)[2]), "+f"((c)[3]) \
        : "r"((a)[0]), "r"((a)[1]), "r"((a)[2]), "r"((a)[3]), "r"(b0), "r"(b1))

#define CPA(s, g)  asm volatile("cp.async.cg.shared.global [%0], [%1], 16;" :: "r"(s), "l"(g))
#define CPC()      asm volatile("cp.async.commit_group;" ::: "memory")
#define CPW0()     asm volatile("cp.async.wait_group 0;" ::: "memory")
#define CPW1()     asm volatile("cp.async.wait_group 1;" ::: "memory")

// smem tensor block: 128 rows x 40 u16 (80B pitch, conflict-free ldmatrix)
#define TPITCH 40
#define TBLK   (128 * TPITCH)                 // u16 units per tensor
#define MM_SMEM (2 * 4 * TBLK * 2)            // bytes: 2 bufs x 4 tensors

// ---------------------------------------------------------------------------
// Split-bf16 tensor-core GEMM: C[M,N] = A[M,K] @ W[N,K]^T, fp32-accurate via
// hi*hi + hi*lo + lo*hi. 128x128 tile, BK=32, cp.async double-buffered.
// Requires M%128==0, N%128==0, K%32==0.
// ---------------------------------------------------------------------------
__global__ __launch_bounds__(256) void mma_gemm(
    const __nv_bfloat16* __restrict__ Ahi, const __nv_bfloat16* __restrict__ Alo,
    const __nv_bfloat16* __restrict__ Bhi, const __nv_bfloat16* __restrict__ Blo,
    float* __restrict__ C, int M, int N, int K)
{
    extern __shared__ u16 sm[];
    const int tid  = threadIdx.x;
    const int wid  = tid >> 5;
    const int lane = tid & 31;
    const int m0 = blockIdx.y * 128, n0 = blockIdx.x * 128;
    const u32 sbase = s2u(sm);

    const __nv_bfloat16* gp[4] = {Ahi + (size_t)m0 * K, Alo + (size_t)m0 * K,
                                  Bhi + (size_t)n0 * K, Blo + (size_t)n0 * K};

    const int wm0 = (wid & 3) * 32;   // warp row offset in tile
    const int wn0 = (wid >> 2) * 64;  // warp col offset in tile

    float acc[2][8][4];
    #pragma unroll
    for (int i = 0; i < 2; i++)
        #pragma unroll
        for (int j = 0; j < 8; j++)
            #pragma unroll
            for (int q = 0; q < 4; q++) acc[i][j][q] = 0.f;

    const int nch = K / 32;

    // prologue: chunk 0 -> buf 0
    #pragma unroll
    for (int i = 0; i < 8; i++) {
        int idx = tid + i * 256;
        int tno = idx >> 9, unit = idx & 511;
        int row = unit >> 2, u = unit & 3;
        u32 s = sbase + (u32)((tno * TBLK + row * TPITCH + u * 8) * 2);
        CPA(s, (const void*)(gp[tno] + (size_t)row * K + u * 8));
    }
    CPC();

    for (int c = 0; c < nch; c++) {
        const int b = c & 1;
        if (c + 1 < nch) {
            const int k0 = (c + 1) * 32;
            const u32 bb = (u32)((b ^ 1) * 4 * TBLK * 2);
            #pragma unroll
            for (int i = 0; i < 8; i++) {
                int idx = tid + i * 256;
                int tno = idx >> 9, unit = idx & 511;
                int row = unit >> 2, u = unit & 3;
                u32 s = sbase + bb + (u32)((tno * TBLK + row * TPITCH + u * 8) * 2);
                CPA(s, (const void*)(gp[tno] + (size_t)row * K + k0 + u * 8));
            }
            CPC();
            CPW1();
        } else {
            CPW0();
        }
        __syncthreads();

        const u32 base = sbase + (u32)(b * 4 * TBLK * 2);
        #pragma unroll
        for (int kk = 0; kk < 32; kk += 16) {
            u32 ah[2][4], al[2][4];
            const int id = lane >> 3;
            #pragma unroll
            for (int mt = 0; mt < 2; mt++) {
                int lrow = wm0 + mt * 16 + ((id & 1) << 3) + (lane & 7);
                int lcol = kk + ((id >> 1) << 3);
                u32 off = (u32)((lrow * TPITCH + lcol) * 2);
                LDSM4(ah[mt], base + off);
                LDSM4(al[mt], base + (u32)(TBLK * 2) + off);
            }
            u32 bh[4][4], bl[4][4];
            #pragma unroll
            for (int p = 0; p < 4; p++) {
                int brow = wn0 + (2 * p + (id >> 1)) * 8 + (lane & 7);
                int bcol = kk + ((id & 1) << 3);
                u32 off = (u32)((brow * TPITCH + bcol) * 2);
                LDSM4(bh[p], base + (u32)(2 * TBLK * 2) + off);
                LDSM4(bl[p], base + (u32)(3 * TBLK * 2) + off);
            }
            #pragma unroll
            for (int mt = 0; mt < 2; mt++)
                #pragma unroll
                for (int nt = 0; nt < 8; nt++) {
                    const int p = nt >> 1, o = (nt & 1) * 2;
                    MMA16816(acc[mt][nt], ah[mt], bh[p][o], bh[p][o + 1]);
                    MMA16816(acc[mt][nt], ah[mt], bl[p][o], bl[p][o + 1]);
                    MMA16816(acc[mt][nt], al[mt], bh[p][o], bh[p][o + 1]);
                }
        }
        __syncthreads();
    }

    // store C fragments
    #pragma unroll
    for (int mt = 0; mt < 2; mt++) {
        const int row = m0 + wm0 + mt * 16 + (lane >> 2);
        #pragma unroll
        for (int nt = 0; nt < 8; nt++) {
            const int col = n0 + wn0 + nt * 8 + (lane & 3) * 2;
            *(float2*)(C + (size_t)row * N + col) =
                make_float2(acc[mt][nt][0], acc[mt][nt][1]);
            *(float2*)(C + (size_t)(row + 8) * N + col) =
                make_float2(acc[mt][nt][2], acc[mt][nt][3]);
        }
    }
}

// ---------------------------------------------------------------------------
// fp32 -> (bf16 hi, bf16 lo)
// ---------------------------------------------------------------------------
__device__ __forceinline__ void bf16_hilo4(const float4& v,
                                           __nv_bfloat16* hi, __nv_bfloat16* lo)
{
    __nv_bfloat16 h0 = __float2bfloat16(v.x), h1 = __float2bfloat16(v.y);
    __nv_bfloat16 h2 = __float2bfloat16(v.z), h3 = __float2bfloat16(v.w);
    hi[0] = h0; hi[1] = h1; hi[2] = h2; hi[3] = h3;
    lo[0] = __float2bfloat16(v.x - __bfloat162float(h0));
    lo[1] = __float2bfloat16(v.y - __bfloat162float(h1));
    lo[2] = __float2bfloat16(v.z - __bfloat162float(h2));
    lo[3] = __float2bfloat16(v.w - __bfloat162float(h3));
}

__global__ void cvt_hilo(const float* __restrict__ x, __nv_bfloat16* __restrict__ hi,
                         __nv_bfloat16* __restrict__ lo, int n)
{
    int i = (blockIdx.x * blockDim.x + threadIdx.x) * 4;
    if (i >= n) return;
    float4 v = *(const float4*)(x + i);
    bf16_hilo4(v, hi + i, lo + i);
}

// ---------------------------------------------------------------------------
// xpw GEMM (N=48) FFMA split-K
// ---------------------------------------------------------------------------
__global__ __launch_bounds__(256) void gemm_xpw(
    const float* __restrict__ A, const float* __restrict__ W,
    float* __restrict__ Cp, int M, int N, int K, int splitK)
{
    __shared__ float As[16][132];
    __shared__ float Ws[16][68];
    const int tid = threadIdx.x;
    const int m0 = blockIdx.y * 128;
    const int Kc = K / splitK;
    const int kbeg = blockIdx.z * Kc;
    const int tm = tid >> 4;
    const int tn = tid & 15;
    const int lr = tid >> 2;
    const int lc = (tid & 3) * 4;

    float acc[8][4] = {};

    for (int k0 = kbeg; k0 < kbeg + Kc; k0 += 16) {
        #pragma unroll
        for (int i = 0; i < 2; i++) {
            int r = lr + i * 64;
            float4 v = *(const float4*)(A + (size_t)(m0 + r) * K + k0 + lc);
            As[lc + 0][r] = v.x; As[lc + 1][r] = v.y;
            As[lc + 2][r] = v.z; As[lc + 3][r] = v.w;
        }
        {
            float4 v = make_float4(0.f, 0.f, 0.f, 0.f);
            if (lr < N)
                v = *(const float4*)(W + (size_t)lr * K + k0 + lc);
            Ws[lc + 0][lr] = v.x; Ws[lc + 1][lr] = v.y;
            Ws[lc + 2][lr] = v.z; Ws[lc + 3][lr] = v.w;
        }
        __syncthreads();
        #pragma unroll
        for (int kk = 0; kk < 16; kk++) {
            float a[8], b[4];
            *(float4*)&a[0] = *(const float4*)&As[kk][tm * 8];
            *(float4*)&a[4] = *(const float4*)&As[kk][tm * 8 + 4];
            *(float4*)&b[0] = *(const float4*)&Ws[kk][tn * 4];
            #pragma unroll
            for (int i = 0; i < 8; i++)
                #pragma unroll
                for (int j = 0; j < 4; j++)
                    acc[i][j] = fmaf(a[i], b[j], acc[i][j]);
        }
        __syncthreads();
    }

    const int n = tn * 4;
    if (n >= N) return;
    float* Cout = Cp + (size_t)blockIdx.z * M * N;
    #pragma unroll
    for (int i = 0; i < 8; i++) {
        int m = m0 + tm * 8 + i;
        float4 v = {acc[i][0], acc[i][1], acc[i][2], acc[i][3]};
        *(float4*)(Cout + (size_t)m * N + n) = v;
    }
}

template<int S, int BIAS>
__global__ void reduce_k(const float* __restrict__ part, const float* __restrict__ bias,
                         float* __restrict__ out, int MN, int N)
{
    int i4 = (blockIdx.x * blockDim.x + threadIdx.x) * 4;
    if (i4 >= MN) return;
    float4 v = *(const float4*)(part + i4);
    #pragma unroll
    for (int s = 1; s < S; s++) {
        float4 p = *(const float4*)(part + (size_t)s * MN + i4);
        v.x += p.x; v.y += p.y; v.z += p.z; v.w += p.w;
    }
    if (BIAS) {
        float4 bv = *(const float4*)(bias + (i4 % N));
        v.x += bv.x; v.y += bv.y; v.z += bv.z; v.w += bv.w;
    }
    *(float4*)(out + i4) = v;
}

// ---------------------------------------------------------------------------
// Warp-per-row epilogues
// ---------------------------------------------------------------------------
__device__ __forceinline__ void warp_stats(const float4& v0, const float4& v1,
                                           float& mu, float& rstd)
{
    float s1 = v0.x + v0.y + v0.z + v0.w + v1.x + v1.y + v1.z + v1.w;
    float s2 = v0.x*v0.x + v0.y*v0.y + v0.z*v0.z + v0.w*v0.w
             + v1.x*v1.x + v1.y*v1.y + v1.z*v1.z + v1.w*v1.w;
    #pragma unroll
    for (int o = 16; o > 0; o >>= 1) {
        s1 += __shfl_xor_sync(0xffffffffu, s1, o);
        s2 += __shfl_xor_sync(0xffffffffu, s2, o);
    }
    mu = s1 * (1.f / 256.f);
    rstd = rsqrtf(s2 * (1.f / 256.f) - mu * mu + 1e-5f);
}
__device__ __forceinline__ float4 ln_apply4(const float4& v, float mu, float rstd,
                                            const float4& g, const float4& b)
{
    float4 o;
    o.x = (v.x - mu) * rstd * g.x + b.x;
    o.y = (v.y - mu) * rstd * g.y + b.y;
    o.z = (v.z - mu) * rstd * g.z + b.z;
    o.w = (v.w - mu) * rstd * g.w + b.w;
    return o;
}
__device__ __forceinline__ float4 gelu4(float4 v) {
    v.x = gelu_f(v.x); v.y = gelu_f(v.y); v.z = gelu_f(v.z); v.w = gelu_f(v.w);
    return v;
}

__global__ void ep_inproj(const float* __restrict__ C, const float* __restrict__ bias,
                          const float* __restrict__ lng, const float* __restrict__ lnb,
                          const float* __restrict__ ng0, const float* __restrict__ nb0,
                          float* __restrict__ hs,
                          __nv_bfloat16* __restrict__ lthi, __nv_bfloat16* __restrict__ ltlo)
{
    const int gi = blockIdx.x * blockDim.x + threadIdx.x;
    const int row = gi >> 5;
    const int lane = gi & 31;
    const int c0 = lane * 4, c1 = 128 + lane * 4;
    const size_t i0 = (size_t)row * D_MODEL + c0;
    const size_t i1 = (size_t)row * D_MODEL + c1;
    float4 v0 = *(const float4*)(C + i0);
    float4 v1 = *(const float4*)(C + i1);
    float4 b0 = *(const float4*)(bias + c0), b1 = *(const float4*)(bias + c1);
    v0.x += b0.x; v0.y += b0.y; v0.z += b0.z; v0.w += b0.w;
    v1.x += b1.x; v1.y += b1.y; v1.z += b1.z; v1.w += b1.w;
    float mu, rstd;
    warp_stats(v0, v1, mu, rstd);
    float4 g0 = *(const float4*)(lng + c0), g1 = *(const float4*)(lng + c1);
    float4 bb0 = *(const float4*)(lnb + c0), bb1 = *(const float4*)(lnb + c1);
    float4 w0 = gelu4(ln_apply4(v0, mu, rstd, g0, bb0));
    float4 w1 = gelu4(ln_apply4(v1, mu, rstd, g1, bb1));
    *(float4*)(hs + i0) = w0;
    *(float4*)(hs + i1) = w1;
    warp_stats(w0, w1, mu, rstd);
    g0 = *(const float4*)(ng0 + c0); g1 = *(const float4*)(ng0 + c1);
    bb0 = *(const float4*)(nb0 + c0); bb1 = *(const float4*)(nb0 + c1);
    float4 t0 = ln_apply4(w0, mu, rstd, g0, bb0);
    float4 t1 = ln_apply4(w1, mu, rstd, g1, bb1);
    bf16_hilo4(t0, lthi + i0, ltlo + i0);
    bf16_hilo4(t1, lthi + i1, ltlo + i1);
}

template<int LN>
__global__ void ep_opw(const float* __restrict__ C, const float* __restrict__ ng,
                       const float* __restrict__ nb, float* __restrict__ hs,
                       __nv_bfloat16* __restrict__ ohi, __nv_bfloat16* __restrict__ olo)
{
    const int gi = blockIdx.x * blockDim.x + threadIdx.x;
    const int row = gi >> 5;
    const int lane = gi & 31;
    const int c0 = lane * 4, c1 = 128 + lane * 4;
    const size_t i0 = (size_t)row * D_MODEL + c0;
    const size_t i1 = (size_t)row * D_MODEL + c1;
    float4 v0 = *(const float4*)(hs + i0);
    float4 v1 = *(const float4*)(hs + i1);
    float4 p0 = *(const float4*)(C + i0);
    float4 p1 = *(const float4*)(C + i1);
    v0.x += p0.x; v0.y += p0.y; v0.z += p0.z; v0.w += p0.w;
    v1.x += p1.x; v1.y += p1.y; v1.z += p1.z; v1.w += p1.w;
    *(float4*)(hs + i0) = v0;
    *(float4*)(hs + i1) = v1;
    if (LN) {
        float mu, rstd;
        warp_stats(v0, v1, mu, rstd);
        float4 g0 = *(const float4*)(ng + c0), g1 = *(const float4*)(ng + c1);
        float4 b0 = *(const float4*)(nb + c0), b1 = *(const float4*)(nb + c1);
        float4 t0 = ln_apply4(v0, mu, rstd, g0, b0);
        float4 t1 = ln_apply4(v1, mu, rstd, g1, b1);
        bf16_hilo4(t0, ohi + i0, olo + i0);
        bf16_hilo4(t1, ohi + i1, olo + i1);
    } else {
        bf16_hilo4(v0, ohi + i0, olo + i0);
        bf16_hilo4(v1, ohi + i1, olo + i1);
    }
}

__global__ void ep_head(const float* __restrict__ C, const float* __restrict__ bias,
                        __nv_bfloat16* __restrict__ h2hi, __nv_bfloat16* __restrict__ h2lo,
                        float* __restrict__ nrm)
{
    const int gi = blockIdx.x * blockDim.x + threadIdx.x;
    const int row = gi >> 5;
    const int lane = gi & 31;
    const int c0 = lane * 4, c1 = 128 + lane * 4;
    const size_t i0 = (size_t)row * D_MODEL + c0;
    const size_t i1 = (size_t)row * D_MODEL + c1;
    float4 v0 = *(const float4*)(C + i0);
    float4 v1 = *(const float4*)(C + i1);
    float4 b0 = *(const float4*)(bias + c0), b1 = *(const float4*)(bias + c1);
    v0.x += b0.x; v0.y += b0.y; v0.z += b0.z; v0.w += b0.w;
    v1.x += b1.x; v1.y += b1.y; v1.z += b1.z; v1.w += b1.w;
    v0 = gelu4(v0); v1 = gelu4(v1);
    bf16_hilo4(v0, h2hi + i0, h2lo + i0);
    bf16_hilo4(v1, h2hi + i1, h2lo + i1);
    float s = v0.x*v0.x + v0.y*v0.y + v0.z*v0.z + v0.w*v0.w
            + v1.x*v1.x + v1.y*v1.y + v1.z*v1.z + v1.w*v1.w;
    #pragma unroll
    for (int o = 16; o > 0; o >>= 1) s += __shfl_xor_sync(0xffffffffu, s, o);
    if (lane == 0) nrm[row] = sqrtf(s);
}

// ---------------------------------------------------------------------------
// Depthwise causal conv (k=4) + SiLU -> u and ut
// ---------------------------------------------------------------------------
__global__ void conv2_kernel(const float* __restrict__ xz, const float* __restrict__ cw,
                             const float* __restrict__ cb, float* __restrict__ u,
                             float* __restrict__ ut)
{
    __shared__ float tile[32][33];
    const int b = blockIdx.z;
    const int t0 = blockIdx.x * 32, d0 = blockIdx.y * 32;
    const int tx = threadIdx.x, ty = threadIdx.y;
    const int d = d0 + tx;
    const float w0 = cw[d * 4 + 0], w1 = cw[d * 4 + 1];
    const float w2 = cw[d * 4 + 2], w3 = cw[d * 4 + 3];
    const float bb = cb[d];
    #pragma unroll
    for (int i = 0; i < 4; i++) {
        const int t = t0 + ty + i * 8;
        const size_t rbase = (size_t)(b * SEQ + t) * (2 * D_INNER) + d;
        float acc = bb;
        if (t >= 3) {
            acc = fmaf(w0, xz[rbase - 3 * 2 * D_INNER], acc);
            acc = fmaf(w1, xz[rbase - 2 * 2 * D_INNER], acc);
            acc = fmaf(w2, xz[rbase - 1 * 2 * D_INNER], acc);
        } else {
            if (t >= 2) acc = fmaf(w1, xz[rbase - 2 * 2 * D_INNER], acc);
            if (t >= 1) acc = fmaf(w2, xz[rbase - 1 * 2 * D_INNER], acc);
        }
        acc = fmaf(w3, xz[rbase], acc);
        acc = silu_f(acc);
        u[(size_t)(b * SEQ + t) * D_INNER + d] = acc;
        tile[ty + i * 8][tx] = acc;
    }
    __syncthreads();
    #pragma unroll
    for (int i = 0; i < 4; i++) {
        const int dd = d0 + ty + i * 8;
        ut[(size_t)(b * D_INNER + dd) * SEQ + t0 + tx] = tile[tx][ty + i * 8];
    }
}

// ---------------------------------------------------------------------------
// delta = softplus(dt @ dtw^T + dtb) -> dltt
// ---------------------------------------------------------------------------
__global__ void deltaT_kernel(const float* __restrict__ xdbc, const float* __restrict__ dtw,
                              const float* __restrict__ dtb, float* __restrict__ dltt)
{
    __shared__ float w_s[32][17];
    __shared__ float b_s[32];
    __shared__ float tile[32][33];
    const int b = blockIdx.z;
    const int t0 = blockIdx.x * 32, d0 = blockIdx.y * 32;
    const int tx = threadIdx.x, ty = threadIdx.y;
    const int tid = ty * 32 + tx;
    {
        int r = tid >> 4, c = tid & 15;
        w_s[r][c] = dtw[(d0 + r) * DT_RANK + c];
        w_s[r + 16][c] = dtw[(d0 + r + 16) * DT_RANK + c];
        if (tid < 32) b_s[tid] = dtb[d0 + tid];
    }
    __syncthreads();
    #pragma unroll
    for (int i = 0; i < 4; i++) {
        const int t = t0 + ty + i * 8;
        const float* xr = xdbc + (size_t)(b * SEQ + t) * 48;
        float acc = b_s[tx];
        #pragma unroll
        for (int r = 0; r < DT_RANK; r++)
            acc = fmaf(__ldg(xr + r), w_s[tx][r], acc);
        tile[ty + i * 8][tx] = (acc > 20.f) ? acc : log1pf(__expf(acc));
    }
    __syncthreads();
    #pragma unroll
    for (int i = 0; i < 4; i++) {
        const int dd = d0 + ty + i * 8;
        dltt[(size_t)(b * D_INNER + dd) * SEQ + t0 + tx] = tile[tx][ty + i * 8];
    }
}

// ---------------------------------------------------------------------------
// Fused chunked selective scan
// ---------------------------------------------------------------------------
__global__ __launch_bounds__(256) void scan_fused(
    const float* __restrict__ dltt, const float* __restrict__ ut,
    const float* __restrict__ xdbc, const float* __restrict__ A_log,
    const float* __restrict__ Dp, float* __restrict__ yt)
{
    __shared__ float Ps[NCHUNK][D_STATE];
    __shared__ float Qs[NCHUNK][D_STATE];
    __shared__ float Ts[NCHUNK][D_STATE];
    const int tid = threadIdx.x;
    const int g = blockIdx.x;
    const int c = tid >> 4;
    const int n = tid & 15;
    const int b = g >> 9;
    const int d = g & (D_INNER - 1);
    const float A  = -__expf(A_log[d * D_STATE + n]);
    const float Dd = Dp[d];
    const size_t base = (size_t)g * SEQ + c * CHUNK;
    const float* xb = xdbc + ((size_t)b * SEQ + c * CHUNK) * 48 + DT_RANK;

    float dt[16], uu[16];
    {
        float s = 0.f, sumd = 0.f;
        for (int tc = 0; tc < CHUNK; tc += 16) {
            #pragma unroll
            for (int q = 0; q < 4; q++) {
                float4 v = ((const float4*)(dltt + base + tc))[q];
                dt[q*4+0] = v.x; dt[q*4+1] = v.y; dt[q*4+2] = v.z; dt[q*4+3] = v.w;
                float4 w = ((const float4*)(ut + base + tc))[q];
                uu[q*4+0] = w.x; uu[q*4+1] = w.y; uu[q*4+2] = w.z; uu[q*4+3] = w.w;
            }
            #pragma unroll
            for (int j = 0; j < 16; j++) {
                const float Bn = __ldg(xb + (size_t)(tc + j) * 48 + n);
                s = fmaf(s, __expf(dt[j] * A), dt[j] * uu[j] * Bn);
                sumd += dt[j];
            }
        }
        Qs[c][n] = s;
        Ps[c][n] = __expf(A * sumd);
    }
    __syncthreads();

    if (tid < D_STATE) {
        float t = 0.f;
        Ts[0][tid] = 0.f;
        #pragma unroll
        for (int cc = 1; cc < NCHUNK; cc++) {
            t = fmaf(Ps[cc - 1][tid], t, Qs[cc - 1][tid]);
            Ts[cc][tid] = t;
        }
    }
    __syncthreads();

    {
        float s = Ts[c][n];
        for (int tc = 0; tc < CHUNK; tc += 16) {
            #pragma unroll
            for (int q = 0; q < 4; q++) {
                float4 v = ((const float4*)(dltt + base + tc))[q];
                dt[q*4+0] = v.x; dt[q*4+1] = v.y; dt[q*4+2] = v.z; dt[q*4+3] = v.w;
                float4 w = ((const float4*)(ut + base + tc))[q];
                uu[q*4+0] = w.x; uu[q*4+1] = w.y; uu[q*4+2] = w.z; uu[q*4+3] = w.w;
            }
            float rv = 0.f;
            #pragma unroll
            for (int j = 0; j < 16; j++) {
                const float* xr = xb + (size_t)(tc + j) * 48;
                const float Bn = __ldg(xr + n);
                const float Cn = __ldg(xr + D_STATE + n);
                s = fmaf(s, __expf(dt[j] * A), dt[j] * uu[j] * Bn);
                float v = s * Cn;
                #pragma unroll
                for (int o = 8; o > 0; o >>= 1) v += __shfl_xor_sync(0xffffffffu, v, o);
                if (n == j) rv = v + uu[j] * Dd;
            }
            yt[base + tc + n] = rv;
        }
    }
}

// ---------------------------------------------------------------------------
// Gate + transpose -> y hi/lo
// ---------------------------------------------------------------------------
__global__ void gate_kernel(const float* __restrict__ yt, const float* __restrict__ xz,
                            __nv_bfloat16* __restrict__ yhi, __nv_bfloat16* __restrict__ ylo)
{
    __shared__ float t0s[32][33];
    const int b = blockIdx.z;
    const int tblk = blockIdx.x * 32, dblk = blockIdx.y * 32;
    const int tx = threadIdx.x, ty = threadIdx.y;
    #pragma unroll
    for (int i = 0; i < 4; i++) {
        int d = dblk + ty + i * 8;
        t0s[ty + i * 8][tx] = yt[(size_t)(b * D_INNER + d) * SEQ + tblk + tx];
    }
    __syncthreads();
    #pragma unroll
    for (int i = 0; i < 4; i++) {
        int t = tblk + ty + i * 8;
        size_t row = (size_t)(b * SEQ + t);
        float z = xz[row * (2 * D_INNER) + D_INNER + dblk + tx];
        float v = t0s[tx][ty + i * 8] * silu_f(z);
        __nv_bfloat16 h = __float2bfloat16(v);
        size_t idx = row * D_INNER + dblk + tx;
        yhi[idx] = h;
        ylo[idx] = __float2bfloat16(v - __bfloat162float(h));
    }
}

__global__ void loss_kernel(const float* __restrict__ nrm, float* __restrict__ out)
{
    const int tid = threadIdx.x;
    float s = 0.f;
    #pragma unroll
    for (int i = 0; i < 4; i++) s += nrm[tid + i * 1024];
    #pragma unroll
    for (int o = 16; o > 0; o >>= 1) s += __shfl_xor_sync(0xffffffffu, s, o);
    __shared__ float sm[32];
    if ((tid & 31) == 0) sm[tid >> 5] = s;
    __syncthreads();
    if (tid == 0) {
        float t = 0.f;
        #pragma unroll
        for (int i = 0; i < 32; i++) t += sm[i];
        *out = 0.01f * t * (1.f / (float)M_ROWS);
    }
}

// ---------------------------------------------------------------------------
// Launch
// ---------------------------------------------------------------------------
extern "C" void kernel_launch(void* const* d_in, const int* in_sizes, int n_in,
                              void* d_out, int out_size)
{
    const float* x      = (const float*)d_in[0];
    const float* in_w   = (const float*)d_in[1];
    const float* in_b   = (const float*)d_in[2];
    const float* ln_g   = (const float*)d_in[3];
    const float* ln_b   = (const float*)d_in[4];
    const float* blk_ng = (const float*)d_in[5];
    const float* blk_nb = (const float*)d_in[6];
    const float* blk_ipw= (const float*)d_in[7];
    const float* blk_cw = (const float*)d_in[8];
    const float* blk_cb = (const float*)d_in[9];
    const float* blk_xpw= (const float*)d_in[10];
    const float* blk_dtw= (const float*)d_in[11];
    const float* blk_dtb= (const float*)d_in[12];
    const float* blk_Al = (const float*)d_in[13];
    const float* blk_D  = (const float*)d_in[14];
    const float* blk_opw= (const float*)d_in[15];
    const float* op_w   = (const float*)d_in[16];
    const float* op_b   = (const float*)d_in[17];
    const float* cls_w  = (const float*)d_in[18];
    const float* cls_b  = (const float*)d_in[19];
    float* out = (float*)d_out;

    float *hs, *xz, *u, *ut, *dltt, *yt, *xdbc, *nrm, *part;
    __nv_bfloat16 *xhi, *xlo, *lthi, *ltlo, *yhi, *ylo, *hshi, *hslo, *h2hi, *h2lo;
    __nv_bfloat16 *wihi, *wilo, *wphi, *wplo, *wohi, *wolo, *wqhi, *wqlo, *wchi, *wclo;
    cudaGetSymbolAddress((void**)&hs,   g_hl);
    cudaGetSymbolAddress((void**)&xz,   g_xz);
    cudaGetSymbolAddress((void**)&u,    g_u);
    cudaGetSymbolAddress((void**)&ut,   g_ut);
    cudaGetSymbolAddress((void**)&dltt, g_dltt);
    cudaGetSymbolAddress((void**)&yt,   g_yt);
    cudaGetSymbolAddress((void**)&xdbc, g_xdbc);
    cudaGetSymbolAddress((void**)&nrm,  g_norm);
    cudaGetSymbolAddress((void**)&part, g_part);
    cudaGetSymbolAddress((void**)&xhi,  g_xhi);  cudaGetSymbolAddress((void**)&xlo,  g_xlo);
    cudaGetSymbolAddress((void**)&lthi, g_lthi); cudaGetSymbolAddress((void**)&ltlo, g_ltlo);
    cudaGetSymbolAddress((void**)&yhi,  g_yhi);  cudaGetSymbolAddress((void**)&ylo,  g_ylo);
    cudaGetSymbolAddress((void**)&hshi, g_hshi); cudaGetSymbolAddress((void**)&hslo, g_hslo);
    cudaGetSymbolAddress((void**)&h2hi, g_h2hi); cudaGetSymbolAddress((void**)&h2lo, g_h2lo);
    cudaGetSymbolAddress((void**)&wihi, g_wihi); cudaGetSymbolAddress((void**)&wilo, g_wilo);
    cudaGetSymbolAddress((void**)&wphi, g_wphi); cudaGetSymbolAddress((void**)&wplo, g_wplo);
    cudaGetSymbolAddress((void**)&wohi, g_wohi); cudaGetSymbolAddress((void**)&wolo, g_wolo);
    cudaGetSymbolAddress((void**)&wqhi, g_wqhi); cudaGetSymbolAddress((void**)&wqlo, g_wqlo);
    cudaGetSymbolAddress((void**)&wchi, g_wchi); cudaGetSymbolAddress((void**)&wclo, g_wclo);

    cudaFuncSetAttribute(mma_gemm, cudaFuncAttributeMaxDynamicSharedMemorySize, MM_SMEM);

    dim3 blk256(256);
    dim3 tblk(32, 8);
    dim3 tgrid(SEQ / 32, D_INNER / 32, BATCH);
    const int EP_BLOCKS = M_ROWS * 32 / 256;

    // hi/lo conversions (x + all weights)
    cvt_hilo<<<(M_ROWS * X_DIM) / 1024, blk256>>>(x, xhi, xlo, M_ROWS * X_DIM);
    cvt_hilo<<<(D_MODEL * X_DIM) / 1024, blk256>>>(in_w, wihi, wilo, D_MODEL * X_DIM);
    cvt_hilo<<<(N_LAYERS * 2 * D_INNER * D_MODEL) / 1024, blk256>>>(
        blk_ipw, wphi, wplo, N_LAYERS * 2 * D_INNER * D_MODEL);
    cvt_hilo<<<(N_LAYERS * D_MODEL * D_INNER) / 1024, blk256>>>(
        blk_opw, wohi, wolo, N_LAYERS * D_MODEL * D_INNER);
    cvt_hilo<<<(D_MODEL * D_MODEL) / 1024, blk256>>>(op_w, wqhi, wqlo, D_MODEL * D_MODEL);
    cvt_hilo<<<(N_CLS * D_MODEL) / 1024, blk256>>>(cls_w, wchi, wclo, N_CLS * D_MODEL);

    // in-proj GEMM + fused epilogue
    mma_gemm<<<dim3(D_MODEL / 128, M_ROWS / 128), blk256, MM_SMEM>>>(
        xhi, xlo, wihi, wilo, part, M_ROWS, D_MODEL, X_DIM);
    ep_inproj<<<EP_BLOCKS, blk256>>>(part, in_b, ln_g, ln_b,
                                     blk_ng, blk_nb, hs, lthi, ltlo);

    for (int l = 0; l < N_LAYERS; l++) {
        const __nv_bfloat16* pwh = wphi + (size_t)l * 2 * D_INNER * D_MODEL;
        const __nv_bfloat16* pwl = wplo + (size_t)l * 2 * D_INNER * D_MODEL;
        const __nv_bfloat16* owh = wohi + (size_t)l * D_MODEL * D_INNER;
        const __nv_bfloat16* owl = wolo + (size_t)l * D_MODEL * D_INNER;
        const float* cw  = blk_cw  + (size_t)l * D_INNER * D_CONV;
        const float* cb  = blk_cb  + (size_t)l * D_INNER;
        const float* xpw = blk_xpw + (size_t)l * 48 * D_INNER;
        const float* dtw = blk_dtw + (size_t)l * D_INNER * DT_RANK;
        const float* dtb = blk_dtb + (size_t)l * D_INNER;
        const float* Al  = blk_Al  + (size_t)l * D_INNER * D_STATE;
        const float* Dp  = blk_D   + (size_t)l * D_INNER;

        mma_gemm<<<dim3(2 * D_INNER / 128, M_ROWS / 128), blk256, MM_SMEM>>>(
            lthi, ltlo, pwh, pwl, xz, M_ROWS, 2 * D_INNER, D_MODEL);
        conv2_kernel<<<tgrid, tblk>>>(xz, cw, cb, u, ut);
        gemm_xpw<<<dim3(1, M_ROWS / 128, 4), blk256>>>(
            u, xpw, part, M_ROWS, 48, D_INNER, 4);
        reduce_k<4,0><<<(M_ROWS * 48 / 4 + 255) / 256, blk256>>>(
            part, nullptr, xdbc, M_ROWS * 48, 48);
        deltaT_kernel<<<tgrid, tblk>>>(xdbc, dtw, dtb, dltt);
        scan_fused<<<NGROUP, blk256>>>(dltt, ut, xdbc, Al, Dp, yt);
        gate_kernel<<<tgrid, tblk>>>(yt, xz, yhi, ylo);
        mma_gemm<<<dim3(D_MODEL / 128, M_ROWS / 128), blk256, MM_SMEM>>>(
            yhi, ylo, owh, owl, part, M_ROWS, D_MODEL, D_INNER);
        if (l + 1 < N_LAYERS) {
            ep_opw<1><<<EP_BLOCKS, blk256>>>(part,
                blk_ng + (size_t)(l + 1) * D_MODEL,
                blk_nb + (size_t)(l + 1) * D_MODEL, hs, lthi, ltlo);
        } else {
            ep_opw<0><<<EP_BLOCKS, blk256>>>(part, nullptr, nullptr, hs, hshi, hslo);
        }
    }

    // head
    mma_gemm<<<dim3(D_MODEL / 128, M_ROWS / 128), blk256, MM_SMEM>>>(
        hshi, hslo, wqhi, wqlo, part, M_ROWS, D_MODEL, D_MODEL);
    ep_head<<<EP_BLOCKS, blk256>>>(part, op_b, h2hi, h2lo, nrm);
    mma_gemm<<<dim3(N_CLS / 128, M_ROWS / 128), blk256, MM_SMEM>>>(
        h2hi, h2lo, wchi, wclo, part, M_ROWS, N_CLS, D_MODEL);
    reduce_k<1,1><<<(M_ROWS * N_CLS / 4 + 255) / 256, blk256>>>(
        part, cls_b, out, M_ROWS * N_CLS, N_CLS);
    loss_kernel<<<1, 1024>>>(nrm, out + (out_size - 1));
}

// round 9
// speedup vs baseline: 5.4863x; 1.1615x over previous
#include <cuda_runtime.h>
#include <cuda_bf16.h>
#include <math.h>

#define BATCH    4
#define SEQ      1024
#define M_ROWS   4096
#define D_MODEL  256
#define D_INNER  512
#define D_STATE  16
#define DT_RANK  16
#define D_CONV   4
#define N_LAYERS 2
#define X_DIM    768
#define N_CLS    128

#define NCHUNK   16
#define CHUNK    64
#define NGROUP   (BATCH * D_INNER)

typedef unsigned int u32;
typedef unsigned short u16;

// ---------------------------------------------------------------------------
// Scratch (fp32)
// ---------------------------------------------------------------------------
__device__ float g_hl  [M_ROWS * D_MODEL];
__device__ float g_xz  [M_ROWS * 2 * D_INNER];
__device__ float g_u   [M_ROWS * D_INNER];
__device__ float g_ut  [M_ROWS * D_INNER];
__device__ float g_dltt[M_ROWS * D_INNER];
__device__ float g_yt  [M_ROWS * D_INNER];
__device__ float g_xdbc[M_ROWS * 48];
__device__ float g_norm[M_ROWS];
__device__ float g_part[4 * M_ROWS * D_MODEL];

// bf16 hi/lo operand buffers
__device__ __nv_bfloat16 g_xhi [M_ROWS * X_DIM],   g_xlo [M_ROWS * X_DIM];
__device__ __nv_bfloat16 g_lthi[M_ROWS * D_MODEL], g_ltlo[M_ROWS * D_MODEL];
__device__ __nv_bfloat16 g_yhi [M_ROWS * D_INNER], g_ylo [M_ROWS * D_INNER];
__device__ __nv_bfloat16 g_hshi[M_ROWS * D_MODEL], g_hslo[M_ROWS * D_MODEL];
__device__ __nv_bfloat16 g_h2hi[M_ROWS * D_MODEL], g_h2lo[M_ROWS * D_MODEL];
__device__ __nv_bfloat16 g_wihi[D_MODEL * X_DIM],  g_wilo[D_MODEL * X_DIM];
__device__ __nv_bfloat16 g_wphi[N_LAYERS * 2 * D_INNER * D_MODEL], g_wplo[N_LAYERS * 2 * D_INNER * D_MODEL];
__device__ __nv_bfloat16 g_wohi[N_LAYERS * D_MODEL * D_INNER],     g_wolo[N_LAYERS * D_MODEL * D_INNER];
__device__ __nv_bfloat16 g_wqhi[D_MODEL * D_MODEL], g_wqlo[D_MODEL * D_MODEL];
__device__ __nv_bfloat16 g_wchi[N_CLS * D_MODEL],   g_wclo[N_CLS * D_MODEL];

__device__ __forceinline__ float gelu_f(float v) {
    return 0.5f * v * (1.f + erff(v * 0.70710678118654752f));
}
__device__ __forceinline__ float silu_f(float v) {
    return v / (1.f + __expf(-v));
}
__device__ __forceinline__ u32 s2u(const void* p) {
    u32 a;
    asm("{ .reg .u64 t; cvta.to.shared.u64 t, %1; cvt.u32.u64 %0, t; }" : "=r"(a) : "l"(p));
    return a;
}

// ---------------------------------------------------------------------------
// Warp-MMA primitives (non-'a' ISA)
// ---------------------------------------------------------------------------
#define LDSM4(r, addr) \
    asm volatile("ldmatrix.sync.aligned.m8n8.x4.shared.b16 {%0,%1,%2,%3}, [%4];" \
        : "=r"((r)[0]), "=r"((r)[1]), "=r"((r)[2]), "=r"((r)[3]) : "r"(addr))

#define MMA16816(c, a, b0, b1) \
    asm volatile("mma.sync.aligned.m16n8k16.row.col.f32.bf16.bf16.f32 " \
        "{%0,%1,%2,%3}, {%4,%5,%6,%7}, {%8,%9}, {%0,%1,%2,%3};" \
        : "+f"((c)[0]), "+f"((c)[1]), "+f"((c)[2]), "+f"((c)[3]) \
        : "r"((a)[0]), "r"((a)[1]), "r"((a)[2]), "r"((a)[3]), "r"(b0), "r"(b1))

#define CPA(s, g)  asm volatile("cp.async.cg.shared.global [%0], [%1], 16;" :: "r"(s), "l"(g))
#define CPC()      asm volatile("cp.async.commit_group;" ::: "memory")
#define CPW0()     asm volatile("cp.async.wait_group 0;" ::: "memory")
#define CPW1()     asm volatile("cp.async.wait_group 1;" ::: "memory")

#define TPITCH 40
#define TBLK   (128 * TPITCH)
#define MM_SMEM (2 * 4 * TBLK * 2)

// ---------------------------------------------------------------------------
// Split-bf16 tensor-core GEMM: C = A @ W^T via hi*hi + hi*lo + lo*hi.
// 128x128 tile, BK=32, cp.async double-buffered.
// SPLIT>1: blockIdx.z picks K-chunk, raw partial written to C + z*M*N.
// Requires M%128==0, N%128==0, (K/SPLIT)%32==0.
// ---------------------------------------------------------------------------
template<int SPLIT>
__global__ __launch_bounds__(256) void mma_gemm(
    const __nv_bfloat16* __restrict__ Ahi, const __nv_bfloat16* __restrict__ Alo,
    const __nv_bfloat16* __restrict__ Bhi, const __nv_bfloat16* __restrict__ Blo,
    float* __restrict__ C, int M, int N, int K)
{
    extern __shared__ u16 sm[];
    const int tid  = threadIdx.x;
    const int wid  = tid >> 5;
    const int lane = tid & 31;
    const int m0 = blockIdx.y * 128, n0 = blockIdx.x * 128;
    const int Kc = K / SPLIT;
    const int kbeg = blockIdx.z * Kc;
    const u32 sbase = s2u(sm);

    const __nv_bfloat16* gp[4] = {Ahi + (size_t)m0 * K + kbeg, Alo + (size_t)m0 * K + kbeg,
                                  Bhi + (size_t)n0 * K + kbeg, Blo + (size_t)n0 * K + kbeg};

    const int wm0 = (wid & 3) * 32;
    const int wn0 = (wid >> 2) * 64;

    float acc[2][8][4];
    #pragma unroll
    for (int i = 0; i < 2; i++)
        #pragma unroll
        for (int j = 0; j < 8; j++)
            #pragma unroll
            for (int q = 0; q < 4; q++) acc[i][j][q] = 0.f;

    const int nch = Kc / 32;

    #pragma unroll
    for (int i = 0; i < 8; i++) {
        int idx = tid + i * 256;
        int tno = idx >> 9, unit = idx & 511;
        int row = unit >> 2, u = unit & 3;
        u32 s = sbase + (u32)((tno * TBLK + row * TPITCH + u * 8) * 2);
        CPA(s, (const void*)(gp[tno] + (size_t)row * K + u * 8));
    }
    CPC();

    for (int c = 0; c < nch; c++) {
        const int b = c & 1;
        if (c + 1 < nch) {
            const int k0 = (c + 1) * 32;
            const u32 bb = (u32)((b ^ 1) * 4 * TBLK * 2);
            #pragma unroll
            for (int i = 0; i < 8; i++) {
                int idx = tid + i * 256;
                int tno = idx >> 9, unit = idx & 511;
                int row = unit >> 2, u = unit & 3;
                u32 s = sbase + bb + (u32)((tno * TBLK + row * TPITCH + u * 8) * 2);
                CPA(s, (const void*)(gp[tno] + (size_t)row * K + k0 + u * 8));
            }
            CPC();
            CPW1();
        } else {
            CPW0();
        }
        __syncthreads();

        const u32 base = sbase + (u32)(b * 4 * TBLK * 2);
        #pragma unroll
        for (int kk = 0; kk < 32; kk += 16) {
            u32 ah[2][4], al[2][4];
            const int id = lane >> 3;
            #pragma unroll
            for (int mt = 0; mt < 2; mt++) {
                int lrow = wm0 + mt * 16 + ((id & 1) << 3) + (lane & 7);
                int lcol = kk + ((id >> 1) << 3);
                u32 off = (u32)((lrow * TPITCH + lcol) * 2);
                LDSM4(ah[mt], base + off);
                LDSM4(al[mt], base + (u32)(TBLK * 2) + off);
            }
            u32 bh[4][4], bl[4][4];
            #pragma unroll
            for (int p = 0; p < 4; p++) {
                int brow = wn0 + (2 * p + (id >> 1)) * 8 + (lane & 7);
                int bcol = kk + ((id & 1) << 3);
                u32 off = (u32)((brow * TPITCH + bcol) * 2);
                LDSM4(bh[p], base + (u32)(2 * TBLK * 2) + off);
                LDSM4(bl[p], base + (u32)(3 * TBLK * 2) + off);
            }
            #pragma unroll
            for (int mt = 0; mt < 2; mt++)
                #pragma unroll
                for (int nt = 0; nt < 8; nt++) {
                    const int p = nt >> 1, o = (nt & 1) * 2;
                    MMA16816(acc[mt][nt], ah[mt], bh[p][o], bh[p][o + 1]);
                    MMA16816(acc[mt][nt], ah[mt], bl[p][o], bl[p][o + 1]);
                    MMA16816(acc[mt][nt], al[mt], bh[p][o], bh[p][o + 1]);
                }
        }
        __syncthreads();
    }

    float* Cout = (SPLIT > 1) ? (C + (size_t)blockIdx.z * M * N) : C;
    #pragma unroll
    for (int mt = 0; mt < 2; mt++) {
        const int row = m0 + wm0 + mt * 16 + (lane >> 2);
        #pragma unroll
        for (int nt = 0; nt < 8; nt++) {
            const int col = n0 + wn0 + nt * 8 + (lane & 3) * 2;
            *(float2*)(Cout + (size_t)row * N + col) =
                make_float2(acc[mt][nt][0], acc[mt][nt][1]);
            *(float2*)(Cout + (size_t)(row + 8) * N + col) =
                make_float2(acc[mt][nt][2], acc[mt][nt][3]);
        }
    }
}

// ---------------------------------------------------------------------------
// fp32 -> (bf16 hi, bf16 lo)
// ---------------------------------------------------------------------------
__device__ __forceinline__ void bf16_hilo4(const float4& v,
                                           __nv_bfloat16* hi, __nv_bfloat16* lo)
{
    __nv_bfloat16 h0 = __float2bfloat16(v.x), h1 = __float2bfloat16(v.y);
    __nv_bfloat16 h2 = __float2bfloat16(v.z), h3 = __float2bfloat16(v.w);
    hi[0] = h0; hi[1] = h1; hi[2] = h2; hi[3] = h3;
    lo[0] = __float2bfloat16(v.x - __bfloat162float(h0));
    lo[1] = __float2bfloat16(v.y - __bfloat162float(h1));
    lo[2] = __float2bfloat16(v.z - __bfloat162float(h2));
    lo[3] = __float2bfloat16(v.w - __bfloat162float(h3));
}

// Batched conversion of x + 5 weight tensors in ONE launch (grid-stride).
#define CV_N0 (M_ROWS * X_DIM)                         // x: 3145728
#define CV_N1 (D_MODEL * X_DIM)                        // in_w: 196608
#define CV_N2 (N_LAYERS * 2 * D_INNER * D_MODEL)       // ipw: 524288
#define CV_N3 (N_LAYERS * D_MODEL * D_INNER)           // opw: 262144
#define CV_N4 (D_MODEL * D_MODEL)                      // op_w: 65536
#define CV_N5 (N_CLS * D_MODEL)                        // cls_w: 32768
#define CV_TOT (CV_N0 + CV_N1 + CV_N2 + CV_N3 + CV_N4 + CV_N5)

__global__ void cvt_all(const float* __restrict__ s0, const float* __restrict__ s1,
                        const float* __restrict__ s2, const float* __restrict__ s3,
                        const float* __restrict__ s4, const float* __restrict__ s5,
                        __nv_bfloat16* h0, __nv_bfloat16* l0,
                        __nv_bfloat16* h1, __nv_bfloat16* l1,
                        __nv_bfloat16* h2, __nv_bfloat16* l2,
                        __nv_bfloat16* h3, __nv_bfloat16* l3,
                        __nv_bfloat16* h4, __nv_bfloat16* l4,
                        __nv_bfloat16* h5, __nv_bfloat16* l5)
{
    int gi = (blockIdx.x * blockDim.x + threadIdx.x) * 4;
    const int stride = gridDim.x * blockDim.x * 4;
    for (; gi < CV_TOT; gi += stride) {
        const float* src; __nv_bfloat16 *hi, *lo; int off = gi;
        if (off < CV_N0) { src = s0; hi = h0; lo = l0; }
        else if ((off -= CV_N0) < CV_N1) { src = s1; hi = h1; lo = l1; }
        else if ((off -= CV_N1) < CV_N2) { src = s2; hi = h2; lo = l2; }
        else if ((off -= CV_N2) < CV_N3) { src = s3; hi = h3; lo = l3; }
        else if ((off -= CV_N3) < CV_N4) { src = s4; hi = h4; lo = l4; }
        else { off -= CV_N4; src = s5; hi = h5; lo = l5; }
        float4 v = *(const float4*)(src + off);
        bf16_hilo4(v, hi + off, lo + off);
    }
}

// ---------------------------------------------------------------------------
// xpw GEMM (N=48) FFMA split-K
// ---------------------------------------------------------------------------
__global__ __launch_bounds__(256) void gemm_xpw(
    const float* __restrict__ A, const float* __restrict__ W,
    float* __restrict__ Cp, int M, int N, int K, int splitK)
{
    __shared__ float As[16][132];
    __shared__ float Ws[16][68];
    const int tid = threadIdx.x;
    const int m0 = blockIdx.y * 128;
    const int Kc = K / splitK;
    const int kbeg = blockIdx.z * Kc;
    const int tm = tid >> 4;
    const int tn = tid & 15;
    const int lr = tid >> 2;
    const int lc = (tid & 3) * 4;

    float acc[8][4] = {};

    for (int k0 = kbeg; k0 < kbeg + Kc; k0 += 16) {
        #pragma unroll
        for (int i = 0; i < 2; i++) {
            int r = lr + i * 64;
            float4 v = *(const float4*)(A + (size_t)(m0 + r) * K + k0 + lc);
            As[lc + 0][r] = v.x; As[lc + 1][r] = v.y;
            As[lc + 2][r] = v.z; As[lc + 3][r] = v.w;
        }
        {
            float4 v = make_float4(0.f, 0.f, 0.f, 0.f);
            if (lr < N)
                v = *(const float4*)(W + (size_t)lr * K + k0 + lc);
            Ws[lc + 0][lr] = v.x; Ws[lc + 1][lr] = v.y;
            Ws[lc + 2][lr] = v.z; Ws[lc + 3][lr] = v.w;
        }
        __syncthreads();
        #pragma unroll
        for (int kk = 0; kk < 16; kk++) {
            float a[8], b[4];
            *(float4*)&a[0] = *(const float4*)&As[kk][tm * 8];
            *(float4*)&a[4] = *(const float4*)&As[kk][tm * 8 + 4];
            *(float4*)&b[0] = *(const float4*)&Ws[kk][tn * 4];
            #pragma unroll
            for (int i = 0; i < 8; i++)
                #pragma unroll
                for (int j = 0; j < 4; j++)
                    acc[i][j] = fmaf(a[i], b[j], acc[i][j]);
        }
        __syncthreads();
    }

    const int n = tn * 4;
    if (n >= N) return;
    float* Cout = Cp + (size_t)blockIdx.z * M * N;
    #pragma unroll
    for (int i = 0; i < 8; i++) {
        int m = m0 + tm * 8 + i;
        float4 v = {acc[i][0], acc[i][1], acc[i][2], acc[i][3]};
        *(float4*)(Cout + (size_t)m * N + n) = v;
    }
}

template<int S, int BIAS>
__global__ void reduce_k(const float* __restrict__ part, const float* __restrict__ bias,
                         float* __restrict__ out, int MN, int N)
{
    int i4 = (blockIdx.x * blockDim.x + threadIdx.x) * 4;
    if (i4 >= MN) return;
    float4 v = *(const float4*)(part + i4);
    #pragma unroll
    for (int s = 1; s < S; s++) {
        float4 p = *(const float4*)(part + (size_t)s * MN + i4);
        v.x += p.x; v.y += p.y; v.z += p.z; v.w += p.w;
    }
    if (BIAS) {
        float4 bv = *(const float4*)(bias + (i4 % N));
        v.x += bv.x; v.y += bv.y; v.z += bv.z; v.w += bv.w;
    }
    *(float4*)(out + i4) = v;
}

// ---------------------------------------------------------------------------
// Warp-per-row epilogues; all reduce S split-K segments of 'part' inline.
// ---------------------------------------------------------------------------
__device__ __forceinline__ void warp_stats(const float4& v0, const float4& v1,
                                           float& mu, float& rstd)
{
    float s1 = v0.x + v0.y + v0.z + v0.w + v1.x + v1.y + v1.z + v1.w;
    float s2 = v0.x*v0.x + v0.y*v0.y + v0.z*v0.z + v0.w*v0.w
             + v1.x*v1.x + v1.y*v1.y + v1.z*v1.z + v1.w*v1.w;
    #pragma unroll
    for (int o = 16; o > 0; o >>= 1) {
        s1 += __shfl_xor_sync(0xffffffffu, s1, o);
        s2 += __shfl_xor_sync(0xffffffffu, s2, o);
    }
    mu = s1 * (1.f / 256.f);
    rstd = rsqrtf(s2 * (1.f / 256.f) - mu * mu + 1e-5f);
}
__device__ __forceinline__ float4 ln_apply4(const float4& v, float mu, float rstd,
                                            const float4& g, const float4& b)
{
    float4 o;
    o.x = (v.x - mu) * rstd * g.x + b.x;
    o.y = (v.y - mu) * rstd * g.y + b.y;
    o.z = (v.z - mu) * rstd * g.z + b.z;
    o.w = (v.w - mu) * rstd * g.w + b.w;
    return o;
}
__device__ __forceinline__ float4 gelu4(float4 v) {
    v.x = gelu_f(v.x); v.y = gelu_f(v.y); v.z = gelu_f(v.z); v.w = gelu_f(v.w);
    return v;
}
__device__ __forceinline__ void add4(float4& a, const float4& b) {
    a.x += b.x; a.y += b.y; a.z += b.z; a.w += b.w;
}

template<int S>
__global__ void ep_inproj(const float* __restrict__ part, const float* __restrict__ bias,
                          const float* __restrict__ lng, const float* __restrict__ lnb,
                          const float* __restrict__ ng0, const float* __restrict__ nb0,
                          float* __restrict__ hs,
                          __nv_bfloat16* __restrict__ lthi, __nv_bfloat16* __restrict__ ltlo)
{
    const int gi = blockIdx.x * blockDim.x + threadIdx.x;
    const int row = gi >> 5;
    const int lane = gi & 31;
    const int MN = M_ROWS * D_MODEL;
    const int c0 = lane * 4, c1 = 128 + lane * 4;
    const size_t i0 = (size_t)row * D_MODEL + c0;
    const size_t i1 = (size_t)row * D_MODEL + c1;
    float4 v0 = *(const float4*)(part + i0);
    float4 v1 = *(const float4*)(part + i1);
    #pragma unroll
    for (int s = 1; s < S; s++) {
        add4(v0, *(const float4*)(part + (size_t)s * MN + i0));
        add4(v1, *(const float4*)(part + (size_t)s * MN + i1));
    }
    add4(v0, *(const float4*)(bias + c0));
    add4(v1, *(const float4*)(bias + c1));
    float mu, rstd;
    warp_stats(v0, v1, mu, rstd);
    float4 g0 = *(const float4*)(lng + c0), g1 = *(const float4*)(lng + c1);
    float4 bb0 = *(const float4*)(lnb + c0), bb1 = *(const float4*)(lnb + c1);
    float4 w0 = gelu4(ln_apply4(v0, mu, rstd, g0, bb0));
    float4 w1 = gelu4(ln_apply4(v1, mu, rstd, g1, bb1));
    *(float4*)(hs + i0) = w0;
    *(float4*)(hs + i1) = w1;
    warp_stats(w0, w1, mu, rstd);
    g0 = *(const float4*)(ng0 + c0); g1 = *(const float4*)(ng0 + c1);
    bb0 = *(const float4*)(nb0 + c0); bb1 = *(const float4*)(nb0 + c1);
    float4 t0 = ln_apply4(w0, mu, rstd, g0, bb0);
    float4 t1 = ln_apply4(w1, mu, rstd, g1, bb1);
    bf16_hilo4(t0, lthi + i0, ltlo + i0);
    bf16_hilo4(t1, lthi + i1, ltlo + i1);
}

template<int S, int LN>
__global__ void ep_opw(const float* __restrict__ part, const float* __restrict__ ng,
                       const float* __restrict__ nb, float* __restrict__ hs,
                       __nv_bfloat16* __restrict__ ohi, __nv_bfloat16* __restrict__ olo)
{
    const int gi = blockIdx.x * blockDim.x + threadIdx.x;
    const int row = gi >> 5;
    const int lane = gi & 31;
    const int MN = M_ROWS * D_MODEL;
    const int c0 = lane * 4, c1 = 128 + lane * 4;
    const size_t i0 = (size_t)row * D_MODEL + c0;
    const size_t i1 = (size_t)row * D_MODEL + c1;
    float4 v0 = *(const float4*)(hs + i0);
    float4 v1 = *(const float4*)(hs + i1);
    #pragma unroll
    for (int s = 0; s < S; s++) {
        add4(v0, *(const float4*)(part + (size_t)s * MN + i0));
        add4(v1, *(const float4*)(part + (size_t)s * MN + i1));
    }
    *(float4*)(hs + i0) = v0;
    *(float4*)(hs + i1) = v1;
    if (LN) {
        float mu, rstd;
        warp_stats(v0, v1, mu, rstd);
        float4 g0 = *(const float4*)(ng + c0), g1 = *(const float4*)(ng + c1);
        float4 b0 = *(const float4*)(nb + c0), b1 = *(const float4*)(nb + c1);
        float4 t0 = ln_apply4(v0, mu, rstd, g0, b0);
        float4 t1 = ln_apply4(v1, mu, rstd, g1, b1);
        bf16_hilo4(t0, ohi + i0, olo + i0);
        bf16_hilo4(t1, ohi + i1, olo + i1);
    } else {
        bf16_hilo4(v0, ohi + i0, olo + i0);
        bf16_hilo4(v1, ohi + i1, olo + i1);
    }
}

template<int S>
__global__ void ep_head(const float* __restrict__ part, const float* __restrict__ bias,
                        __nv_bfloat16* __restrict__ h2hi, __nv_bfloat16* __restrict__ h2lo,
                        float* __restrict__ nrm)
{
    const int gi = blockIdx.x * blockDim.x + threadIdx.x;
    const int row = gi >> 5;
    const int lane = gi & 31;
    const int MN = M_ROWS * D_MODEL;
    const int c0 = lane * 4, c1 = 128 + lane * 4;
    const size_t i0 = (size_t)row * D_MODEL + c0;
    const size_t i1 = (size_t)row * D_MODEL + c1;
    float4 v0 = *(const float4*)(part + i0);
    float4 v1 = *(const float4*)(part + i1);
    #pragma unroll
    for (int s = 1; s < S; s++) {
        add4(v0, *(const float4*)(part + (size_t)s * MN + i0));
        add4(v1, *(const float4*)(part + (size_t)s * MN + i1));
    }
    add4(v0, *(const float4*)(bias + c0));
    add4(v1, *(const float4*)(bias + c1));
    v0 = gelu4(v0); v1 = gelu4(v1);
    bf16_hilo4(v0, h2hi + i0, h2lo + i0);
    bf16_hilo4(v1, h2hi + i1, h2lo + i1);
    float s = v0.x*v0.x + v0.y*v0.y + v0.z*v0.z + v0.w*v0.w
            + v1.x*v1.x + v1.y*v1.y + v1.z*v1.z + v1.w*v1.w;
    #pragma unroll
    for (int o = 16; o > 0; o >>= 1) s += __shfl_xor_sync(0xffffffffu, s, o);
    if (lane == 0) nrm[row] = sqrtf(s);
}

// ---------------------------------------------------------------------------
// Depthwise causal conv (k=4) + SiLU -> u and ut
// ---------------------------------------------------------------------------
__global__ void conv2_kernel(const float* __restrict__ xz, const float* __restrict__ cw,
                             const float* __restrict__ cb, float* __restrict__ u,
                             float* __restrict__ ut)
{
    __shared__ float tile[32][33];
    const int b = blockIdx.z;
    const int t0 = blockIdx.x * 32, d0 = blockIdx.y * 32;
    const int tx = threadIdx.x, ty = threadIdx.y;
    const int d = d0 + tx;
    const float w0 = cw[d * 4 + 0], w1 = cw[d * 4 + 1];
    const float w2 = cw[d * 4 + 2], w3 = cw[d * 4 + 3];
    const float bb = cb[d];
    #pragma unroll
    for (int i = 0; i < 4; i++) {
        const int t = t0 + ty + i * 8;
        const size_t rbase = (size_t)(b * SEQ + t) * (2 * D_INNER) + d;
        float acc = bb;
        if (t >= 3) {
            acc = fmaf(w0, xz[rbase - 3 * 2 * D_INNER], acc);
            acc = fmaf(w1, xz[rbase - 2 * 2 * D_INNER], acc);
            acc = fmaf(w2, xz[rbase - 1 * 2 * D_INNER], acc);
        } else {
            if (t >= 2) acc = fmaf(w1, xz[rbase - 2 * 2 * D_INNER], acc);
            if (t >= 1) acc = fmaf(w2, xz[rbase - 1 * 2 * D_INNER], acc);
        }
        acc = fmaf(w3, xz[rbase], acc);
        acc = silu_f(acc);
        u[(size_t)(b * SEQ + t) * D_INNER + d] = acc;
        tile[ty + i * 8][tx] = acc;
    }
    __syncthreads();
    #pragma unroll
    for (int i = 0; i < 4; i++) {
        const int dd = d0 + ty + i * 8;
        ut[(size_t)(b * D_INNER + dd) * SEQ + t0 + tx] = tile[tx][ty + i * 8];
    }
}

// ---------------------------------------------------------------------------
// delta = softplus(dt @ dtw^T + dtb) -> dltt
// ---------------------------------------------------------------------------
__global__ void deltaT_kernel(const float* __restrict__ xdbc, const float* __restrict__ dtw,
                              const float* __restrict__ dtb, float* __restrict__ dltt)
{
    __shared__ float w_s[32][17];
    __shared__ float b_s[32];
    __shared__ float tile[32][33];
    const int b = blockIdx.z;
    const int t0 = blockIdx.x * 32, d0 = blockIdx.y * 32;
    const int tx = threadIdx.x, ty = threadIdx.y;
    const int tid = ty * 32 + tx;
    {
        int r = tid >> 4, c = tid & 15;
        w_s[r][c] = dtw[(d0 + r) * DT_RANK + c];
        w_s[r + 16][c] = dtw[(d0 + r + 16) * DT_RANK + c];
        if (tid < 32) b_s[tid] = dtb[d0 + tid];
    }
    __syncthreads();
    #pragma unroll
    for (int i = 0; i < 4; i++) {
        const int t = t0 + ty + i * 8;
        const float* xr = xdbc + (size_t)(b * SEQ + t) * 48;
        float acc = b_s[tx];
        #pragma unroll
        for (int r = 0; r < DT_RANK; r++)
            acc = fmaf(__ldg(xr + r), w_s[tx][r], acc);
        tile[ty + i * 8][tx] = (acc > 20.f) ? acc : log1pf(__expf(acc));
    }
    __syncthreads();
    #pragma unroll
    for (int i = 0; i < 4; i++) {
        const int dd = d0 + ty + i * 8;
        dltt[(size_t)(b * D_INNER + dd) * SEQ + t0 + tx] = tile[tx][ty + i * 8];
    }
}

// ---------------------------------------------------------------------------
// Fused chunked selective scan
// ---------------------------------------------------------------------------
__global__ __launch_bounds__(256) void scan_fused(
    const float* __restrict__ dltt, const float* __restrict__ ut,
    const float* __restrict__ xdbc, const float* __restrict__ A_log,
    const float* __restrict__ Dp, float* __restrict__ yt)
{
    __shared__ float Ps[NCHUNK][D_STATE];
    __shared__ float Qs[NCHUNK][D_STATE];
    __shared__ float Ts[NCHUNK][D_STATE];
    const int tid = threadIdx.x;
    const int g = blockIdx.x;
    const int c = tid >> 4;
    const int n = tid & 15;
    const int b = g >> 9;
    const int d = g & (D_INNER - 1);
    const float A  = -__expf(A_log[d * D_STATE + n]);
    const float Dd = Dp[d];
    const size_t base = (size_t)g * SEQ + c * CHUNK;
    const float* xb = xdbc + ((size_t)b * SEQ + c * CHUNK) * 48 + DT_RANK;

    float dt[16], uu[16];
    {
        float s = 0.f, sumd = 0.f;
        for (int tc = 0; tc < CHUNK; tc += 16) {
            #pragma unroll
            for (int q = 0; q < 4; q++) {
                float4 v = ((const float4*)(dltt + base + tc))[q];
                dt[q*4+0] = v.x; dt[q*4+1] = v.y; dt[q*4+2] = v.z; dt[q*4+3] = v.w;
                float4 w = ((const float4*)(ut + base + tc))[q];
                uu[q*4+0] = w.x; uu[q*4+1] = w.y; uu[q*4+2] = w.z; uu[q*4+3] = w.w;
            }
            #pragma unroll
            for (int j = 0; j < 16; j++) {
                const float Bn = __ldg(xb + (size_t)(tc + j) * 48 + n);
                s = fmaf(s, __expf(dt[j] * A), dt[j] * uu[j] * Bn);
                sumd += dt[j];
            }
        }
        Qs[c][n] = s;
        Ps[c][n] = __expf(A * sumd);
    }
    __syncthreads();

    if (tid < D_STATE) {
        float t = 0.f;
        Ts[0][tid] = 0.f;
        #pragma unroll
        for (int cc = 1; cc < NCHUNK; cc++) {
            t = fmaf(Ps[cc - 1][tid], t, Qs[cc - 1][tid]);
            Ts[cc][tid] = t;
        }
    }
    __syncthreads();

    {
        float s = Ts[c][n];
        for (int tc = 0; tc < CHUNK; tc += 16) {
            #pragma unroll
            for (int q = 0; q < 4; q++) {
                float4 v = ((const float4*)(dltt + base + tc))[q];
                dt[q*4+0] = v.x; dt[q*4+1] = v.y; dt[q*4+2] = v.z; dt[q*4+3] = v.w;
                float4 w = ((const float4*)(ut + base + tc))[q];
                uu[q*4+0] = w.x; uu[q*4+1] = w.y; uu[q*4+2] = w.z; uu[q*4+3] = w.w;
            }
            float rv = 0.f;
            #pragma unroll
            for (int j = 0; j < 16; j++) {
                const float* xr = xb + (size_t)(tc + j) * 48;
                const float Bn = __ldg(xr + n);
                const float Cn = __ldg(xr + D_STATE + n);
                s = fmaf(s, __expf(dt[j] * A), dt[j] * uu[j] * Bn);
                float v = s * Cn;
                #pragma unroll
                for (int o = 8; o > 0; o >>= 1) v += __shfl_xor_sync(0xffffffffu, v, o);
                if (n == j) rv = v + uu[j] * Dd;
            }
            yt[base + tc + n] = rv;
        }
    }
}

// ---------------------------------------------------------------------------
// Gate + transpose -> y hi/lo
// ---------------------------------------------------------------------------
__global__ void gate_kernel(const float* __restrict__ yt, const float* __restrict__ xz,
                            __nv_bfloat16* __restrict__ yhi, __nv_bfloat16* __restrict__ ylo)
{
    __shared__ float t0s[32][33];
    const int b = blockIdx.z;
    const int tblk = blockIdx.x * 32, dblk = blockIdx.y * 32;
    const int tx = threadIdx.x, ty = threadIdx.y;
    #pragma unroll
    for (int i = 0; i < 4; i++) {
        int d = dblk + ty + i * 8;
        t0s[ty + i * 8][tx] = yt[(size_t)(b * D_INNER + d) * SEQ + tblk + tx];
    }
    __syncthreads();
    #pragma unroll
    for (int i = 0; i < 4; i++) {
        int t = tblk + ty + i * 8;
        size_t row = (size_t)(b * SEQ + t);
        float z = xz[row * (2 * D_INNER) + D_INNER + dblk + tx];
        float v = t0s[tx][ty + i * 8] * silu_f(z);
        __nv_bfloat16 h = __float2bfloat16(v);
        size_t idx = row * D_INNER + dblk + tx;
        yhi[idx] = h;
        ylo[idx] = __float2bfloat16(v - __bfloat162float(h));
    }
}

__global__ void loss_kernel(const float* __restrict__ nrm, float* __restrict__ out)
{
    const int tid = threadIdx.x;
    float s = 0.f;
    #pragma unroll
    for (int i = 0; i < 4; i++) s += nrm[tid + i * 1024];
    #pragma unroll
    for (int o = 16; o > 0; o >>= 1) s += __shfl_xor_sync(0xffffffffu, s, o);
    __shared__ float sm[32];
    if ((tid & 31) == 0) sm[tid >> 5] = s;
    __syncthreads();
    if (tid == 0) {
        float t = 0.f;
        #pragma unroll
        for (int i = 0; i < 32; i++) t += sm[i];
        *out = 0.01f * t * (1.f / (float)M_ROWS);
    }
}

// ---------------------------------------------------------------------------
// Launch
// ---------------------------------------------------------------------------
extern "C" void kernel_launch(void* const* d_in, const int* in_sizes, int n_in,
                              void* d_out, int out_size)
{
    const float* x      = (const float*)d_in[0];
    const float* in_w   = (const float*)d_in[1];
    const float* in_b   = (const float*)d_in[2];
    const float* ln_g   = (const float*)d_in[3];
    const float* ln_b   = (const float*)d_in[4];
    const float* blk_ng = (const float*)d_in[5];
    const float* blk_nb = (const float*)d_in[6];
    const float* blk_ipw= (const float*)d_in[7];
    const float* blk_cw = (const float*)d_in[8];
    const float* blk_cb = (const float*)d_in[9];
    const float* blk_xpw= (const float*)d_in[10];
    const float* blk_dtw= (const float*)d_in[11];
    const float* blk_dtb= (const float*)d_in[12];
    const float* blk_Al = (const float*)d_in[13];
    const float* blk_D  = (const float*)d_in[14];
    const float* blk_opw= (const float*)d_in[15];
    const float* op_w   = (const float*)d_in[16];
    const float* op_b   = (const float*)d_in[17];
    const float* cls_w  = (const float*)d_in[18];
    const float* cls_b  = (const float*)d_in[19];
    float* out = (float*)d_out;

    float *hs, *xz, *u, *ut, *dltt, *yt, *xdbc, *nrm, *part;
    __nv_bfloat16 *xhi, *xlo, *lthi, *ltlo, *yhi, *ylo, *hshi, *hslo, *h2hi, *h2lo;
    __nv_bfloat16 *wihi, *wilo, *wphi, *wplo, *wohi, *wolo, *wqhi, *wqlo, *wchi, *wclo;
    cudaGetSymbolAddress((void**)&hs,   g_hl);
    cudaGetSymbolAddress((void**)&xz,   g_xz);
    cudaGetSymbolAddress((void**)&u,    g_u);
    cudaGetSymbolAddress((void**)&ut,   g_ut);
    cudaGetSymbolAddress((void**)&dltt, g_dltt);
    cudaGetSymbolAddress((void**)&yt,   g_yt);
    cudaGetSymbolAddress((void**)&xdbc, g_xdbc);
    cudaGetSymbolAddress((void**)&nrm,  g_norm);
    cudaGetSymbolAddress((void**)&part, g_part);
    cudaGetSymbolAddress((void**)&xhi,  g_xhi);  cudaGetSymbolAddress((void**)&xlo,  g_xlo);
    cudaGetSymbolAddress((void**)&lthi, g_lthi); cudaGetSymbolAddress((void**)&ltlo, g_ltlo);
    cudaGetSymbolAddress((void**)&yhi,  g_yhi);  cudaGetSymbolAddress((void**)&ylo,  g_ylo);
    cudaGetSymbolAddress((void**)&hshi, g_hshi); cudaGetSymbolAddress((void**)&hslo, g_hslo);
    cudaGetSymbolAddress((void**)&h2hi, g_h2hi); cudaGetSymbolAddress((void**)&h2lo, g_h2lo);
    cudaGetSymbolAddress((void**)&wihi, g_wihi); cudaGetSymbolAddress((void**)&wilo, g_wilo);
    cudaGetSymbolAddress((void**)&wphi, g_wphi); cudaGetSymbolAddress((void**)&wplo, g_wplo);
    cudaGetSymbolAddress((void**)&wohi, g_wohi); cudaGetSymbolAddress((void**)&wolo, g_wolo);
    cudaGetSymbolAddress((void**)&wqhi, g_wqhi); cudaGetSymbolAddress((void**)&wqlo, g_wqlo);
    cudaGetSymbolAddress((void**)&wchi, g_wchi); cudaGetSymbolAddress((void**)&wclo, g_wclo);

    cudaFuncSetAttribute(mma_gemm<1>, cudaFuncAttributeMaxDynamicSharedMemorySize, MM_SMEM);
    cudaFuncSetAttribute(mma_gemm<2>, cudaFuncAttributeMaxDynamicSharedMemorySize, MM_SMEM);

    dim3 blk256(256);
    dim3 tblk(32, 8);
    dim3 tgrid(SEQ / 32, D_INNER / 32, BATCH);
    const int EP_BLOCKS = M_ROWS * 32 / 256;

    // ONE batched conversion launch (x + all weights)
    cvt_all<<<1184, blk256>>>(x, in_w, blk_ipw, blk_opw, op_w, cls_w,
                              xhi, xlo, wihi, wilo, wphi, wplo,
                              wohi, wolo, wqhi, wqlo, wchi, wclo);

    // in-proj (split-K=2, 128 CTAs) + fused epilogue
    mma_gemm<2><<<dim3(D_MODEL / 128, M_ROWS / 128, 2), blk256, MM_SMEM>>>(
        xhi, xlo, wihi, wilo, part, M_ROWS, D_MODEL, X_DIM);
    ep_inproj<2><<<EP_BLOCKS, blk256>>>(part, in_b, ln_g, ln_b,
                                        blk_ng, blk_nb, hs, lthi, ltlo);

    for (int l = 0; l < N_LAYERS; l++) {
        const __nv_bfloat16* pwh = wphi + (size_t)l * 2 * D_INNER * D_MODEL;
        const __nv_bfloat16* pwl = wplo + (size_t)l * 2 * D_INNER * D_MODEL;
        const __nv_bfloat16* owh = wohi + (size_t)l * D_MODEL * D_INNER;
        const __nv_bfloat16* owl = wolo + (size_t)l * D_MODEL * D_INNER;
        const float* cw  = blk_cw  + (size_t)l * D_INNER * D_CONV;
        const float* cb  = blk_cb  + (size_t)l * D_INNER;
        const float* xpw = blk_xpw + (size_t)l * 48 * D_INNER;
        const float* dtw = blk_dtw + (size_t)l * D_INNER * DT_RANK;
        const float* dtb = blk_dtb + (size_t)l * D_INNER;
        const float* Al  = blk_Al  + (size_t)l * D_INNER * D_STATE;
        const float* Dp  = blk_D   + (size_t)l * D_INNER;

        // ipw GEMM: N=1024 -> 256 CTAs, no split
        mma_gemm<1><<<dim3(2 * D_INNER / 128, M_ROWS / 128, 1), blk256, MM_SMEM>>>(
            lthi, ltlo, pwh, pwl, xz, M_ROWS, 2 * D_INNER, D_MODEL);
        conv2_kernel<<<tgrid, tblk>>>(xz, cw, cb, u, ut);
        gemm_xpw<<<dim3(1, M_ROWS / 128, 4), blk256>>>(
            u, xpw, part, M_ROWS, 48, D_INNER, 4);
        reduce_k<4,0><<<(M_ROWS * 48 / 4 + 255) / 256, blk256>>>(
            part, nullptr, xdbc, M_ROWS * 48, 48);
        deltaT_kernel<<<tgrid, tblk>>>(xdbc, dtw, dtb, dltt);
        scan_fused<<<NGROUP, blk256>>>(dltt, ut, xdbc, Al, Dp, yt);
        gate_kernel<<<tgrid, tblk>>>(yt, xz, yhi, ylo);
        // opw GEMM: split-K=2 -> 128 CTAs
        mma_gemm<2><<<dim3(D_MODEL / 128, M_ROWS / 128, 2), blk256, MM_SMEM>>>(
            yhi, ylo, owh, owl, part, M_ROWS, D_MODEL, D_INNER);
        if (l + 1 < N_LAYERS) {
            ep_opw<2,1><<<EP_BLOCKS, blk256>>>(part,
                blk_ng + (size_t)(l + 1) * D_MODEL,
                blk_nb + (size_t)(l + 1) * D_MODEL, hs, lthi, ltlo);
        } else {
            ep_opw<2,0><<<EP_BLOCKS, blk256>>>(part, nullptr, nullptr, hs, hshi, hslo);
        }
    }

    // head: split-K=2 -> 128 CTAs
    mma_gemm<2><<<dim3(D_MODEL / 128, M_ROWS / 128, 2), blk256, MM_SMEM>>>(
        hshi, hslo, wqhi, wqlo, part, M_ROWS, D_MODEL, D_MODEL);
    ep_head<2><<<EP_BLOCKS, blk256>>>(part, op_b, h2hi, h2lo, nrm);
    // cls: split-K=2 -> 64 CTAs
    mma_gemm<2><<<dim3(N_CLS / 128, M_ROWS / 128, 2), blk256, MM_SMEM>>>(
        h2hi, h2lo, wchi, wclo, part, M_ROWS, N_CLS, D_MODEL);
    reduce_k<2,1><<<(M_ROWS * N_CLS / 4 + 255) / 256, blk256>>>(
        part, cls_b, out, M_ROWS * N_CLS, N_CLS);
    loss_kernel<<<1, 1024>>>(nrm, out + (out_size - 1));
}